// round 13
// baseline (speedup 1.0000x reference)
#include <cuda_runtime.h>
#include <cuda_bf16.h>
#include <cstdint>
#include <cstddef>

#define BATCH 32
#define HEADS 8
#define NTOK 1024
#define DH 64
#define ML 256          // landmarks
#define CDIM 512
#define BHN (BATCH*HEADS)   // 256
#define KSZ 33

// ---------------- device scratch ----------------
__device__ float g_xt[(size_t)BATCH*NTOK*CDIM];     // x transposed: (b, n, c), tf32-rounded
__device__ float g_wqkvT[3*CDIM*CDIM];              // (1536, 512), tf32-rounded
__device__ float g_woutT[CDIM*CDIM];                // (512, 512), tf32-rounded
__device__ float g_q [BHN*NTOK*DH];
__device__ float g_k [BHN*NTOK*DH];
__device__ float g_v [BHN*NTOK*DH];
__device__ float g_ql[BHN*ML*DH];
__device__ float g_kl[BHN*ML*DH];
__device__ float g_attn1[(size_t)BHN*NTOK*ML];      // (bh,1024,256)
__device__ float g_attn3[(size_t)BHN*ML*NTOK];      // (bh,256,1024)
__device__ float g_attn2[BHN*ML*ML];
__device__ float g_zA[BHN*ML*ML];
__device__ float g_zB[BHN*ML*ML];
__device__ float g_xz[BHN*ML*ML];
__device__ float g_t1[BHN*ML*ML];
__device__ float g_t2[BHN*ML*ML];
__device__ float g_av[BHN*ML*DH];
__device__ float g_bv[BHN*ML*DH];
__device__ float g_outf[(size_t)BATCH*NTOK*CDIM];   // (b, n, 512)
__device__ unsigned g_colmax;
__device__ unsigned g_rowmax;
// bf16 pinv buffers
__device__ __nv_bfloat16 g_a2h [BHN*ML*ML];   // bf16(a2), row-major [M][K]
__device__ __nv_bfloat16 g_zhA [BHN*ML*ML];   // z row-major
__device__ __nv_bfloat16 g_zhB [BHN*ML*ML];
__device__ __nv_bfloat16 g_zhTA[BHN*ML*ML];   // z^T (K-major for B operand)
__device__ __nv_bfloat16 g_zhTB[BHN*ML*ML];
__device__ __nv_bfloat16 g_xzh [BHN*ML*ML];
__device__ __nv_bfloat16 g_xzhT[BHN*ML*ML];
__device__ __nv_bfloat16 g_t1hT[BHN*ML*ML];
__device__ __nv_bfloat16 g_t2hT[BHN*ML*ML];

// ================= helpers =================
__device__ __forceinline__ float cvt_tf32(float x) {
    uint32_t u;
    asm("cvt.rna.tf32.f32 %0, %1;" : "=r"(u) : "f"(x));
    return __uint_as_float(u);
}
__device__ __forceinline__ void mma_tf32_16x8x8(float c[4],
    uint32_t a0, uint32_t a1, uint32_t a2, uint32_t a3, uint32_t b0, uint32_t b1) {
    asm volatile(
        "mma.sync.aligned.m16n8k8.row.col.f32.tf32.tf32.f32 "
        "{%0,%1,%2,%3},{%4,%5,%6,%7},{%8,%9},{%0,%1,%2,%3};"
        : "+f"(c[0]), "+f"(c[1]), "+f"(c[2]), "+f"(c[3])
        : "r"(a0), "r"(a1), "r"(a2), "r"(a3), "r"(b0), "r"(b1));
}
__device__ __forceinline__ void mma_bf16_16x8x16(float c[4],
    uint32_t a0, uint32_t a1, uint32_t a2, uint32_t a3, uint32_t b0, uint32_t b1) {
    asm volatile(
        "mma.sync.aligned.m16n8k16.row.col.f32.bf16.bf16.f32 "
        "{%0,%1,%2,%3},{%4,%5,%6,%7},{%8,%9},{%0,%1,%2,%3};"
        : "+f"(c[0]), "+f"(c[1]), "+f"(c[2]), "+f"(c[3])
        : "r"(a0), "r"(a1), "r"(a2), "r"(a3), "r"(b0), "r"(b1));
}
__device__ __forceinline__ void ldsm_x4(uint32_t& r0, uint32_t& r1,
                                        uint32_t& r2, uint32_t& r3, uint32_t saddr) {
    asm volatile("ldmatrix.sync.aligned.m8n8.x4.shared.b16 {%0,%1,%2,%3}, [%4];"
                 : "=r"(r0), "=r"(r1), "=r"(r2), "=r"(r3) : "r"(saddr));
}
__device__ __forceinline__ void cp16(uint32_t dst, const void* src) {
    asm volatile("cp.async.cg.shared.global [%0], [%1], 16;" :: "r"(dst), "l"(src));
}
#define CP_COMMIT() asm volatile("cp.async.commit_group;")
#define CP_WAIT1()  asm volatile("cp.async.wait_group 1;" ::: "memory")
#define CP_WAIT0()  asm volatile("cp.async.wait_group 0;" ::: "memory")

#define PPITCH 36
#define PSTAGE (128*PPITCH)
#define G128_SMEM3 (6*PSTAGE*4)                     // 110592 (A,B both K-major fp32)

#define BNP128 136
#define BRSTG128 (32*BNP128)
#define PB_SMEM3 ((3*PSTAGE + 3*BRSTG128)*4)        // 107520

#define BNP64 72
#define BRSTG64 (32*BNP64)
#define G64R_SMEM3 ((3*PSTAGE + 3*BRSTG64)*4)       // 82944

// bf16 tiles: [128 rows][KPH halves] per chunk (32 halves data, pitch 40)
#define KPH 40
#define HSTG (128*KPH)                               // halves per stage
#define BH_SMEM3 (6*HSTG*2)                          // 61440 bytes

// ============ mainloop A: B stored K-major ([N rows][K]) — sims/qkv/final ============
__device__ __forceinline__ void mainloop128x128(
    const float* __restrict__ A, const float* __restrict__ B,
    int lda, int ldb, int kch, float* sm, int tid, float acc[4][4][4])
{
    const uint32_t sbase = (uint32_t)__cvta_generic_to_shared(sm);
    const uint32_t bbase = sbase + 3*PSTAGE*4;
    const int wid = tid >> 5, lane = tid & 31;
    const int wm = wid >> 2, wn = wid & 3;
    const int g = lane >> 3, r8 = lane & 7;
    const uint32_t a_lm = (uint32_t)((wm*64 + (g&1)*8 + r8)*PPITCH + (g>>1)*4)*4;
    const uint32_t b_lm = (uint32_t)((wn*32 + (g>>1)*8 + r8)*PPITCH + (g&1)*4)*4;
    int rrow[4], rc4[4];
    #pragma unroll
    for (int e = 0; e < 4; e++) {
        int f4 = e * 256 + tid;
        rrow[e] = f4 >> 3;
        rc4[e] = (f4 & 7) << 2;
    }
    #pragma unroll
    for (int p = 0; p < 2; p++) {
        if (p < kch) {
            const int k0 = p * 32;
            #pragma unroll
            for (int e = 0; e < 4; e++) {
                cp16(sbase + (uint32_t)(p*PSTAGE + rrow[e]*PPITCH + rc4[e])*4,
                     &A[(size_t)rrow[e] * lda + k0 + rc4[e]]);
                cp16(bbase + (uint32_t)(p*PSTAGE + rrow[e]*PPITCH + rc4[e])*4,
                     &B[(size_t)rrow[e] * ldb + k0 + rc4[e]]);
            }
        }
        CP_COMMIT();
    }
    for (int c = 0; c < kch; c++) {
        const int st = c % 3;
        if (c + 1 < kch) { CP_WAIT1(); } else { CP_WAIT0(); }
        __syncthreads();
        if (c + 2 < kch) {
            const int nst = (c + 2) % 3;
            const int k0 = (c + 2) * 32;
            #pragma unroll
            for (int e = 0; e < 4; e++) {
                cp16(sbase + (uint32_t)(nst*PSTAGE + rrow[e]*PPITCH + rc4[e])*4,
                     &A[(size_t)rrow[e] * lda + k0 + rc4[e]]);
                cp16(bbase + (uint32_t)(nst*PSTAGE + rrow[e]*PPITCH + rc4[e])*4,
                     &B[(size_t)rrow[e] * ldb + k0 + rc4[e]]);
            }
            CP_COMMIT();
        }
        const uint32_t a_st = sbase + (uint32_t)(st*PSTAGE)*4 + a_lm;
        const uint32_t b_st = bbase + (uint32_t)(st*PSTAGE)*4 + b_lm;
        #pragma unroll
        for (int ks = 0; ks < 4; ks++) {
            uint32_t af[4][4];
            #pragma unroll
            for (int mi = 0; mi < 4; mi++)
                ldsm_x4(af[mi][0], af[mi][1], af[mi][2], af[mi][3],
                        a_st + (uint32_t)(mi*16*PPITCH + ks*8)*4);
            uint32_t bf[4][2];
            #pragma unroll
            for (int p = 0; p < 2; p++)
                ldsm_x4(bf[2*p][0], bf[2*p][1], bf[2*p+1][0], bf[2*p+1][1],
                        b_st + (uint32_t)(p*16*PPITCH + ks*8)*4);
            #pragma unroll
            for (int mi = 0; mi < 4; mi++)
                #pragma unroll
                for (int ni = 0; ni < 4; ni++)
                    mma_tf32_16x8x8(acc[mi][ni],
                        af[mi][0], af[mi][1], af[mi][2], af[mi][3],
                        bf[ni][0], bf[ni][1]);
        }
    }
}

// ============ mainloop B: B stored row-major [K][N] — tf32 pinv/chain ============
__device__ __forceinline__ void mainloop128x128_rowB(
    const float* __restrict__ A, const float* __restrict__ B,
    int lda, int ldb, int kch, float* sm, int tid, float acc[4][4][4])
{
    const uint32_t sbase = (uint32_t)__cvta_generic_to_shared(sm);
    const uint32_t bbase = sbase + 3*PSTAGE*4;
    const int wid = tid >> 5, lane = tid & 31;
    const int gr = lane >> 2, gc = lane & 3;
    const int wm = wid >> 2, wn = wid & 3;
    const int g = lane >> 3, r8 = lane & 7;
    const uint32_t a_lm = (uint32_t)((wm*64 + (g&1)*8 + r8)*PPITCH + (g>>1)*4)*4;
    int arow[4], ac4[4], bk[4], bn4[4];
    #pragma unroll
    for (int e = 0; e < 4; e++) {
        int f4 = e * 256 + tid;
        arow[e] = f4 >> 3;  ac4[e] = (f4 & 7) << 2;
        bk[e]   = f4 >> 5;  bn4[e] = (f4 & 31) << 2;
    }
    #pragma unroll
    for (int p = 0; p < 2; p++) {
        if (p < kch) {
            const int k0 = p * 32;
            #pragma unroll
            for (int e = 0; e < 4; e++) {
                cp16(sbase + (uint32_t)(p*PSTAGE + arow[e]*PPITCH + ac4[e])*4,
                     &A[(size_t)arow[e] * lda + k0 + ac4[e]]);
                cp16(bbase + (uint32_t)(p*BRSTG128 + bk[e]*BNP128 + bn4[e])*4,
                     &B[(size_t)(k0 + bk[e]) * ldb + bn4[e]]);
            }
        }
        CP_COMMIT();
    }
    for (int c = 0; c < kch; c++) {
        const int st = c % 3;
        if (c + 1 < kch) { CP_WAIT1(); } else { CP_WAIT0(); }
        __syncthreads();
        if (c + 2 < kch) {
            const int nst = (c + 2) % 3;
            const int k0 = (c + 2) * 32;
            #pragma unroll
            for (int e = 0; e < 4; e++) {
                cp16(sbase + (uint32_t)(nst*PSTAGE + arow[e]*PPITCH + ac4[e])*4,
                     &A[(size_t)arow[e] * lda + k0 + ac4[e]]);
                cp16(bbase + (uint32_t)(nst*BRSTG128 + bk[e]*BNP128 + bn4[e])*4,
                     &B[(size_t)(k0 + bk[e]) * ldb + bn4[e]]);
            }
            CP_COMMIT();
        }
        const uint32_t a_st = sbase + (uint32_t)(st*PSTAGE)*4 + a_lm;
        const float* Bb = sm + 3*PSTAGE + st*BRSTG128;
        #pragma unroll
        for (int ks = 0; ks < 4; ks++) {
            uint32_t af[4][4];
            #pragma unroll
            for (int mi = 0; mi < 4; mi++)
                ldsm_x4(af[mi][0], af[mi][1], af[mi][2], af[mi][3],
                        a_st + (uint32_t)(mi*16*PPITCH + ks*8)*4);
            uint32_t bf[4][2];
            #pragma unroll
            for (int ni = 0; ni < 4; ni++) {
                int n = wn*32 + ni*8 + gr;
                bf[ni][0] = __float_as_uint(Bb[(ks*8 + gc)*BNP128 + n]);
                bf[ni][1] = __float_as_uint(Bb[(ks*8 + gc + 4)*BNP128 + n]);
            }
            #pragma unroll
            for (int mi = 0; mi < 4; mi++)
                #pragma unroll
                for (int ni = 0; ni < 4; ni++)
                    mma_tf32_16x8x8(acc[mi][ni],
                        af[mi][0], af[mi][1], af[mi][2], af[mi][3],
                        bf[ni][0], bf[ni][1]);
        }
    }
}

// ============ bf16 pinv batched GEMM: D = c1*U + c2*(A @ B^T), both K-major ============
// Outputs (each optional): Cn bf16 [M][N], Ct bf16 [N][M], Cf fp32 tf32-rounded [M][N].
__global__ void __launch_bounds__(256, 2) pinv_bf16_kernel(
    const __nv_bfloat16* __restrict__ A, const __nv_bfloat16* __restrict__ B,
    const __nv_bfloat16* __restrict__ U,
    __nv_bfloat16* __restrict__ Cn, __nv_bfloat16* __restrict__ Ct,
    float* __restrict__ Cf, float c1, float c2)
{
    extern __shared__ __nv_bfloat16 smh[];
    const uint32_t sbase = (uint32_t)__cvta_generic_to_shared(smh);
    const uint32_t bbase = sbase + 3*HSTG*2;
    const int tid = threadIdx.x;
    const int wid = tid >> 5, lane = tid & 31;
    const int wm = wid >> 2, wn = wid & 3;
    const int gr = lane >> 2, gc = lane & 3;
    const int mtx = lane >> 3, mrow = lane & 7;
    const uint32_t a_lm = ((uint32_t)(((mtx&1)*8 + mrow)) * KPH + (uint32_t)((mtx>>1)*8)) * 2;
    const uint32_t b_lm = ((uint32_t)(((mtx>>1)*8 + mrow)) * KPH + (uint32_t)((mtx&1)*8)) * 2;

    const int tile = blockIdx.x;
    const int batch = tile >> 2;
    const int m0 = ((tile >> 1) & 1) << 7;
    const int n0 = (tile & 1) << 7;
    const size_t boff = (size_t)batch << 16;
    A += boff + (size_t)m0 * ML;
    B += boff + (size_t)n0 * ML;
    if (U)  U  += boff;
    if (Cn) Cn += boff;
    if (Ct) Ct += boff;
    if (Cf) Cf += boff;

    int crow[2], cseg[2];
    #pragma unroll
    for (int e = 0; e < 2; e++) {
        int f = e * 256 + tid;
        crow[e] = f >> 2;
        cseg[e] = (f & 3) * 8;
    }

    float acc[4][4][4];
    #pragma unroll
    for (int mi = 0; mi < 4; mi++)
        #pragma unroll
        for (int ni = 0; ni < 4; ni++)
            #pragma unroll
            for (int e = 0; e < 4; e++) acc[mi][ni][e] = 0.f;

    #pragma unroll
    for (int p = 0; p < 2; p++) {
        const int k0 = p * 32;
        #pragma unroll
        for (int e = 0; e < 2; e++) {
            cp16(sbase + (uint32_t)(p*HSTG + crow[e]*KPH + cseg[e])*2,
                 &A[(size_t)crow[e] * ML + k0 + cseg[e]]);
            cp16(bbase + (uint32_t)(p*HSTG + crow[e]*KPH + cseg[e])*2,
                 &B[(size_t)crow[e] * ML + k0 + cseg[e]]);
        }
        CP_COMMIT();
    }
    for (int c = 0; c < 8; c++) {
        const int st = c % 3;
        if (c + 1 < 8) { CP_WAIT1(); } else { CP_WAIT0(); }
        __syncthreads();
        if (c + 2 < 8) {
            const int nst = (c + 2) % 3;
            const int k0 = (c + 2) * 32;
            #pragma unroll
            for (int e = 0; e < 2; e++) {
                cp16(sbase + (uint32_t)(nst*HSTG + crow[e]*KPH + cseg[e])*2,
                     &A[(size_t)crow[e] * ML + k0 + cseg[e]]);
                cp16(bbase + (uint32_t)(nst*HSTG + crow[e]*KPH + cseg[e])*2,
                     &B[(size_t)crow[e] * ML + k0 + cseg[e]]);
            }
            CP_COMMIT();
        }
        const uint32_t a_st = sbase + (uint32_t)(st*HSTG)*2 + a_lm;
        const uint32_t b_st = bbase + (uint32_t)(st*HSTG)*2 + b_lm;
        #pragma unroll
        for (int ks = 0; ks < 2; ks++) {
            uint32_t af[4][4];
            #pragma unroll
            for (int mi = 0; mi < 4; mi++)
                ldsm_x4(af[mi][0], af[mi][1], af[mi][2], af[mi][3],
                        a_st + (uint32_t)((wm*64 + mi*16)*KPH + ks*16)*2);
            uint32_t bf[4][2];
            #pragma unroll
            for (int p = 0; p < 2; p++)
                ldsm_x4(bf[2*p][0], bf[2*p][1], bf[2*p+1][0], bf[2*p+1][1],
                        b_st + (uint32_t)((wn*32 + p*16)*KPH + ks*16)*2);
            #pragma unroll
            for (int mi = 0; mi < 4; mi++)
                #pragma unroll
                for (int ni = 0; ni < 4; ni++)
                    mma_bf16_16x8x16(acc[mi][ni],
                        af[mi][0], af[mi][1], af[mi][2], af[mi][3],
                        bf[ni][0], bf[ni][1]);
        }
    }

    #pragma unroll
    for (int mi = 0; mi < 4; mi++) {
        #pragma unroll
        for (int ni = 0; ni < 4; ni++) {
            int grow = m0 + wm*64 + mi*16 + gr;
            int gcol = n0 + wn*32 + ni*8 + gc*2;
            const float* a = acc[mi][ni];
            float d0, d1, d2, d3;
            if (U) {
                __nv_bfloat162 u0 = *reinterpret_cast<const __nv_bfloat162*>(&U[(size_t)grow * ML + gcol]);
                __nv_bfloat162 u1 = *reinterpret_cast<const __nv_bfloat162*>(&U[(size_t)(grow+8) * ML + gcol]);
                d0 = c1*__bfloat162float(u0.x) + c2*a[0];
                d1 = c1*__bfloat162float(u0.y) + c2*a[1];
                d2 = c1*__bfloat162float(u1.x) + c2*a[2];
                d3 = c1*__bfloat162float(u1.y) + c2*a[3];
            } else {
                d0 = c2*a[0]; d1 = c2*a[1]; d2 = c2*a[2]; d3 = c2*a[3];
            }
            __nv_bfloat16 h0 = __float2bfloat16(d0), h1 = __float2bfloat16(d1);
            __nv_bfloat16 h2 = __float2bfloat16(d2), h3 = __float2bfloat16(d3);
            if (Cn) {
                __nv_bfloat162 p0; p0.x = h0; p0.y = h1;
                __nv_bfloat162 p1; p1.x = h2; p1.y = h3;
                *reinterpret_cast<__nv_bfloat162*>(&Cn[(size_t)grow * ML + gcol]) = p0;
                *reinterpret_cast<__nv_bfloat162*>(&Cn[(size_t)(grow+8) * ML + gcol]) = p1;
            }
            if (Ct) {
                Ct[(size_t)gcol * ML + grow]       = h0;
                Ct[(size_t)(gcol+1) * ML + grow]   = h1;
                Ct[(size_t)gcol * ML + grow+8]     = h2;
                Ct[(size_t)(gcol+1) * ML + grow+8] = h3;
            }
            if (Cf) {
                *reinterpret_cast<float2*>(&Cf[(size_t)grow * ML + gcol]) =
                    make_float2(cvt_tf32(d0), cvt_tf32(d1));
                *reinterpret_cast<float2*>(&Cf[(size_t)(grow+8) * ML + gcol]) =
                    make_float2(cvt_tf32(d2), cvt_tf32(d3));
            }
        }
    }
}

// ============ plain batched GEMM: C[z] = A[z] @ B[z]^T (B K-major; sims) ============
__global__ void __launch_bounds__(256, 2) gemm_tc_kernel(
    const float* __restrict__ A, const float* __restrict__ B, float* __restrict__ C,
    int lda, int ldb, int ldc, int kch,
    size_t sA, size_t sB, size_t sC)
{
    extern __shared__ float sm[];
    const int tid = threadIdx.x;
    const int z = blockIdx.z;
    const int m0 = blockIdx.y * 128, n0 = blockIdx.x * 128;
    A += (size_t)z * sA + (size_t)m0 * lda;
    B += (size_t)z * sB + (size_t)n0 * ldb;
    C += (size_t)z * sC;
    float acc[4][4][4];
    #pragma unroll
    for (int mi = 0; mi < 4; mi++)
        #pragma unroll
        for (int ni = 0; ni < 4; ni++)
            #pragma unroll
            for (int e = 0; e < 4; e++) acc[mi][ni][e] = 0.f;
    mainloop128x128(A, B, lda, ldb, kch, sm, tid, acc);
    const int wid = tid >> 5, lane = tid & 31;
    const int gr = lane >> 2, gc = lane & 3;
    const int wm = wid >> 2, wn = wid & 3;
    #pragma unroll
    for (int mi = 0; mi < 4; mi++) {
        #pragma unroll
        for (int ni = 0; ni < 4; ni++) {
            int lr = m0 + wm*64 + mi*16 + gr;
            int lc = n0 + wn*32 + ni*8 + gc*2;
            const float* a = acc[mi][ni];
            *reinterpret_cast<float2*>(&C[(size_t)lr * ldc + lc]) = make_float2(a[0], a[1]);
            *reinterpret_cast<float2*>(&C[(size_t)(lr+8) * ldc + lc]) = make_float2(a[2], a[3]);
        }
    }
}

// ============ QKV GEMM with scatter epilogue (tf32-rounded outputs) ============
__global__ void __launch_bounds__(256, 2) qkv_tc_kernel(void) {
    extern __shared__ float sm[];
    const int tid = threadIdx.x;
    const int m0 = blockIdx.y * 128;
    const int n0 = blockIdx.x * 128;
    const float* A = g_xt + (size_t)m0 * CDIM;
    const float* B = g_wqkvT + (size_t)n0 * CDIM;
    float acc[4][4][4];
    #pragma unroll
    for (int mi = 0; mi < 4; mi++)
        #pragma unroll
        for (int ni = 0; ni < 4; ni++)
            #pragma unroll
            for (int e = 0; e < 4; e++) acc[mi][ni][e] = 0.f;
    mainloop128x128(A, B, CDIM, CDIM, CDIM/32, sm, tid, acc);
    const int wid = tid >> 5, lane = tid & 31;
    const int gr = lane >> 2, gc = lane & 3;
    const int wm = wid >> 2, wn = wid & 3;
    #pragma unroll
    for (int mi = 0; mi < 4; mi++) {
        int m = m0 + wm*64 + mi*16 + gr;
        int b = m >> 10, i = m & 1023;
        #pragma unroll
        for (int ni = 0; ni < 4; ni++) {
            int n = n0 + wn*32 + ni*8 + gc*2;
            int which = n >> 9;
            int h = (n >> 6) & 7;
            int d = n & 63;
            int bh = b*8 + h;
            float* dst = (which == 0) ? g_q : ((which == 1) ? g_k : g_v);
            float sc = (which == 0) ? 0.125f : 1.0f;
            const float* a = acc[mi][ni];
            float r0 = cvt_tf32(a[0]*sc), r1 = cvt_tf32(a[1]*sc);
            float r2 = cvt_tf32(a[2]*sc), r3 = cvt_tf32(a[3]*sc);
            *reinterpret_cast<float2*>(&dst[((size_t)(bh*NTOK + i))*DH + d]) = make_float2(r0, r1);
            *reinterpret_cast<float2*>(&dst[((size_t)(bh*NTOK + i + 8))*DH + d]) = make_float2(r2, r3);
        }
    }
}

// ============ final GEMM: out = outf @ woutT^T + bias, transposed store (fp32) ============
__global__ void __launch_bounds__(256, 2) final_tc_kernel(
    const float* __restrict__ bias, float* __restrict__ out)
{
    extern __shared__ float sm[];
    const int tid = threadIdx.x;
    const int m0 = blockIdx.y * 128;
    const int n0 = blockIdx.x * 128;
    const float* A = g_outf + (size_t)m0 * CDIM;
    const float* B = g_woutT + (size_t)n0 * CDIM;
    float acc[4][4][4];
    #pragma unroll
    for (int mi = 0; mi < 4; mi++)
        #pragma unroll
        for (int ni = 0; ni < 4; ni++)
            #pragma unroll
            for (int e = 0; e < 4; e++) acc[mi][ni][e] = 0.f;
    mainloop128x128(A, B, CDIM, CDIM, CDIM/32, sm, tid, acc);
    const int wid = tid >> 5, lane = tid & 31;
    const int gr = lane >> 2, gc = lane & 3;
    const int wm = wid >> 2, wn = wid & 3;
    #pragma unroll
    for (int mi = 0; mi < 4; mi++) {
        int m = m0 + wm*64 + mi*16 + gr;
        int b = m >> 10, i = m & 1023;
        #pragma unroll
        for (int ni = 0; ni < 4; ni++) {
            int n = n0 + wn*32 + ni*8 + gc*2;
            const float* a = acc[mi][ni];
            float b0 = bias[n], b1 = bias[n+1];
            out[((size_t)(b*CDIM + n))*NTOK + i]       = a[0] + b0;
            out[((size_t)(b*CDIM + n + 1))*NTOK + i]   = a[1] + b1;
            out[((size_t)(b*CDIM + n))*NTOK + i + 8]   = a[2] + b0;
            out[((size_t)(b*CDIM + n + 1))*NTOK + i + 8] = a[3] + b1;
        }
    }
}

// ============ 128x64 batched GEMM, B row-major [K,64]: C = A @ B ============
// flatC path optionally fuses the depthwise 33-tap conv residual (rk != nullptr):
// C[(b*1024+i)*512 + h*64 + d] = tf32(acc + sum_t rk[h][t]*v[bh][i+t-16][d])
__global__ void __launch_bounds__(256, 2) gemm64_rowB_kernel(
    const float* __restrict__ A, const float* __restrict__ B, float* __restrict__ C,
    const float* __restrict__ rk,
    int lda, int kch, size_t sA, size_t sB, int flatC)
{
    extern __shared__ float sm[];
    __shared__ float s_ker[KSZ];
    const uint32_t sbase = (uint32_t)__cvta_generic_to_shared(sm);
    const uint32_t bbase = sbase + 3*PSTAGE*4;
    const int tid = threadIdx.x;
    const int wid = tid >> 5, lane = tid & 31;
    const int gr = lane >> 2, gc = lane & 3;
    const int wm = wid >> 1, wn = wid & 1;
    const int g = lane >> 3, r8 = lane & 7;
    const uint32_t a_lm = (uint32_t)((wm*32 + (g&1)*8 + r8)*PPITCH + (g>>1)*4)*4;
    const int z = blockIdx.z;
    const int m0 = blockIdx.x * 128;
    A += (size_t)z * sA + (size_t)m0 * lda;
    B += (size_t)z * sB;
    if (flatC) C += (size_t)(z >> 3) * (NTOK*CDIM) + (size_t)(z & 7) * DH;
    else       C += (size_t)z * (ML*DH);
    if (rk && tid < KSZ) s_ker[tid] = rk[(z & 7) * KSZ + tid];  // visible after mainloop syncs

    int arow[4], ac4[4], bk[2], bn4[2];
    #pragma unroll
    for (int e = 0; e < 4; e++) {
        int f4 = e * 256 + tid;
        arow[e] = f4 >> 3;  ac4[e] = (f4 & 7) << 2;
    }
    #pragma unroll
    for (int e = 0; e < 2; e++) {
        int f4 = e * 256 + tid;
        bk[e] = f4 >> 4;  bn4[e] = (f4 & 15) << 2;
    }

    float acc[2][4][4];
    #pragma unroll
    for (int mi = 0; mi < 2; mi++)
        #pragma unroll
        for (int ni = 0; ni < 4; ni++)
            #pragma unroll
            for (int e = 0; e < 4; e++) acc[mi][ni][e] = 0.f;

    #pragma unroll
    for (int p = 0; p < 2; p++) {
        if (p < kch) {
            const int k0 = p * 32;
            #pragma unroll
            for (int e = 0; e < 4; e++)
                cp16(sbase + (uint32_t)(p*PSTAGE + arow[e]*PPITCH + ac4[e])*4,
                     &A[(size_t)arow[e] * lda + k0 + ac4[e]]);
            #pragma unroll
            for (int e = 0; e < 2; e++)
                cp16(bbase + (uint32_t)(p*BRSTG64 + bk[e]*BNP64 + bn4[e])*4,
                     &B[(size_t)(k0 + bk[e]) * DH + bn4[e]]);
        }
        CP_COMMIT();
    }

    for (int c = 0; c < kch; c++) {
        const int st = c % 3;
        if (c + 1 < kch) { CP_WAIT1(); } else { CP_WAIT0(); }
        __syncthreads();
        if (c + 2 < kch) {
            const int nst = (c + 2) % 3;
            const int k0 = (c + 2) * 32;
            #pragma unroll
            for (int e = 0; e < 4; e++)
                cp16(sbase + (uint32_t)(nst*PSTAGE + arow[e]*PPITCH + ac4[e])*4,
                     &A[(size_t)arow[e] * lda + k0 + ac4[e]]);
            #pragma unroll
            for (int e = 0; e < 2; e++)
                cp16(bbase + (uint32_t)(nst*BRSTG64 + bk[e]*BNP64 + bn4[e])*4,
                     &B[(size_t)(k0 + bk[e]) * DH + bn4[e]]);
            CP_COMMIT();
        }
        const uint32_t a_st = sbase + (uint32_t)(st*PSTAGE)*4 + a_lm;
        const float* Bb = sm + 3*PSTAGE + st*BRSTG64;
        #pragma unroll
        for (int ks = 0; ks < 4; ks++) {
            uint32_t af[2][4];
            #pragma unroll
            for (int mi = 0; mi < 2; mi++)
                ldsm_x4(af[mi][0], af[mi][1], af[mi][2], af[mi][3],
                        a_st + (uint32_t)(mi*16*PPITCH + ks*8)*4);
            uint32_t bf[4][2];
            #pragma unroll
            for (int ni = 0; ni < 4; ni++) {
                int n = wn*32 + ni*8 + gr;
                bf[ni][0] = __float_as_uint(Bb[(ks*8 + gc)*BNP64 + n]);
                bf[ni][1] = __float_as_uint(Bb[(ks*8 + gc + 4)*BNP64 + n]);
            }
            #pragma unroll
            for (int mi = 0; mi < 2; mi++)
                #pragma unroll
                for (int ni = 0; ni < 4; ni++)
                    mma_tf32_16x8x8(acc[mi][ni],
                        af[mi][0], af[mi][1], af[mi][2], af[mi][3],
                        bf[ni][0], bf[ni][1]);
        }
    }

    const int ldc = flatC ? CDIM : DH;
    if (rk) {
        // fused depthwise conv residual (flatC only): v footprint is L1-resident
        const float* vb = g_v + (size_t)z * (NTOK*DH);
        #pragma unroll
        for (int mi = 0; mi < 2; mi++) {
            #pragma unroll
            for (int ni = 0; ni < 4; ni++) {
                int lr = m0 + wm*32 + mi*16 + gr;
                int lc = wn*32 + ni*8 + gc*2;
                const float* a = acc[mi][ni];
                float s00 = 0.f, s01 = 0.f, s10 = 0.f, s11 = 0.f;
                for (int t = 0; t < KSZ; t++) {
                    float kt = s_ker[t];
                    int i1 = lr + t - (KSZ/2);
                    int i2 = i1 + 8;
                    if (i1 >= 0 && i1 < NTOK) {
                        float2 vv = *reinterpret_cast<const float2*>(&vb[(size_t)i1*DH + lc]);
                        s00 += kt * vv.x; s01 += kt * vv.y;
                    }
                    if (i2 >= 0 && i2 < NTOK) {
                        float2 vv = *reinterpret_cast<const float2*>(&vb[(size_t)i2*DH + lc]);
                        s10 += kt * vv.x; s11 += kt * vv.y;
                    }
                }
                float d0 = cvt_tf32(a[0] + s00), d1 = cvt_tf32(a[1] + s01);
                float d2 = cvt_tf32(a[2] + s10), d3 = cvt_tf32(a[3] + s11);
                *reinterpret_cast<float2*>(&C[(size_t)lr * ldc + lc]) = make_float2(d0, d1);
                *reinterpret_cast<float2*>(&C[(size_t)(lr+8) * ldc + lc]) = make_float2(d2, d3);
            }
        }
    } else {
        #pragma unroll
        for (int mi = 0; mi < 2; mi++) {
            #pragma unroll
            for (int ni = 0; ni < 4; ni++) {
                int lr = m0 + wm*32 + mi*16 + gr;
                int lc = wn*32 + ni*8 + gc*2;
                const float* a = acc[mi][ni];
                float d0 = cvt_tf32(a[0]), d1 = cvt_tf32(a[1]);
                float d2 = cvt_tf32(a[2]), d3 = cvt_tf32(a[3]);
                *reinterpret_cast<float2*>(&C[(size_t)lr * ldc + lc]) = make_float2(d0, d1);
                *reinterpret_cast<float2*>(&C[(size_t)(lr+8) * ldc + lc]) = make_float2(d2, d3);
            }
        }
    }
}

// ---------------- batched 2D transpose (tf32-rounded output) ----------------
__global__ void transpose_kernel(const float* __restrict__ in, float* __restrict__ out,
                                 int R, int C) {
    __shared__ float tile[32][33];
    const int z = blockIdx.z;
    in  += (size_t)z * R * C;
    out += (size_t)z * R * C;
    int c0 = blockIdx.x * 32, r0 = blockIdx.y * 32;
    int tx = threadIdx.x, ty = threadIdx.y;
    #pragma unroll
    for (int j = 0; j < 4; j++)
        tile[ty + j*8][tx] = in[(size_t)(r0 + ty + j*8) * C + c0 + tx];
    __syncthreads();
    #pragma unroll
    for (int j = 0; j < 4; j++)
        out[(size_t)(c0 + ty + j*8) * R + r0 + tx] = cvt_tf32(tile[tx][ty + j*8]);
}

// ================= tf32 pinv batched GEMM: Cn = c1*U + c2*(P @ B), B row-major =================
__global__ void __launch_bounds__(256, 2) pinv_mma_kernel(
    const float* __restrict__ P, const float* __restrict__ B,
    const float* __restrict__ U, float* __restrict__ Cn,
    float c1, float c2)
{
    extern __shared__ float sm[];
    const int tid = threadIdx.x;
    const int wid = tid >> 5, lane = tid & 31;
    const int wm = wid >> 2, wn = wid & 3;
    const int gr = lane >> 2, gc = lane & 3;
    const int tile = blockIdx.x;
    const int batch = tile >> 2;
    const int m0 = ((tile >> 1) & 1) << 7;
    const int n0 = (tile & 1) << 7;
    const size_t boff = (size_t)batch << 16;
    P += boff + (size_t)m0 * ML;
    B += boff + n0;
    if (U) U += boff;
    Cn += boff;

    float acc[4][4][4];
    #pragma unroll
    for (int mi = 0; mi < 4; mi++)
        #pragma unroll
        for (int ni = 0; ni < 4; ni++)
            #pragma unroll
            for (int e = 0; e < 4; e++) acc[mi][ni][e] = 0.f;
    mainloop128x128_rowB(P, B, ML, ML, 8, sm, tid, acc);

    #pragma unroll
    for (int mi = 0; mi < 4; mi++) {
        #pragma unroll
        for (int ni = 0; ni < 4; ni++) {
            int lr = wm*64 + mi*16 + gr;
            int lc = wn*32 + ni*8 + gc*2;
            int grow = m0 + lr, gcol = n0 + lc;
            const float* a = acc[mi][ni];
            float d0, d1, d2, d3;
            if (U) {
                float2 u0 = *reinterpret_cast<const float2*>(&U[(size_t)grow * ML + gcol]);
                float2 u1 = *reinterpret_cast<const float2*>(&U[(size_t)(grow+8) * ML + gcol]);
                d0 = c1*u0.x + c2*a[0]; d1 = c1*u0.y + c2*a[1];
                d2 = c1*u1.x + c2*a[2]; d3 = c1*u1.y + c2*a[3];
            } else {
                d0 = c2*a[0]; d1 = c2*a[1]; d2 = c2*a[2]; d3 = c2*a[3];
            }
            d0 = cvt_tf32(d0); d1 = cvt_tf32(d1); d2 = cvt_tf32(d2); d3 = cvt_tf32(d3);
            *reinterpret_cast<float2*>(&Cn[(size_t)grow * ML + gcol]) = make_float2(d0, d1);
            *reinterpret_cast<float2*>(&Cn[(size_t)(grow+8) * ML + gcol]) = make_float2(d2, d3);
        }
    }
}

// ---------------- landmark means (tf32-rounded) ----------------
__global__ void land_kernel() {
    int idx = blockIdx.x * blockDim.x + threadIdx.x;
    if (idx >= BHN*ML*DH) return;
    int d  = idx & 63;
    int j  = (idx >> 6) & 255;
    int bh = idx >> 14;
    size_t base = ((size_t)bh * NTOK + j*4) * DH + d;
    g_ql[idx] = cvt_tf32(0.25f * (g_q[base] + g_q[base+64] + g_q[base+128] + g_q[base+192]));
    g_kl[idx] = cvt_tf32(0.25f * (g_k[base] + g_k[base+64] + g_k[base+128] + g_k[base+192]));
}

// ---------------- warp-per-row softmax: fast exp, zero block barriers ----------------
template<int W>
__global__ void softmax_warp_kernel(float* __restrict__ data) {
    const int lane = threadIdx.x & 31;
    const int row = blockIdx.x * 8 + (threadIdx.x >> 5);
    float* r = data + (size_t)row * W;
    constexpr int PE = W / 32;
    float v[PE];
    float mx = -1e30f;
    #pragma unroll
    for (int e = 0; e < PE; e++) { v[e] = r[lane + e*32]; mx = fmaxf(mx, v[e]); }
    #pragma unroll
    for (int o = 16; o > 0; o >>= 1) mx = fmaxf(mx, __shfl_xor_sync(0xffffffffu, mx, o));
    float s = 0.f;
    #pragma unroll
    for (int e = 0; e < PE; e++) { v[e] = __expf(v[e] - mx); s += v[e]; }
    #pragma unroll
    for (int o = 16; o > 0; o >>= 1) s += __shfl_xor_sync(0xffffffffu, s, o);
    float inv = 1.0f / s;
    #pragma unroll
    for (int e = 0; e < PE; e++) r[lane + e*32] = cvt_tf32(v[e] * inv);
}

// ---------------- pinv scale reductions ----------------
__global__ void reset_max_kernel() { if (threadIdx.x == 0) { g_colmax = 0u; g_rowmax = 0u; } }

__global__ void colmax_kernel() {
    int gw = (blockIdx.x * blockDim.x + threadIdx.x) >> 5;
    int lane = threadIdx.x & 31;
    if (gw >= BHN * ML) return;
    const float* row = g_attn2 + (size_t)gw * ML;
    float s = 0.f;
    #pragma unroll
    for (int j = lane; j < ML; j += 32) s += fabsf(row[j]);
    #pragma unroll
    for (int o = 16; o > 0; o >>= 1) s += __shfl_down_sync(0xffffffffu, s, o);
    if (lane == 0) atomicMax(&g_colmax, __float_as_uint(s));
}

__global__ void rowmax_kernel() {
    int idx = blockIdx.x * blockDim.x + threadIdx.x;
    if (idx >= BHN * ML) return;
    int bh = idx >> 8, j = idx & 255;
    const float* base = g_attn2 + (size_t)bh * ML * ML + j;
    float s = 0.f;
    for (int i = 0; i < ML; i++) s += fabsf(base[(size_t)i * ML]);
    atomicMax(&g_rowmax, __float_as_uint(s));
}

// zinit: z0 (bf16, row + transposed) and a2h (bf16 of a2)
__global__ void zinit_kernel() {
    float inv = 1.0f / (__uint_as_float(g_colmax) * __uint_as_float(g_rowmax));
    size_t idx = (size_t)blockIdx.x * 256 + threadIdx.x;
    int j  = idx & 255;
    int i  = (idx >> 8) & 255;
    size_t bh = idx >> 16;
    float a2v  = g_attn2[idx];
    float a2tv = g_attn2[(bh << 16) + ((size_t)j << 8) + i];
    g_zhA[idx]  = __float2bfloat16(a2tv * inv);   // z0 row-major = scaled x^T
    g_zhTA[idx] = __float2bfloat16(a2v * inv);    // z0^T = scaled x
    g_a2h[idx]  = __float2bfloat16(a2v);
}

// ---------------- host ----------------
extern "C" void kernel_launch(void* const* d_in, const int* in_sizes, int n_in,
                              void* d_out, int out_size) {
    const float* x     = (const float*)d_in[0];
    const float* w_qkv = (const float*)d_in[1];
    const float* w_out = (const float*)d_in[2];
    const float* b_out = (const float*)d_in[3];
    const float* rk    = (const float*)d_in[4];
    float* out = (float*)d_out;

    float *xt, *wqkvT, *woutT, *q, *k, *v, *ql, *kl, *a1, *a3, *a2;
    float *zA, *zB, *xz, *t1, *t2, *av, *bv, *outf;
    __nv_bfloat16 *a2h, *zhA, *zhB, *zhTA, *zhTB, *xzh, *xzhT, *t1hT, *t2hT;
    cudaGetSymbolAddress((void**)&xt, g_xt);
    cudaGetSymbolAddress((void**)&wqkvT, g_wqkvT);
    cudaGetSymbolAddress((void**)&woutT, g_woutT);
    cudaGetSymbolAddress((void**)&q,  g_q);
    cudaGetSymbolAddress((void**)&k,  g_k);
    cudaGetSymbolAddress((void**)&v,  g_v);
    cudaGetSymbolAddress((void**)&ql, g_ql);
    cudaGetSymbolAddress((void**)&kl, g_kl);
    cudaGetSymbolAddress((void**)&a1, g_attn1);
    cudaGetSymbolAddress((void**)&a3, g_attn3);
    cudaGetSymbolAddress((void**)&a2, g_attn2);
    cudaGetSymbolAddress((void**)&zA, g_zA);
    cudaGetSymbolAddress((void**)&zB, g_zB);
    cudaGetSymbolAddress((void**)&xz, g_xz);
    cudaGetSymbolAddress((void**)&t1, g_t1);
    cudaGetSymbolAddress((void**)&t2, g_t2);
    cudaGetSymbolAddress((void**)&av, g_av);
    cudaGetSymbolAddress((void**)&bv, g_bv);
    cudaGetSymbolAddress((void**)&outf, g_outf);
    cudaGetSymbolAddress((void**)&a2h,  g_a2h);
    cudaGetSymbolAddress((void**)&zhA,  g_zhA);
    cudaGetSymbolAddress((void**)&zhB,  g_zhB);
    cudaGetSymbolAddress((void**)&zhTA, g_zhTA);
    cudaGetSymbolAddress((void**)&zhTB, g_zhTB);
    cudaGetSymbolAddress((void**)&xzh,  g_xzh);
    cudaGetSymbolAddress((void**)&xzhT, g_xzhT);
    cudaGetSymbolAddress((void**)&t1hT, g_t1hT);
    cudaGetSymbolAddress((void**)&t2hT, g_t2hT);

    cudaFuncSetAttribute(pinv_mma_kernel,    cudaFuncAttributeMaxDynamicSharedMemorySize, PB_SMEM3);
    cudaFuncSetAttribute(pinv_bf16_kernel,   cudaFuncAttributeMaxDynamicSharedMemorySize, BH_SMEM3);
    cudaFuncSetAttribute(gemm_tc_kernel,     cudaFuncAttributeMaxDynamicSharedMemorySize, G128_SMEM3);
    cudaFuncSetAttribute(qkv_tc_kernel,      cudaFuncAttributeMaxDynamicSharedMemorySize, G128_SMEM3);
    cudaFuncSetAttribute(final_tc_kernel,    cudaFuncAttributeMaxDynamicSharedMemorySize, G128_SMEM3);
    cudaFuncSetAttribute(gemm64_rowB_kernel, cudaFuncAttributeMaxDynamicSharedMemorySize, G64R_SMEM3);

    // 0) layout prep
    transpose_kernel<<<dim3(NTOK/32, CDIM/32, BATCH), dim3(32,8)>>>(x, xt, CDIM, NTOK);
    transpose_kernel<<<dim3(48, 16, 1), dim3(32,8)>>>(w_qkv, wqkvT, CDIM, 3*CDIM);
    transpose_kernel<<<dim3(16, 16, 1), dim3(32,8)>>>(w_out, woutT, CDIM, CDIM);
    // 1) QKV projection
    qkv_tc_kernel<<<dim3(12, 256), 256, G128_SMEM3>>>();
    // 2) landmarks
    land_kernel<<<(BHN*ML*DH + 255)/256, 256>>>();
    // 3) similarity GEMMs
    gemm_tc_kernel<<<dim3(2, 8, BHN), 256, G128_SMEM3>>>(q,  kl, a1, DH, DH, ML,   2,
        (size_t)NTOK*DH, (size_t)ML*DH, (size_t)NTOK*ML);
    gemm_tc_kernel<<<dim3(2, 2, BHN), 256, G128_SMEM3>>>(ql, kl, a2, DH, DH, ML,   2,
        (size_t)ML*DH,   (size_t)ML*DH, (size_t)ML*ML);
    gemm_tc_kernel<<<dim3(8, 2, BHN), 256, G128_SMEM3>>>(ql, k,  a3, DH, DH, NTOK, 2,
        (size_t)ML*DH,   (size_t)NTOK*DH, (size_t)ML*NTOK);
    // 4) softmaxes — warp-per-row, fast exp
    softmax_warp_kernel<256> <<<BHN*NTOK/8, 256>>>(a1);
    softmax_warp_kernel<256> <<<BHN*ML/8,   256>>>(a2);
    softmax_warp_kernel<1024><<<BHN*ML/8,   256>>>(a3);
    // 5) pinv init (bf16 z0 / z0^T / a2h)
    reset_max_kernel<<<1, 32>>>();
    colmax_kernel<<<(BHN*ML*32)/256, 256>>>();
    rowmax_kernel<<<(BHN*ML)/256, 256>>>();
    zinit_kernel<<<(BHN*ML*ML)/256, 256>>>();
    // 6) Newton–Schulz: iterations 1–5 in bf16, iteration 6 in tf32
    __nv_bfloat16 *zh_in = zhA, *zh_out = zhB, *zhT_in = zhTA, *zhT_out = zhTB;
    for (int it = 0; it < 5; it++) {
        pinv_bf16_kernel<<<1024, 256, BH_SMEM3>>>(a2h, zhT_in, nullptr, xzh, xzhT, nullptr, 0.0f, 1.0f);
        pinv_bf16_kernel<<<1024, 256, BH_SMEM3>>>(xzh, xzhT, xzh, nullptr, t1hT, nullptr, 7.0f, -1.0f);
        pinv_bf16_kernel<<<1024, 256, BH_SMEM3>>>(xzh, t1hT, xzh, nullptr, t2hT, nullptr, 15.0f, -1.0f);
        if (it < 4) {
            pinv_bf16_kernel<<<1024, 256, BH_SMEM3>>>(zh_in, t2hT, zh_in, zh_out, zhT_out, nullptr, 3.25f, -0.25f);
            __nv_bfloat16* tmp;
            tmp = zh_in;  zh_in  = zh_out;  zh_out  = tmp;
            tmp = zhT_in; zhT_in = zhT_out; zhT_out = tmp;
        } else {
            pinv_bf16_kernel<<<1024, 256, BH_SMEM3>>>(zh_in, t2hT, zh_in, nullptr, nullptr, zA, 3.25f, -0.25f);
        }
    }
    pinv_mma_kernel<<<1024, 256, PB_SMEM3>>>(a2, zA, nullptr, xz, 0.0f, 1.0f);
    pinv_mma_kernel<<<1024, 256, PB_SMEM3>>>(xz, xz, xz, t1, 7.0f, -1.0f);
    pinv_mma_kernel<<<1024, 256, PB_SMEM3>>>(xz, t1, xz, t2, 15.0f, -1.0f);
    pinv_mma_kernel<<<1024, 256, PB_SMEM3>>>(zA, t2, zA, zB, 3.25f, -0.25f);
    float* zfin = zB;
    // 7) output chain: av = attn3@v ; bv = z@av ; outf = attn1@bv (+ fused conv residual)
    gemm64_rowB_kernel<<<dim3(2, 1, BHN), 256, G64R_SMEM3>>>(a3, v, av, nullptr,
        NTOK, 32, (size_t)ML*NTOK, (size_t)NTOK*DH, 0);
    gemm64_rowB_kernel<<<dim3(2, 1, BHN), 256, G64R_SMEM3>>>(zfin, av, bv, nullptr,
        ML, 8, (size_t)ML*ML, (size_t)ML*DH, 0);
    gemm64_rowB_kernel<<<dim3(8, 1, BHN), 256, G64R_SMEM3>>>(a1, bv, outf, rk,
        ML, 8, (size_t)NTOK*ML, (size_t)ML*DH, 1);
    // 8) output projection + bias + transposed store
    final_tc_kernel<<<dim3(4, 256), 256, G128_SMEM3>>>(b_out, out);
}

// round 14
// speedup vs baseline: 1.0383x; 1.0383x over previous
#include <cuda_runtime.h>
#include <cuda_bf16.h>
#include <cstdint>
#include <cstddef>

#define BATCH 32
#define HEADS 8
#define NTOK 1024
#define DH 64
#define ML 256          // landmarks
#define CDIM 512
#define BHN (BATCH*HEADS)   // 256
#define KSZ 33

// ---------------- device scratch ----------------
__device__ float g_xt[(size_t)BATCH*NTOK*CDIM];     // x transposed: (b, n, c), tf32-rounded
__device__ float g_wqkvT[3*CDIM*CDIM];              // (1536, 512), tf32-rounded
__device__ float g_woutT[CDIM*CDIM];                // (512, 512), tf32-rounded
__device__ float g_q [BHN*NTOK*DH];
__device__ float g_k [BHN*NTOK*DH];
__device__ float g_v [BHN*NTOK*DH];
__device__ float g_ql[BHN*ML*DH];
__device__ float g_kl[BHN*ML*DH];
__device__ float g_attn1[(size_t)BHN*NTOK*ML];      // (bh,1024,256)
__device__ float g_attn3[(size_t)BHN*ML*NTOK];      // (bh,256,1024)
__device__ float g_attn2[BHN*ML*ML];
__device__ float g_zA[BHN*ML*ML];
__device__ float g_zB[BHN*ML*ML];
__device__ float g_xz[BHN*ML*ML];
__device__ float g_t1[BHN*ML*ML];
__device__ float g_t2[BHN*ML*ML];
__device__ float g_av[BHN*ML*DH];
__device__ float g_bv[BHN*ML*DH];
__device__ float g_outf[(size_t)BATCH*NTOK*CDIM];   // (b, n, 512)
__device__ unsigned g_colmax;
__device__ unsigned g_rowmax;
// bf16 pinv buffers
__device__ __nv_bfloat16 g_a2h [BHN*ML*ML];   // bf16(a2), row-major [M][K]
__device__ __nv_bfloat16 g_zhA [BHN*ML*ML];   // z row-major
__device__ __nv_bfloat16 g_zhB [BHN*ML*ML];
__device__ __nv_bfloat16 g_zhTA[BHN*ML*ML];   // z^T (K-major for B operand)
__device__ __nv_bfloat16 g_zhTB[BHN*ML*ML];
__device__ __nv_bfloat16 g_xzh [BHN*ML*ML];
__device__ __nv_bfloat16 g_xzhT[BHN*ML*ML];
__device__ __nv_bfloat16 g_t1hT[BHN*ML*ML];
__device__ __nv_bfloat16 g_t2hT[BHN*ML*ML];

// ================= helpers =================
__device__ __forceinline__ float cvt_tf32(float x) {
    uint32_t u;
    asm("cvt.rna.tf32.f32 %0, %1;" : "=r"(u) : "f"(x));
    return __uint_as_float(u);
}
__device__ __forceinline__ void mma_tf32_16x8x8(float c[4],
    uint32_t a0, uint32_t a1, uint32_t a2, uint32_t a3, uint32_t b0, uint32_t b1) {
    asm volatile(
        "mma.sync.aligned.m16n8k8.row.col.f32.tf32.tf32.f32 "
        "{%0,%1,%2,%3},{%4,%5,%6,%7},{%8,%9},{%0,%1,%2,%3};"
        : "+f"(c[0]), "+f"(c[1]), "+f"(c[2]), "+f"(c[3])
        : "r"(a0), "r"(a1), "r"(a2), "r"(a3), "r"(b0), "r"(b1));
}
__device__ __forceinline__ void mma_bf16_16x8x16(float c[4],
    uint32_t a0, uint32_t a1, uint32_t a2, uint32_t a3, uint32_t b0, uint32_t b1) {
    asm volatile(
        "mma.sync.aligned.m16n8k16.row.col.f32.bf16.bf16.f32 "
        "{%0,%1,%2,%3},{%4,%5,%6,%7},{%8,%9},{%0,%1,%2,%3};"
        : "+f"(c[0]), "+f"(c[1]), "+f"(c[2]), "+f"(c[3])
        : "r"(a0), "r"(a1), "r"(a2), "r"(a3), "r"(b0), "r"(b1));
}
__device__ __forceinline__ void ldsm_x4(uint32_t& r0, uint32_t& r1,
                                        uint32_t& r2, uint32_t& r3, uint32_t saddr) {
    asm volatile("ldmatrix.sync.aligned.m8n8.x4.shared.b16 {%0,%1,%2,%3}, [%4];"
                 : "=r"(r0), "=r"(r1), "=r"(r2), "=r"(r3) : "r"(saddr));
}
__device__ __forceinline__ void cp16(uint32_t dst, const void* src) {
    asm volatile("cp.async.cg.shared.global [%0], [%1], 16;" :: "r"(dst), "l"(src));
}
#define CP_COMMIT() asm volatile("cp.async.commit_group;")
#define CP_WAIT1()  asm volatile("cp.async.wait_group 1;" ::: "memory")
#define CP_WAIT0()  asm volatile("cp.async.wait_group 0;" ::: "memory")

#define PPITCH 36
#define PSTAGE (128*PPITCH)
#define G128_SMEM3 (6*PSTAGE*4)                     // 110592 (A,B both K-major fp32)

#define BNP128 136
#define BRSTG128 (32*BNP128)
#define PB_SMEM3 ((3*PSTAGE + 3*BRSTG128)*4)        // 107520

#define BNP64 72
#define BRSTG64 (32*BNP64)
#define G64R_SMEM3 ((3*PSTAGE + 3*BRSTG64)*4)       // 82944

// bf16 tiles: [128 rows][KPH halves] per chunk (32 halves data, pitch 40)
#define KPH 40
#define HSTG (128*KPH)                               // halves per stage
#define BH_SMEM3 (6*HSTG*2)                          // 61440 bytes

// ============ mainloop A: B stored K-major ([N rows][K]) — sims/qkv/final ============
__device__ __forceinline__ void mainloop128x128(
    const float* __restrict__ A, const float* __restrict__ B,
    int lda, int ldb, int kch, float* sm, int tid, float acc[4][4][4])
{
    const uint32_t sbase = (uint32_t)__cvta_generic_to_shared(sm);
    const uint32_t bbase = sbase + 3*PSTAGE*4;
    const int wid = tid >> 5, lane = tid & 31;
    const int wm = wid >> 2, wn = wid & 3;
    const int g = lane >> 3, r8 = lane & 7;
    const uint32_t a_lm = (uint32_t)((wm*64 + (g&1)*8 + r8)*PPITCH + (g>>1)*4)*4;
    const uint32_t b_lm = (uint32_t)((wn*32 + (g>>1)*8 + r8)*PPITCH + (g&1)*4)*4;
    int rrow[4], rc4[4];
    #pragma unroll
    for (int e = 0; e < 4; e++) {
        int f4 = e * 256 + tid;
        rrow[e] = f4 >> 3;
        rc4[e] = (f4 & 7) << 2;
    }
    #pragma unroll
    for (int p = 0; p < 2; p++) {
        if (p < kch) {
            const int k0 = p * 32;
            #pragma unroll
            for (int e = 0; e < 4; e++) {
                cp16(sbase + (uint32_t)(p*PSTAGE + rrow[e]*PPITCH + rc4[e])*4,
                     &A[(size_t)rrow[e] * lda + k0 + rc4[e]]);
                cp16(bbase + (uint32_t)(p*PSTAGE + rrow[e]*PPITCH + rc4[e])*4,
                     &B[(size_t)rrow[e] * ldb + k0 + rc4[e]]);
            }
        }
        CP_COMMIT();
    }
    for (int c = 0; c < kch; c++) {
        const int st = c % 3;
        if (c + 1 < kch) { CP_WAIT1(); } else { CP_WAIT0(); }
        __syncthreads();
        if (c + 2 < kch) {
            const int nst = (c + 2) % 3;
            const int k0 = (c + 2) * 32;
            #pragma unroll
            for (int e = 0; e < 4; e++) {
                cp16(sbase + (uint32_t)(nst*PSTAGE + rrow[e]*PPITCH + rc4[e])*4,
                     &A[(size_t)rrow[e] * lda + k0 + rc4[e]]);
                cp16(bbase + (uint32_t)(nst*PSTAGE + rrow[e]*PPITCH + rc4[e])*4,
                     &B[(size_t)rrow[e] * ldb + k0 + rc4[e]]);
            }
            CP_COMMIT();
        }
        const uint32_t a_st = sbase + (uint32_t)(st*PSTAGE)*4 + a_lm;
        const uint32_t b_st = bbase + (uint32_t)(st*PSTAGE)*4 + b_lm;
        #pragma unroll
        for (int ks = 0; ks < 4; ks++) {
            uint32_t af[4][4];
            #pragma unroll
            for (int mi = 0; mi < 4; mi++)
                ldsm_x4(af[mi][0], af[mi][1], af[mi][2], af[mi][3],
                        a_st + (uint32_t)(mi*16*PPITCH + ks*8)*4);
            uint32_t bf[4][2];
            #pragma unroll
            for (int p = 0; p < 2; p++)
                ldsm_x4(bf[2*p][0], bf[2*p][1], bf[2*p+1][0], bf[2*p+1][1],
                        b_st + (uint32_t)(p*16*PPITCH + ks*8)*4);
            #pragma unroll
            for (int mi = 0; mi < 4; mi++)
                #pragma unroll
                for (int ni = 0; ni < 4; ni++)
                    mma_tf32_16x8x8(acc[mi][ni],
                        af[mi][0], af[mi][1], af[mi][2], af[mi][3],
                        bf[ni][0], bf[ni][1]);
        }
    }
}

// ============ mainloop B: B stored row-major [K][N] — tf32 pinv/chain ============
__device__ __forceinline__ void mainloop128x128_rowB(
    const float* __restrict__ A, const float* __restrict__ B,
    int lda, int ldb, int kch, float* sm, int tid, float acc[4][4][4])
{
    const uint32_t sbase = (uint32_t)__cvta_generic_to_shared(sm);
    const uint32_t bbase = sbase + 3*PSTAGE*4;
    const int wid = tid >> 5, lane = tid & 31;
    const int gr = lane >> 2, gc = lane & 3;
    const int wm = wid >> 2, wn = wid & 3;
    const int g = lane >> 3, r8 = lane & 7;
    const uint32_t a_lm = (uint32_t)((wm*64 + (g&1)*8 + r8)*PPITCH + (g>>1)*4)*4;
    int arow[4], ac4[4], bk[4], bn4[4];
    #pragma unroll
    for (int e = 0; e < 4; e++) {
        int f4 = e * 256 + tid;
        arow[e] = f4 >> 3;  ac4[e] = (f4 & 7) << 2;
        bk[e]   = f4 >> 5;  bn4[e] = (f4 & 31) << 2;
    }
    #pragma unroll
    for (int p = 0; p < 2; p++) {
        if (p < kch) {
            const int k0 = p * 32;
            #pragma unroll
            for (int e = 0; e < 4; e++) {
                cp16(sbase + (uint32_t)(p*PSTAGE + arow[e]*PPITCH + ac4[e])*4,
                     &A[(size_t)arow[e] * lda + k0 + ac4[e]]);
                cp16(bbase + (uint32_t)(p*BRSTG128 + bk[e]*BNP128 + bn4[e])*4,
                     &B[(size_t)(k0 + bk[e]) * ldb + bn4[e]]);
            }
        }
        CP_COMMIT();
    }
    for (int c = 0; c < kch; c++) {
        const int st = c % 3;
        if (c + 1 < kch) { CP_WAIT1(); } else { CP_WAIT0(); }
        __syncthreads();
        if (c + 2 < kch) {
            const int nst = (c + 2) % 3;
            const int k0 = (c + 2) * 32;
            #pragma unroll
            for (int e = 0; e < 4; e++) {
                cp16(sbase + (uint32_t)(nst*PSTAGE + arow[e]*PPITCH + ac4[e])*4,
                     &A[(size_t)arow[e] * lda + k0 + ac4[e]]);
                cp16(bbase + (uint32_t)(nst*BRSTG128 + bk[e]*BNP128 + bn4[e])*4,
                     &B[(size_t)(k0 + bk[e]) * ldb + bn4[e]]);
            }
            CP_COMMIT();
        }
        const uint32_t a_st = sbase + (uint32_t)(st*PSTAGE)*4 + a_lm;
        const float* Bb = sm + 3*PSTAGE + st*BRSTG128;
        #pragma unroll
        for (int ks = 0; ks < 4; ks++) {
            uint32_t af[4][4];
            #pragma unroll
            for (int mi = 0; mi < 4; mi++)
                ldsm_x4(af[mi][0], af[mi][1], af[mi][2], af[mi][3],
                        a_st + (uint32_t)(mi*16*PPITCH + ks*8)*4);
            uint32_t bf[4][2];
            #pragma unroll
            for (int ni = 0; ni < 4; ni++) {
                int n = wn*32 + ni*8 + gr;
                bf[ni][0] = __float_as_uint(Bb[(ks*8 + gc)*BNP128 + n]);
                bf[ni][1] = __float_as_uint(Bb[(ks*8 + gc + 4)*BNP128 + n]);
            }
            #pragma unroll
            for (int mi = 0; mi < 4; mi++)
                #pragma unroll
                for (int ni = 0; ni < 4; ni++)
                    mma_tf32_16x8x8(acc[mi][ni],
                        af[mi][0], af[mi][1], af[mi][2], af[mi][3],
                        bf[ni][0], bf[ni][1]);
        }
    }
}

// ============ bf16 pinv batched GEMM: D = c1*U + c2*(A @ B^T), both K-major ============
// Outputs (each optional): Cn bf16 [M][N], Ct bf16 [N][M], Cf fp32 tf32-rounded [M][N].
__global__ void __launch_bounds__(256, 2) pinv_bf16_kernel(
    const __nv_bfloat16* __restrict__ A, const __nv_bfloat16* __restrict__ B,
    const __nv_bfloat16* __restrict__ U,
    __nv_bfloat16* __restrict__ Cn, __nv_bfloat16* __restrict__ Ct,
    float* __restrict__ Cf, float c1, float c2)
{
    extern __shared__ __nv_bfloat16 smh[];
    const uint32_t sbase = (uint32_t)__cvta_generic_to_shared(smh);
    const uint32_t bbase = sbase + 3*HSTG*2;
    const int tid = threadIdx.x;
    const int wid = tid >> 5, lane = tid & 31;
    const int wm = wid >> 2, wn = wid & 3;
    const int gr = lane >> 2, gc = lane & 3;
    const int mtx = lane >> 3, mrow = lane & 7;
    const uint32_t a_lm = ((uint32_t)(((mtx&1)*8 + mrow)) * KPH + (uint32_t)((mtx>>1)*8)) * 2;
    const uint32_t b_lm = ((uint32_t)(((mtx>>1)*8 + mrow)) * KPH + (uint32_t)((mtx&1)*8)) * 2;

    const int tile = blockIdx.x;
    const int batch = tile >> 2;
    const int m0 = ((tile >> 1) & 1) << 7;
    const int n0 = (tile & 1) << 7;
    const size_t boff = (size_t)batch << 16;
    A += boff + (size_t)m0 * ML;
    B += boff + (size_t)n0 * ML;
    if (U)  U  += boff;
    if (Cn) Cn += boff;
    if (Ct) Ct += boff;
    if (Cf) Cf += boff;

    int crow[2], cseg[2];
    #pragma unroll
    for (int e = 0; e < 2; e++) {
        int f = e * 256 + tid;
        crow[e] = f >> 2;
        cseg[e] = (f & 3) * 8;
    }

    float acc[4][4][4];
    #pragma unroll
    for (int mi = 0; mi < 4; mi++)
        #pragma unroll
        for (int ni = 0; ni < 4; ni++)
            #pragma unroll
            for (int e = 0; e < 4; e++) acc[mi][ni][e] = 0.f;

    #pragma unroll
    for (int p = 0; p < 2; p++) {
        const int k0 = p * 32;
        #pragma unroll
        for (int e = 0; e < 2; e++) {
            cp16(sbase + (uint32_t)(p*HSTG + crow[e]*KPH + cseg[e])*2,
                 &A[(size_t)crow[e] * ML + k0 + cseg[e]]);
            cp16(bbase + (uint32_t)(p*HSTG + crow[e]*KPH + cseg[e])*2,
                 &B[(size_t)crow[e] * ML + k0 + cseg[e]]);
        }
        CP_COMMIT();
    }
    for (int c = 0; c < 8; c++) {
        const int st = c % 3;
        if (c + 1 < 8) { CP_WAIT1(); } else { CP_WAIT0(); }
        __syncthreads();
        if (c + 2 < 8) {
            const int nst = (c + 2) % 3;
            const int k0 = (c + 2) * 32;
            #pragma unroll
            for (int e = 0; e < 2; e++) {
                cp16(sbase + (uint32_t)(nst*HSTG + crow[e]*KPH + cseg[e])*2,
                     &A[(size_t)crow[e] * ML + k0 + cseg[e]]);
                cp16(bbase + (uint32_t)(nst*HSTG + crow[e]*KPH + cseg[e])*2,
                     &B[(size_t)crow[e] * ML + k0 + cseg[e]]);
            }
            CP_COMMIT();
        }
        const uint32_t a_st = sbase + (uint32_t)(st*HSTG)*2 + a_lm;
        const uint32_t b_st = bbase + (uint32_t)(st*HSTG)*2 + b_lm;
        #pragma unroll
        for (int ks = 0; ks < 2; ks++) {
            uint32_t af[4][4];
            #pragma unroll
            for (int mi = 0; mi < 4; mi++)
                ldsm_x4(af[mi][0], af[mi][1], af[mi][2], af[mi][3],
                        a_st + (uint32_t)((wm*64 + mi*16)*KPH + ks*16)*2);
            uint32_t bf[4][2];
            #pragma unroll
            for (int p = 0; p < 2; p++)
                ldsm_x4(bf[2*p][0], bf[2*p][1], bf[2*p+1][0], bf[2*p+1][1],
                        b_st + (uint32_t)((wn*32 + p*16)*KPH + ks*16)*2);
            #pragma unroll
            for (int mi = 0; mi < 4; mi++)
                #pragma unroll
                for (int ni = 0; ni < 4; ni++)
                    mma_bf16_16x8x16(acc[mi][ni],
                        af[mi][0], af[mi][1], af[mi][2], af[mi][3],
                        bf[ni][0], bf[ni][1]);
        }
    }

    #pragma unroll
    for (int mi = 0; mi < 4; mi++) {
        #pragma unroll
        for (int ni = 0; ni < 4; ni++) {
            int grow = m0 + wm*64 + mi*16 + gr;
            int gcol = n0 + wn*32 + ni*8 + gc*2;
            const float* a = acc[mi][ni];
            float d0, d1, d2, d3;
            if (U) {
                __nv_bfloat162 u0 = *reinterpret_cast<const __nv_bfloat162*>(&U[(size_t)grow * ML + gcol]);
                __nv_bfloat162 u1 = *reinterpret_cast<const __nv_bfloat162*>(&U[(size_t)(grow+8) * ML + gcol]);
                d0 = c1*__bfloat162float(u0.x) + c2*a[0];
                d1 = c1*__bfloat162float(u0.y) + c2*a[1];
                d2 = c1*__bfloat162float(u1.x) + c2*a[2];
                d3 = c1*__bfloat162float(u1.y) + c2*a[3];
            } else {
                d0 = c2*a[0]; d1 = c2*a[1]; d2 = c2*a[2]; d3 = c2*a[3];
            }
            __nv_bfloat16 h0 = __float2bfloat16(d0), h1 = __float2bfloat16(d1);
            __nv_bfloat16 h2 = __float2bfloat16(d2), h3 = __float2bfloat16(d3);
            if (Cn) {
                __nv_bfloat162 p0; p0.x = h0; p0.y = h1;
                __nv_bfloat162 p1; p1.x = h2; p1.y = h3;
                *reinterpret_cast<__nv_bfloat162*>(&Cn[(size_t)grow * ML + gcol]) = p0;
                *reinterpret_cast<__nv_bfloat162*>(&Cn[(size_t)(grow+8) * ML + gcol]) = p1;
            }
            if (Ct) {
                Ct[(size_t)gcol * ML + grow]       = h0;
                Ct[(size_t)(gcol+1) * ML + grow]   = h1;
                Ct[(size_t)gcol * ML + grow+8]     = h2;
                Ct[(size_t)(gcol+1) * ML + grow+8] = h3;
            }
            if (Cf) {
                *reinterpret_cast<float2*>(&Cf[(size_t)grow * ML + gcol]) =
                    make_float2(cvt_tf32(d0), cvt_tf32(d1));
                *reinterpret_cast<float2*>(&Cf[(size_t)(grow+8) * ML + gcol]) =
                    make_float2(cvt_tf32(d2), cvt_tf32(d3));
            }
        }
    }
}

// ============ plain batched GEMM: C[z] = A[z] @ B[z]^T (B K-major; sims) ============
__global__ void __launch_bounds__(256, 2) gemm_tc_kernel(
    const float* __restrict__ A, const float* __restrict__ B, float* __restrict__ C,
    int lda, int ldb, int ldc, int kch,
    size_t sA, size_t sB, size_t sC)
{
    extern __shared__ float sm[];
    const int tid = threadIdx.x;
    const int z = blockIdx.z;
    const int m0 = blockIdx.y * 128, n0 = blockIdx.x * 128;
    A += (size_t)z * sA + (size_t)m0 * lda;
    B += (size_t)z * sB + (size_t)n0 * ldb;
    C += (size_t)z * sC;
    float acc[4][4][4];
    #pragma unroll
    for (int mi = 0; mi < 4; mi++)
        #pragma unroll
        for (int ni = 0; ni < 4; ni++)
            #pragma unroll
            for (int e = 0; e < 4; e++) acc[mi][ni][e] = 0.f;
    mainloop128x128(A, B, lda, ldb, kch, sm, tid, acc);
    const int wid = tid >> 5, lane = tid & 31;
    const int gr = lane >> 2, gc = lane & 3;
    const int wm = wid >> 2, wn = wid & 3;
    #pragma unroll
    for (int mi = 0; mi < 4; mi++) {
        #pragma unroll
        for (int ni = 0; ni < 4; ni++) {
            int lr = m0 + wm*64 + mi*16 + gr;
            int lc = n0 + wn*32 + ni*8 + gc*2;
            const float* a = acc[mi][ni];
            *reinterpret_cast<float2*>(&C[(size_t)lr * ldc + lc]) = make_float2(a[0], a[1]);
            *reinterpret_cast<float2*>(&C[(size_t)(lr+8) * ldc + lc]) = make_float2(a[2], a[3]);
        }
    }
}

// ============ QKV GEMM with scatter epilogue (tf32-rounded outputs) ============
__global__ void __launch_bounds__(256, 2) qkv_tc_kernel(void) {
    extern __shared__ float sm[];
    const int tid = threadIdx.x;
    const int m0 = blockIdx.y * 128;
    const int n0 = blockIdx.x * 128;
    const float* A = g_xt + (size_t)m0 * CDIM;
    const float* B = g_wqkvT + (size_t)n0 * CDIM;
    float acc[4][4][4];
    #pragma unroll
    for (int mi = 0; mi < 4; mi++)
        #pragma unroll
        for (int ni = 0; ni < 4; ni++)
            #pragma unroll
            for (int e = 0; e < 4; e++) acc[mi][ni][e] = 0.f;
    mainloop128x128(A, B, CDIM, CDIM, CDIM/32, sm, tid, acc);
    const int wid = tid >> 5, lane = tid & 31;
    const int gr = lane >> 2, gc = lane & 3;
    const int wm = wid >> 2, wn = wid & 3;
    #pragma unroll
    for (int mi = 0; mi < 4; mi++) {
        int m = m0 + wm*64 + mi*16 + gr;
        int b = m >> 10, i = m & 1023;
        #pragma unroll
        for (int ni = 0; ni < 4; ni++) {
            int n = n0 + wn*32 + ni*8 + gc*2;
            int which = n >> 9;
            int h = (n >> 6) & 7;
            int d = n & 63;
            int bh = b*8 + h;
            float* dst = (which == 0) ? g_q : ((which == 1) ? g_k : g_v);
            float sc = (which == 0) ? 0.125f : 1.0f;
            const float* a = acc[mi][ni];
            float r0 = cvt_tf32(a[0]*sc), r1 = cvt_tf32(a[1]*sc);
            float r2 = cvt_tf32(a[2]*sc), r3 = cvt_tf32(a[3]*sc);
            *reinterpret_cast<float2*>(&dst[((size_t)(bh*NTOK + i))*DH + d]) = make_float2(r0, r1);
            *reinterpret_cast<float2*>(&dst[((size_t)(bh*NTOK + i + 8))*DH + d]) = make_float2(r2, r3);
        }
    }
}

// ============ final GEMM: out = outf @ woutT^T + bias, transposed store (fp32) ============
__global__ void __launch_bounds__(256, 2) final_tc_kernel(
    const float* __restrict__ bias, float* __restrict__ out)
{
    extern __shared__ float sm[];
    const int tid = threadIdx.x;
    const int m0 = blockIdx.y * 128;
    const int n0 = blockIdx.x * 128;
    const float* A = g_outf + (size_t)m0 * CDIM;
    const float* B = g_woutT + (size_t)n0 * CDIM;
    float acc[4][4][4];
    #pragma unroll
    for (int mi = 0; mi < 4; mi++)
        #pragma unroll
        for (int ni = 0; ni < 4; ni++)
            #pragma unroll
            for (int e = 0; e < 4; e++) acc[mi][ni][e] = 0.f;
    mainloop128x128(A, B, CDIM, CDIM, CDIM/32, sm, tid, acc);
    const int wid = tid >> 5, lane = tid & 31;
    const int gr = lane >> 2, gc = lane & 3;
    const int wm = wid >> 2, wn = wid & 3;
    #pragma unroll
    for (int mi = 0; mi < 4; mi++) {
        int m = m0 + wm*64 + mi*16 + gr;
        int b = m >> 10, i = m & 1023;
        #pragma unroll
        for (int ni = 0; ni < 4; ni++) {
            int n = n0 + wn*32 + ni*8 + gc*2;
            const float* a = acc[mi][ni];
            float b0 = bias[n], b1 = bias[n+1];
            out[((size_t)(b*CDIM + n))*NTOK + i]       = a[0] + b0;
            out[((size_t)(b*CDIM + n + 1))*NTOK + i]   = a[1] + b1;
            out[((size_t)(b*CDIM + n))*NTOK + i + 8]   = a[2] + b0;
            out[((size_t)(b*CDIM + n + 1))*NTOK + i + 8] = a[3] + b1;
        }
    }
}

// ============ 128x64 batched GEMM, B row-major [K,64]: C = A @ B ============
__global__ void __launch_bounds__(256, 2) gemm64_rowB_kernel(
    const float* __restrict__ A, const float* __restrict__ B, float* __restrict__ C,
    int lda, int kch, size_t sA, size_t sB, int flatC)
{
    extern __shared__ float sm[];
    const uint32_t sbase = (uint32_t)__cvta_generic_to_shared(sm);
    const uint32_t bbase = sbase + 3*PSTAGE*4;
    const int tid = threadIdx.x;
    const int wid = tid >> 5, lane = tid & 31;
    const int gr = lane >> 2, gc = lane & 3;
    const int wm = wid >> 1, wn = wid & 1;
    const int g = lane >> 3, r8 = lane & 7;
    const uint32_t a_lm = (uint32_t)((wm*32 + (g&1)*8 + r8)*PPITCH + (g>>1)*4)*4;
    const int z = blockIdx.z;
    const int m0 = blockIdx.x * 128;
    A += (size_t)z * sA + (size_t)m0 * lda;
    B += (size_t)z * sB;
    if (flatC) C += (size_t)(z >> 3) * (NTOK*CDIM) + (size_t)(z & 7) * DH;
    else       C += (size_t)z * (ML*DH);

    int arow[4], ac4[4], bk[2], bn4[2];
    #pragma unroll
    for (int e = 0; e < 4; e++) {
        int f4 = e * 256 + tid;
        arow[e] = f4 >> 3;  ac4[e] = (f4 & 7) << 2;
    }
    #pragma unroll
    for (int e = 0; e < 2; e++) {
        int f4 = e * 256 + tid;
        bk[e] = f4 >> 4;  bn4[e] = (f4 & 15) << 2;
    }

    float acc[2][4][4];
    #pragma unroll
    for (int mi = 0; mi < 2; mi++)
        #pragma unroll
        for (int ni = 0; ni < 4; ni++)
            #pragma unroll
            for (int e = 0; e < 4; e++) acc[mi][ni][e] = 0.f;

    #pragma unroll
    for (int p = 0; p < 2; p++) {
        if (p < kch) {
            const int k0 = p * 32;
            #pragma unroll
            for (int e = 0; e < 4; e++)
                cp16(sbase + (uint32_t)(p*PSTAGE + arow[e]*PPITCH + ac4[e])*4,
                     &A[(size_t)arow[e] * lda + k0 + ac4[e]]);
            #pragma unroll
            for (int e = 0; e < 2; e++)
                cp16(bbase + (uint32_t)(p*BRSTG64 + bk[e]*BNP64 + bn4[e])*4,
                     &B[(size_t)(k0 + bk[e]) * DH + bn4[e]]);
        }
        CP_COMMIT();
    }

    for (int c = 0; c < kch; c++) {
        const int st = c % 3;
        if (c + 1 < kch) { CP_WAIT1(); } else { CP_WAIT0(); }
        __syncthreads();
        if (c + 2 < kch) {
            const int nst = (c + 2) % 3;
            const int k0 = (c + 2) * 32;
            #pragma unroll
            for (int e = 0; e < 4; e++)
                cp16(sbase + (uint32_t)(nst*PSTAGE + arow[e]*PPITCH + ac4[e])*4,
                     &A[(size_t)arow[e] * lda + k0 + ac4[e]]);
            #pragma unroll
            for (int e = 0; e < 2; e++)
                cp16(bbase + (uint32_t)(nst*BRSTG64 + bk[e]*BNP64 + bn4[e])*4,
                     &B[(size_t)(k0 + bk[e]) * DH + bn4[e]]);
            CP_COMMIT();
        }
        const uint32_t a_st = sbase + (uint32_t)(st*PSTAGE)*4 + a_lm;
        const float* Bb = sm + 3*PSTAGE + st*BRSTG64;
        #pragma unroll
        for (int ks = 0; ks < 4; ks++) {
            uint32_t af[2][4];
            #pragma unroll
            for (int mi = 0; mi < 2; mi++)
                ldsm_x4(af[mi][0], af[mi][1], af[mi][2], af[mi][3],
                        a_st + (uint32_t)(mi*16*PPITCH + ks*8)*4);
            uint32_t bf[4][2];
            #pragma unroll
            for (int ni = 0; ni < 4; ni++) {
                int n = wn*32 + ni*8 + gr;
                bf[ni][0] = __float_as_uint(Bb[(ks*8 + gc)*BNP64 + n]);
                bf[ni][1] = __float_as_uint(Bb[(ks*8 + gc + 4)*BNP64 + n]);
            }
            #pragma unroll
            for (int mi = 0; mi < 2; mi++)
                #pragma unroll
                for (int ni = 0; ni < 4; ni++)
                    mma_tf32_16x8x8(acc[mi][ni],
                        af[mi][0], af[mi][1], af[mi][2], af[mi][3],
                        bf[ni][0], bf[ni][1]);
        }
    }

    #pragma unroll
    for (int mi = 0; mi < 2; mi++) {
        #pragma unroll
        for (int ni = 0; ni < 4; ni++) {
            int lr = m0 + wm*32 + mi*16 + gr;
            int lc = wn*32 + ni*8 + gc*2;
            const float* a = acc[mi][ni];
            float d0 = cvt_tf32(a[0]), d1 = cvt_tf32(a[1]);
            float d2 = cvt_tf32(a[2]), d3 = cvt_tf32(a[3]);
            int ldc = flatC ? CDIM : DH;
            *reinterpret_cast<float2*>(&C[(size_t)lr * ldc + lc]) = make_float2(d0, d1);
            *reinterpret_cast<float2*>(&C[(size_t)(lr+8) * ldc + lc]) = make_float2(d2, d3);
        }
    }
}

// ---------------- batched 2D transpose (tf32-rounded output) ----------------
__global__ void transpose_kernel(const float* __restrict__ in, float* __restrict__ out,
                                 int R, int C) {
    __shared__ float tile[32][33];
    const int z = blockIdx.z;
    in  += (size_t)z * R * C;
    out += (size_t)z * R * C;
    int c0 = blockIdx.x * 32, r0 = blockIdx.y * 32;
    int tx = threadIdx.x, ty = threadIdx.y;
    #pragma unroll
    for (int j = 0; j < 4; j++)
        tile[ty + j*8][tx] = in[(size_t)(r0 + ty + j*8) * C + c0 + tx];
    __syncthreads();
    #pragma unroll
    for (int j = 0; j < 4; j++)
        out[(size_t)(c0 + ty + j*8) * R + r0 + tx] = cvt_tf32(tile[tx][ty + j*8]);
}

// ======= tf32 pinv batched GEMM: D = c1*U + c2*(P @ B), B row-major ========
// Outputs (each optional): Cn fp32 tf32-rounded row-major; Chn bf16 row-major;
// ChT bf16 transposed (K-major for downstream B operands).
__global__ void __launch_bounds__(256, 2) pinv_mma_kernel(
    const float* __restrict__ P, const float* __restrict__ B,
    const float* __restrict__ U, float* __restrict__ Cn,
    __nv_bfloat16* __restrict__ Chn, __nv_bfloat16* __restrict__ ChT,
    float c1, float c2)
{
    extern __shared__ float sm[];
    const int tid = threadIdx.x;
    const int wid = tid >> 5, lane = tid & 31;
    const int wm = wid >> 2, wn = wid & 3;
    const int gr = lane >> 2, gc = lane & 3;
    const int tile = blockIdx.x;
    const int batch = tile >> 2;
    const int m0 = ((tile >> 1) & 1) << 7;
    const int n0 = (tile & 1) << 7;
    const size_t boff = (size_t)batch << 16;
    P += boff + (size_t)m0 * ML;
    B += boff + n0;
    if (U) U += boff;
    if (Cn) Cn += boff;
    if (Chn) Chn += boff;
    if (ChT) ChT += boff;

    float acc[4][4][4];
    #pragma unroll
    for (int mi = 0; mi < 4; mi++)
        #pragma unroll
        for (int ni = 0; ni < 4; ni++)
            #pragma unroll
            for (int e = 0; e < 4; e++) acc[mi][ni][e] = 0.f;
    mainloop128x128_rowB(P, B, ML, ML, 8, sm, tid, acc);

    #pragma unroll
    for (int mi = 0; mi < 4; mi++) {
        #pragma unroll
        for (int ni = 0; ni < 4; ni++) {
            int lr = wm*64 + mi*16 + gr;
            int lc = wn*32 + ni*8 + gc*2;
            int grow = m0 + lr, gcol = n0 + lc;
            const float* a = acc[mi][ni];
            float d0, d1, d2, d3;
            if (U) {
                float2 u0 = *reinterpret_cast<const float2*>(&U[(size_t)grow * ML + gcol]);
                float2 u1 = *reinterpret_cast<const float2*>(&U[(size_t)(grow+8) * ML + gcol]);
                d0 = c1*u0.x + c2*a[0]; d1 = c1*u0.y + c2*a[1];
                d2 = c1*u1.x + c2*a[2]; d3 = c1*u1.y + c2*a[3];
            } else {
                d0 = c2*a[0]; d1 = c2*a[1]; d2 = c2*a[2]; d3 = c2*a[3];
            }
            if (Cn) {
                *reinterpret_cast<float2*>(&Cn[(size_t)grow * ML + gcol]) =
                    make_float2(cvt_tf32(d0), cvt_tf32(d1));
                *reinterpret_cast<float2*>(&Cn[(size_t)(grow+8) * ML + gcol]) =
                    make_float2(cvt_tf32(d2), cvt_tf32(d3));
            }
            if (Chn || ChT) {
                __nv_bfloat16 h0 = __float2bfloat16(d0), h1 = __float2bfloat16(d1);
                __nv_bfloat16 h2 = __float2bfloat16(d2), h3 = __float2bfloat16(d3);
                if (Chn) {
                    __nv_bfloat162 p0; p0.x = h0; p0.y = h1;
                    __nv_bfloat162 p1; p1.x = h2; p1.y = h3;
                    *reinterpret_cast<__nv_bfloat162*>(&Chn[(size_t)grow * ML + gcol]) = p0;
                    *reinterpret_cast<__nv_bfloat162*>(&Chn[(size_t)(grow+8) * ML + gcol]) = p1;
                }
                if (ChT) {
                    ChT[(size_t)gcol * ML + grow]       = h0;
                    ChT[(size_t)(gcol+1) * ML + grow]   = h1;
                    ChT[(size_t)gcol * ML + grow+8]     = h2;
                    ChT[(size_t)(gcol+1) * ML + grow+8] = h3;
                }
            }
        }
    }
}

// ---------------- landmark means (tf32-rounded) ----------------
__global__ void land_kernel() {
    int idx = blockIdx.x * blockDim.x + threadIdx.x;
    if (idx >= BHN*ML*DH) return;
    int d  = idx & 63;
    int j  = (idx >> 6) & 255;
    int bh = idx >> 14;
    size_t base = ((size_t)bh * NTOK + j*4) * DH + d;
    g_ql[idx] = cvt_tf32(0.25f * (g_q[base] + g_q[base+64] + g_q[base+128] + g_q[base+192]));
    g_kl[idx] = cvt_tf32(0.25f * (g_k[base] + g_k[base+64] + g_k[base+128] + g_k[base+192]));
}

// ---------------- warp-per-row softmax: fast exp, zero block barriers ----------------
template<int W>
__global__ void softmax_warp_kernel(float* __restrict__ data) {
    const int lane = threadIdx.x & 31;
    const int row = blockIdx.x * 8 + (threadIdx.x >> 5);
    float* r = data + (size_t)row * W;
    constexpr int PE = W / 32;
    float v[PE];
    float mx = -1e30f;
    #pragma unroll
    for (int e = 0; e < PE; e++) { v[e] = r[lane + e*32]; mx = fmaxf(mx, v[e]); }
    #pragma unroll
    for (int o = 16; o > 0; o >>= 1) mx = fmaxf(mx, __shfl_xor_sync(0xffffffffu, mx, o));
    float s = 0.f;
    #pragma unroll
    for (int e = 0; e < PE; e++) { v[e] = __expf(v[e] - mx); s += v[e]; }
    #pragma unroll
    for (int o = 16; o > 0; o >>= 1) s += __shfl_xor_sync(0xffffffffu, s, o);
    float inv = 1.0f / s;
    #pragma unroll
    for (int e = 0; e < PE; e++) r[lane + e*32] = cvt_tf32(v[e] * inv);
}

// ---------------- pinv scale reductions ----------------
__global__ void reset_max_kernel() { if (threadIdx.x == 0) { g_colmax = 0u; g_rowmax = 0u; } }

__global__ void colmax_kernel() {
    int gw = (blockIdx.x * blockDim.x + threadIdx.x) >> 5;
    int lane = threadIdx.x & 31;
    if (gw >= BHN * ML) return;
    const float* row = g_attn2 + (size_t)gw * ML;
    float s = 0.f;
    #pragma unroll
    for (int j = lane; j < ML; j += 32) s += fabsf(row[j]);
    #pragma unroll
    for (int o = 16; o > 0; o >>= 1) s += __shfl_down_sync(0xffffffffu, s, o);
    if (lane == 0) atomicMax(&g_colmax, __float_as_uint(s));
}

__global__ void rowmax_kernel() {
    int idx = blockIdx.x * blockDim.x + threadIdx.x;
    if (idx >= BHN * ML) return;
    int bh = idx >> 8, j = idx & 255;
    const float* base = g_attn2 + (size_t)bh * ML * ML + j;
    float s = 0.f;
    for (int i = 0; i < ML; i++) s += fabsf(base[(size_t)i * ML]);
    atomicMax(&g_rowmax, __float_as_uint(s));
}

// zinit: z0 (bf16, row + transposed) and a2h (bf16 of a2)
__global__ void zinit_kernel() {
    float inv = 1.0f / (__uint_as_float(g_colmax) * __uint_as_float(g_rowmax));
    size_t idx = (size_t)blockIdx.x * 256 + threadIdx.x;
    int j  = idx & 255;
    int i  = (idx >> 8) & 255;
    size_t bh = idx >> 16;
    float a2v  = g_attn2[idx];
    float a2tv = g_attn2[(bh << 16) + ((size_t)j << 8) + i];
    g_zhA[idx]  = __float2bfloat16(a2tv * inv);   // z0 row-major = scaled x^T
    g_zhTA[idx] = __float2bfloat16(a2v * inv);    // z0^T = scaled x
    g_a2h[idx]  = __float2bfloat16(a2v);
}

// ---------------- depthwise 33-tap conv residual (tf32-rounded add) ----------------
__global__ void res_add_kernel(const float* __restrict__ rk) {
    __shared__ float ker[KSZ];
    int blk = blockIdx.x;
    int bh = blk >> 8;
    int ichunk = blk & 255;
    int h = bh & 7, b = bh >> 3;
    if (threadIdx.x < KSZ) ker[threadIdx.x] = rk[h*KSZ + threadIdx.x];
    __syncthreads();
    int d = threadIdx.x & 63;
    int i = ichunk * 4 + (threadIdx.x >> 6);
    const float* vb = g_v + (size_t)bh * NTOK * DH;
    float s = 0.f;
    #pragma unroll
    for (int t = 0; t < KSZ; t++) {
        int ii = i + t - (KSZ/2);
        if (ii >= 0 && ii < NTOK) s += ker[t] * vb[(size_t)ii * DH + d];
    }
    size_t o = ((size_t)(b*NTOK + i)) * CDIM + h*64 + d;
    g_outf[o] = cvt_tf32(g_outf[o] + s);
}

// ---------------- host ----------------
extern "C" void kernel_launch(void* const* d_in, const int* in_sizes, int n_in,
                              void* d_out, int out_size) {
    const float* x     = (const float*)d_in[0];
    const float* w_qkv = (const float*)d_in[1];
    const float* w_out = (const float*)d_in[2];
    const float* b_out = (const float*)d_in[3];
    const float* rk    = (const float*)d_in[4];
    float* out = (float*)d_out;

    float *xt, *wqkvT, *woutT, *q, *k, *v, *ql, *kl, *a1, *a3, *a2;
    float *zA, *zB, *t2, *av, *bv, *outf;
    __nv_bfloat16 *a2h, *zhA, *zhB, *zhTA, *zhTB, *xzh, *xzhT, *t1hT, *t2hT;
    cudaGetSymbolAddress((void**)&xt, g_xt);
    cudaGetSymbolAddress((void**)&wqkvT, g_wqkvT);
    cudaGetSymbolAddress((void**)&woutT, g_woutT);
    cudaGetSymbolAddress((void**)&q,  g_q);
    cudaGetSymbolAddress((void**)&k,  g_k);
    cudaGetSymbolAddress((void**)&v,  g_v);
    cudaGetSymbolAddress((void**)&ql, g_ql);
    cudaGetSymbolAddress((void**)&kl, g_kl);
    cudaGetSymbolAddress((void**)&a1, g_attn1);
    cudaGetSymbolAddress((void**)&a3, g_attn3);
    cudaGetSymbolAddress((void**)&a2, g_attn2);
    cudaGetSymbolAddress((void**)&zA, g_zA);
    cudaGetSymbolAddress((void**)&zB, g_zB);
    cudaGetSymbolAddress((void**)&t2, g_t2);
    cudaGetSymbolAddress((void**)&av, g_av);
    cudaGetSymbolAddress((void**)&bv, g_bv);
    cudaGetSymbolAddress((void**)&outf, g_outf);
    cudaGetSymbolAddress((void**)&a2h,  g_a2h);
    cudaGetSymbolAddress((void**)&zhA,  g_zhA);
    cudaGetSymbolAddress((void**)&zhB,  g_zhB);
    cudaGetSymbolAddress((void**)&zhTA, g_zhTA);
    cudaGetSymbolAddress((void**)&zhTB, g_zhTB);
    cudaGetSymbolAddress((void**)&xzh,  g_xzh);
    cudaGetSymbolAddress((void**)&xzhT, g_xzhT);
    cudaGetSymbolAddress((void**)&t1hT, g_t1hT);
    cudaGetSymbolAddress((void**)&t2hT, g_t2hT);

    cudaFuncSetAttribute(pinv_mma_kernel,    cudaFuncAttributeMaxDynamicSharedMemorySize, PB_SMEM3);
    cudaFuncSetAttribute(pinv_bf16_kernel,   cudaFuncAttributeMaxDynamicSharedMemorySize, BH_SMEM3);
    cudaFuncSetAttribute(gemm_tc_kernel,     cudaFuncAttributeMaxDynamicSharedMemorySize, G128_SMEM3);
    cudaFuncSetAttribute(qkv_tc_kernel,      cudaFuncAttributeMaxDynamicSharedMemorySize, G128_SMEM3);
    cudaFuncSetAttribute(final_tc_kernel,    cudaFuncAttributeMaxDynamicSharedMemorySize, G128_SMEM3);
    cudaFuncSetAttribute(gemm64_rowB_kernel, cudaFuncAttributeMaxDynamicSharedMemorySize, G64R_SMEM3);

    // 0) layout prep
    transpose_kernel<<<dim3(NTOK/32, CDIM/32, BATCH), dim3(32,8)>>>(x, xt, CDIM, NTOK);
    transpose_kernel<<<dim3(48, 16, 1), dim3(32,8)>>>(w_qkv, wqkvT, CDIM, 3*CDIM);
    transpose_kernel<<<dim3(16, 16, 1), dim3(32,8)>>>(w_out, woutT, CDIM, CDIM);
    // 1) QKV projection
    qkv_tc_kernel<<<dim3(12, 256), 256, G128_SMEM3>>>();
    // 2) landmarks
    land_kernel<<<(BHN*ML*DH + 255)/256, 256>>>();
    // 3) similarity GEMMs
    gemm_tc_kernel<<<dim3(2, 8, BHN), 256, G128_SMEM3>>>(q,  kl, a1, DH, DH, ML,   2,
        (size_t)NTOK*DH, (size_t)ML*DH, (size_t)NTOK*ML);
    gemm_tc_kernel<<<dim3(2, 2, BHN), 256, G128_SMEM3>>>(ql, kl, a2, DH, DH, ML,   2,
        (size_t)ML*DH,   (size_t)ML*DH, (size_t)ML*ML);
    gemm_tc_kernel<<<dim3(8, 2, BHN), 256, G128_SMEM3>>>(ql, k,  a3, DH, DH, NTOK, 2,
        (size_t)ML*DH,   (size_t)NTOK*DH, (size_t)ML*NTOK);
    // 4) softmaxes — warp-per-row, fast exp
    softmax_warp_kernel<256> <<<BHN*NTOK/8, 256>>>(a1);
    softmax_warp_kernel<256> <<<BHN*ML/8,   256>>>(a2);
    softmax_warp_kernel<1024><<<BHN*ML/8,   256>>>(a3);
    // 5) pinv init (bf16 z0 / z0^T / a2h)
    reset_max_kernel<<<1, 32>>>();
    colmax_kernel<<<(BHN*ML*32)/256, 256>>>();
    rowmax_kernel<<<(BHN*ML)/256, 256>>>();
    zinit_kernel<<<(BHN*ML*ML)/256, 256>>>();
    // 6) Newton–Schulz: iterations 1–5 in bf16, iteration 6 hybrid:
    //    xz on tf32 A-side (fp32 z) -> bf16 dual store; t1/t2 in bf16 (correction
    //    terms only; error enters z' scaled by 0.25 with K=256 averaging); final
    //    z-update in tf32 with fp32 operands.
    __nv_bfloat16 *zh_in = zhA, *zh_out = zhB, *zhT_in = zhTA, *zhT_out = zhTB;
    for (int it = 0; it < 5; it++) {
        pinv_bf16_kernel<<<1024, 256, BH_SMEM3>>>(a2h, zhT_in, nullptr, xzh, xzhT, nullptr, 0.0f, 1.0f);
        pinv_bf16_kernel<<<1024, 256, BH_SMEM3>>>(xzh, xzhT, xzh, nullptr, t1hT, nullptr, 7.0f, -1.0f);
        pinv_bf16_kernel<<<1024, 256, BH_SMEM3>>>(xzh, t1hT, xzh, nullptr, t2hT, nullptr, 15.0f, -1.0f);
        if (it < 4) {
            pinv_bf16_kernel<<<1024, 256, BH_SMEM3>>>(zh_in, t2hT, zh_in, zh_out, zhT_out, nullptr, 3.25f, -0.25f);
            __nv_bfloat16* tmp;
            tmp = zh_in;  zh_in  = zh_out;  zh_out  = tmp;
            tmp = zhT_in; zhT_in = zhT_out; zhT_out = tmp;
        } else {
            pinv_bf16_kernel<<<1024, 256, BH_SMEM3>>>(zh_in, t2hT, zh_in, nullptr, nullptr, zA, 3.25f, -0.25f);
        }
    }
    // iteration 6 (hybrid precision)
    pinv_mma_kernel<<<1024, 256, PB_SMEM3>>>(a2, zA, nullptr, nullptr, xzh, xzhT, 0.0f, 1.0f);
    pinv_bf16_kernel<<<1024, 256, BH_SMEM3>>>(xzh, xzhT, xzh, nullptr, t1hT, nullptr, 7.0f, -1.0f);
    pinv_bf16_kernel<<<1024, 256, BH_SMEM3>>>(xzh, t1hT, xzh, nullptr, nullptr, t2, 15.0f, -1.0f);
    pinv_mma_kernel<<<1024, 256, PB_SMEM3>>>(zA, t2, zA, zB, nullptr, nullptr, 3.25f, -0.25f);
    float* zfin = zB;
    // 7) output chain: av = attn3@v ; bv = z@av ; outf = attn1@bv
    gemm64_rowB_kernel<<<dim3(2, 1, BHN), 256, G64R_SMEM3>>>(a3, v, av,
        NTOK, 32, (size_t)ML*NTOK, (size_t)NTOK*DH, 0);
    gemm64_rowB_kernel<<<dim3(2, 1, BHN), 256, G64R_SMEM3>>>(zfin, av, bv,
        ML, 8, (size_t)ML*ML, (size_t)ML*DH, 0);
    gemm64_rowB_kernel<<<dim3(8, 1, BHN), 256, G64R_SMEM3>>>(a1, bv, outf,
        ML, 8, (size_t)NTOK*ML, (size_t)ML*DH, 1);
    // 8) depthwise conv residual (standalone — epilogue fusion regressed in R13)
    res_add_kernel<<<BHN*256, 256>>>(rk);
    // 9) output projection + bias + transposed store
    final_tc_kernel<<<dim3(4, 256), 256, G128_SMEM3>>>(b_out, out);
}

// round 15
// speedup vs baseline: 1.0603x; 1.0212x over previous
#include <cuda_runtime.h>
#include <cuda_bf16.h>
#include <cstdint>
#include <cstddef>

#define BATCH 32
#define HEADS 8
#define NTOK 1024
#define DH 64
#define ML 256          // landmarks
#define CDIM 512
#define BHN (BATCH*HEADS)   // 256
#define KSZ 33

// ---------------- device scratch ----------------
__device__ float g_wqkvT[3*CDIM*CDIM];              // (1536, 512), tf32-rounded
__device__ float g_woutT[CDIM*CDIM];                // (512, 512), tf32-rounded
__device__ float g_q [BHN*NTOK*DH];
__device__ float g_k [BHN*NTOK*DH];
__device__ float g_v [BHN*NTOK*DH];
__device__ float g_ql[BHN*ML*DH];
__device__ float g_kl[BHN*ML*DH];
__device__ float g_attn1[(size_t)BHN*NTOK*ML];      // (bh,1024,256)
__device__ float g_attn3[(size_t)BHN*ML*NTOK];      // (bh,256,1024)
__device__ float g_attn2[BHN*ML*ML];
__device__ float g_zA[BHN*ML*ML];                   // final z (fp32)
__device__ float g_av[BHN*ML*DH];
__device__ float g_bv[BHN*ML*DH];
__device__ float g_outf[(size_t)BATCH*NTOK*CDIM];   // (b, n, 512)
__device__ unsigned g_colmax;
__device__ unsigned g_rowmax;
// bf16 pinv buffers
__device__ __nv_bfloat16 g_a2h [BHN*ML*ML];   // bf16(a2), row-major [M][K]
__device__ __nv_bfloat16 g_zhA [BHN*ML*ML];   // z row-major
__device__ __nv_bfloat16 g_zhB [BHN*ML*ML];
__device__ __nv_bfloat16 g_zhTA[BHN*ML*ML];   // z^T (K-major for B operand)
__device__ __nv_bfloat16 g_zhTB[BHN*ML*ML];
__device__ __nv_bfloat16 g_xzh [BHN*ML*ML];
__device__ __nv_bfloat16 g_xzhT[BHN*ML*ML];
__device__ __nv_bfloat16 g_t1hT[BHN*ML*ML];
__device__ __nv_bfloat16 g_t2hT[BHN*ML*ML];

// ================= helpers =================
__device__ __forceinline__ float cvt_tf32(float x) {
    uint32_t u;
    asm("cvt.rna.tf32.f32 %0, %1;" : "=r"(u) : "f"(x));
    return __uint_as_float(u);
}
__device__ __forceinline__ void mma_tf32_16x8x8(float c[4],
    uint32_t a0, uint32_t a1, uint32_t a2, uint32_t a3, uint32_t b0, uint32_t b1) {
    asm volatile(
        "mma.sync.aligned.m16n8k8.row.col.f32.tf32.tf32.f32 "
        "{%0,%1,%2,%3},{%4,%5,%6,%7},{%8,%9},{%0,%1,%2,%3};"
        : "+f"(c[0]), "+f"(c[1]), "+f"(c[2]), "+f"(c[3])
        : "r"(a0), "r"(a1), "r"(a2), "r"(a3), "r"(b0), "r"(b1));
}
__device__ __forceinline__ void mma_bf16_16x8x16(float c[4],
    uint32_t a0, uint32_t a1, uint32_t a2, uint32_t a3, uint32_t b0, uint32_t b1) {
    asm volatile(
        "mma.sync.aligned.m16n8k16.row.col.f32.bf16.bf16.f32 "
        "{%0,%1,%2,%3},{%4,%5,%6,%7},{%8,%9},{%0,%1,%2,%3};"
        : "+f"(c[0]), "+f"(c[1]), "+f"(c[2]), "+f"(c[3])
        : "r"(a0), "r"(a1), "r"(a2), "r"(a3), "r"(b0), "r"(b1));
}
__device__ __forceinline__ void ldsm_x4(uint32_t& r0, uint32_t& r1,
                                        uint32_t& r2, uint32_t& r3, uint32_t saddr) {
    asm volatile("ldmatrix.sync.aligned.m8n8.x4.shared.b16 {%0,%1,%2,%3}, [%4];"
                 : "=r"(r0), "=r"(r1), "=r"(r2), "=r"(r3) : "r"(saddr));
}
__device__ __forceinline__ void cp16(uint32_t dst, const void* src) {
    asm volatile("cp.async.cg.shared.global [%0], [%1], 16;" :: "r"(dst), "l"(src));
}
#define CP_COMMIT() asm volatile("cp.async.commit_group;")
#define CP_WAIT1()  asm volatile("cp.async.wait_group 1;" ::: "memory")
#define CP_WAIT0()  asm volatile("cp.async.wait_group 0;" ::: "memory")

#define PPITCH 36
#define PSTAGE (128*PPITCH)
#define G128_SMEM3 (6*PSTAGE*4)                     // 110592 (A,B both K-major fp32)

#define BNP128 136
#define BRSTG128 (32*BNP128)
#define PB_SMEM3 ((3*PSTAGE + 3*BRSTG128)*4)        // 107520

#define BNP64 72
#define BRSTG64 (32*BNP64)
#define G64R_SMEM3 ((3*PSTAGE + 3*BRSTG64)*4)       // 82944

// bf16 tiles: [128 rows][KPH halves] per chunk (32 halves data, pitch 40)
#define KPH 40
#define HSTG (128*KPH)                               // halves per stage
#define BH_SMEM3 (6*HSTG*2)                          // 61440 bytes

// ============ mainloop A: B stored K-major ([N rows][K]) — sims/final ============
__device__ __forceinline__ void mainloop128x128(
    const float* __restrict__ A, const float* __restrict__ B,
    int lda, int ldb, int kch, float* sm, int tid, float acc[4][4][4])
{
    const uint32_t sbase = (uint32_t)__cvta_generic_to_shared(sm);
    const uint32_t bbase = sbase + 3*PSTAGE*4;
    const int wid = tid >> 5, lane = tid & 31;
    const int wm = wid >> 2, wn = wid & 3;
    const int g = lane >> 3, r8 = lane & 7;
    const uint32_t a_lm = (uint32_t)((wm*64 + (g&1)*8 + r8)*PPITCH + (g>>1)*4)*4;
    const uint32_t b_lm = (uint32_t)((wn*32 + (g>>1)*8 + r8)*PPITCH + (g&1)*4)*4;
    int rrow[4], rc4[4];
    #pragma unroll
    for (int e = 0; e < 4; e++) {
        int f4 = e * 256 + tid;
        rrow[e] = f4 >> 3;
        rc4[e] = (f4 & 7) << 2;
    }
    #pragma unroll
    for (int p = 0; p < 2; p++) {
        if (p < kch) {
            const int k0 = p * 32;
            #pragma unroll
            for (int e = 0; e < 4; e++) {
                cp16(sbase + (uint32_t)(p*PSTAGE + rrow[e]*PPITCH + rc4[e])*4,
                     &A[(size_t)rrow[e] * lda + k0 + rc4[e]]);
                cp16(bbase + (uint32_t)(p*PSTAGE + rrow[e]*PPITCH + rc4[e])*4,
                     &B[(size_t)rrow[e] * ldb + k0 + rc4[e]]);
            }
        }
        CP_COMMIT();
    }
    for (int c = 0; c < kch; c++) {
        const int st = c % 3;
        if (c + 1 < kch) { CP_WAIT1(); } else { CP_WAIT0(); }
        __syncthreads();
        if (c + 2 < kch) {
            const int nst = (c + 2) % 3;
            const int k0 = (c + 2) * 32;
            #pragma unroll
            for (int e = 0; e < 4; e++) {
                cp16(sbase + (uint32_t)(nst*PSTAGE + rrow[e]*PPITCH + rc4[e])*4,
                     &A[(size_t)rrow[e] * lda + k0 + rc4[e]]);
                cp16(bbase + (uint32_t)(nst*PSTAGE + rrow[e]*PPITCH + rc4[e])*4,
                     &B[(size_t)rrow[e] * ldb + k0 + rc4[e]]);
            }
            CP_COMMIT();
        }
        const uint32_t a_st = sbase + (uint32_t)(st*PSTAGE)*4 + a_lm;
        const uint32_t b_st = bbase + (uint32_t)(st*PSTAGE)*4 + b_lm;
        #pragma unroll
        for (int ks = 0; ks < 4; ks++) {
            uint32_t af[4][4];
            #pragma unroll
            for (int mi = 0; mi < 4; mi++)
                ldsm_x4(af[mi][0], af[mi][1], af[mi][2], af[mi][3],
                        a_st + (uint32_t)(mi*16*PPITCH + ks*8)*4);
            uint32_t bf[4][2];
            #pragma unroll
            for (int p = 0; p < 2; p++)
                ldsm_x4(bf[2*p][0], bf[2*p][1], bf[2*p+1][0], bf[2*p+1][1],
                        b_st + (uint32_t)(p*16*PPITCH + ks*8)*4);
            #pragma unroll
            for (int mi = 0; mi < 4; mi++)
                #pragma unroll
                for (int ni = 0; ni < 4; ni++)
                    mma_tf32_16x8x8(acc[mi][ni],
                        af[mi][0], af[mi][1], af[mi][2], af[mi][3],
                        bf[ni][0], bf[ni][1]);
        }
    }
}

// ============ mainloop B: B stored row-major [K][N] — qkvT ============
__device__ __forceinline__ void mainloop128x128_rowB(
    const float* __restrict__ A, const float* __restrict__ B,
    int lda, int ldb, int kch, float* sm, int tid, float acc[4][4][4])
{
    const uint32_t sbase = (uint32_t)__cvta_generic_to_shared(sm);
    const uint32_t bbase = sbase + 3*PSTAGE*4;
    const int wid = tid >> 5, lane = tid & 31;
    const int gr = lane >> 2, gc = lane & 3;
    const int wm = wid >> 2, wn = wid & 3;
    const int g = lane >> 3, r8 = lane & 7;
    const uint32_t a_lm = (uint32_t)((wm*64 + (g&1)*8 + r8)*PPITCH + (g>>1)*4)*4;
    int arow[4], ac4[4], bk[4], bn4[4];
    #pragma unroll
    for (int e = 0; e < 4; e++) {
        int f4 = e * 256 + tid;
        arow[e] = f4 >> 3;  ac4[e] = (f4 & 7) << 2;
        bk[e]   = f4 >> 5;  bn4[e] = (f4 & 31) << 2;
    }
    #pragma unroll
    for (int p = 0; p < 2; p++) {
        if (p < kch) {
            const int k0 = p * 32;
            #pragma unroll
            for (int e = 0; e < 4; e++) {
                cp16(sbase + (uint32_t)(p*PSTAGE + arow[e]*PPITCH + ac4[e])*4,
                     &A[(size_t)arow[e] * lda + k0 + ac4[e]]);
                cp16(bbase + (uint32_t)(p*BRSTG128 + bk[e]*BNP128 + bn4[e])*4,
                     &B[(size_t)(k0 + bk[e]) * ldb + bn4[e]]);
            }
        }
        CP_COMMIT();
    }
    for (int c = 0; c < kch; c++) {
        const int st = c % 3;
        if (c + 1 < kch) { CP_WAIT1(); } else { CP_WAIT0(); }
        __syncthreads();
        if (c + 2 < kch) {
            const int nst = (c + 2) % 3;
            const int k0 = (c + 2) * 32;
            #pragma unroll
            for (int e = 0; e < 4; e++) {
                cp16(sbase + (uint32_t)(nst*PSTAGE + arow[e]*PPITCH + ac4[e])*4,
                     &A[(size_t)arow[e] * lda + k0 + ac4[e]]);
                cp16(bbase + (uint32_t)(nst*BRSTG128 + bk[e]*BNP128 + bn4[e])*4,
                     &B[(size_t)(k0 + bk[e]) * ldb + bn4[e]]);
            }
            CP_COMMIT();
        }
        const uint32_t a_st = sbase + (uint32_t)(st*PSTAGE)*4 + a_lm;
        const float* Bb = sm + 3*PSTAGE + st*BRSTG128;
        #pragma unroll
        for (int ks = 0; ks < 4; ks++) {
            uint32_t af[4][4];
            #pragma unroll
            for (int mi = 0; mi < 4; mi++)
                ldsm_x4(af[mi][0], af[mi][1], af[mi][2], af[mi][3],
                        a_st + (uint32_t)(mi*16*PPITCH + ks*8)*4);
            uint32_t bf[4][2];
            #pragma unroll
            for (int ni = 0; ni < 4; ni++) {
                int n = wn*32 + ni*8 + gr;
                bf[ni][0] = __float_as_uint(Bb[(ks*8 + gc)*BNP128 + n]);
                bf[ni][1] = __float_as_uint(Bb[(ks*8 + gc + 4)*BNP128 + n]);
            }
            #pragma unroll
            for (int mi = 0; mi < 4; mi++)
                #pragma unroll
                for (int ni = 0; ni < 4; ni++)
                    mma_tf32_16x8x8(acc[mi][ni],
                        af[mi][0], af[mi][1], af[mi][2], af[mi][3],
                        bf[ni][0], bf[ni][1]);
        }
    }
}

// ============ bf16 pinv batched GEMM: D = c1*U + c2*(A @ B^T), both K-major ============
// Outputs (each optional): Cn bf16 [M][N], Ct bf16 [N][M], Cf fp32 tf32-rounded [M][N].
__global__ void __launch_bounds__(256, 2) pinv_bf16_kernel(
    const __nv_bfloat16* __restrict__ A, const __nv_bfloat16* __restrict__ B,
    const __nv_bfloat16* __restrict__ U,
    __nv_bfloat16* __restrict__ Cn, __nv_bfloat16* __restrict__ Ct,
    float* __restrict__ Cf, float c1, float c2)
{
    extern __shared__ __nv_bfloat16 smh[];
    const uint32_t sbase = (uint32_t)__cvta_generic_to_shared(smh);
    const uint32_t bbase = sbase + 3*HSTG*2;
    const int tid = threadIdx.x;
    const int wid = tid >> 5, lane = tid & 31;
    const int wm = wid >> 2, wn = wid & 3;
    const int gr = lane >> 2, gc = lane & 3;
    const int mtx = lane >> 3, mrow = lane & 7;
    const uint32_t a_lm = ((uint32_t)(((mtx&1)*8 + mrow)) * KPH + (uint32_t)((mtx>>1)*8)) * 2;
    const uint32_t b_lm = ((uint32_t)(((mtx>>1)*8 + mrow)) * KPH + (uint32_t)((mtx&1)*8)) * 2;

    const int tile = blockIdx.x;
    const int batch = tile >> 2;
    const int m0 = ((tile >> 1) & 1) << 7;
    const int n0 = (tile & 1) << 7;
    const size_t boff = (size_t)batch << 16;
    A += boff + (size_t)m0 * ML;
    B += boff + (size_t)n0 * ML;
    if (U)  U  += boff;
    if (Cn) Cn += boff;
    if (Ct) Ct += boff;
    if (Cf) Cf += boff;

    int crow[2], cseg[2];
    #pragma unroll
    for (int e = 0; e < 2; e++) {
        int f = e * 256 + tid;
        crow[e] = f >> 2;
        cseg[e] = (f & 3) * 8;
    }

    float acc[4][4][4];
    #pragma unroll
    for (int mi = 0; mi < 4; mi++)
        #pragma unroll
        for (int ni = 0; ni < 4; ni++)
            #pragma unroll
            for (int e = 0; e < 4; e++) acc[mi][ni][e] = 0.f;

    #pragma unroll
    for (int p = 0; p < 2; p++) {
        const int k0 = p * 32;
        #pragma unroll
        for (int e = 0; e < 2; e++) {
            cp16(sbase + (uint32_t)(p*HSTG + crow[e]*KPH + cseg[e])*2,
                 &A[(size_t)crow[e] * ML + k0 + cseg[e]]);
            cp16(bbase + (uint32_t)(p*HSTG + crow[e]*KPH + cseg[e])*2,
                 &B[(size_t)crow[e] * ML + k0 + cseg[e]]);
        }
        CP_COMMIT();
    }
    for (int c = 0; c < 8; c++) {
        const int st = c % 3;
        if (c + 1 < 8) { CP_WAIT1(); } else { CP_WAIT0(); }
        __syncthreads();
        if (c + 2 < 8) {
            const int nst = (c + 2) % 3;
            const int k0 = (c + 2) * 32;
            #pragma unroll
            for (int e = 0; e < 2; e++) {
                cp16(sbase + (uint32_t)(nst*HSTG + crow[e]*KPH + cseg[e])*2,
                     &A[(size_t)crow[e] * ML + k0 + cseg[e]]);
                cp16(bbase + (uint32_t)(nst*HSTG + crow[e]*KPH + cseg[e])*2,
                     &B[(size_t)crow[e] * ML + k0 + cseg[e]]);
            }
            CP_COMMIT();
        }
        const uint32_t a_st = sbase + (uint32_t)(st*HSTG)*2 + a_lm;
        const uint32_t b_st = bbase + (uint32_t)(st*HSTG)*2 + b_lm;
        #pragma unroll
        for (int ks = 0; ks < 2; ks++) {
            uint32_t af[4][4];
            #pragma unroll
            for (int mi = 0; mi < 4; mi++)
                ldsm_x4(af[mi][0], af[mi][1], af[mi][2], af[mi][3],
                        a_st + (uint32_t)((wm*64 + mi*16)*KPH + ks*16)*2);
            uint32_t bf[4][2];
            #pragma unroll
            for (int p = 0; p < 2; p++)
                ldsm_x4(bf[2*p][0], bf[2*p][1], bf[2*p+1][0], bf[2*p+1][1],
                        b_st + (uint32_t)((wn*32 + p*16)*KPH + ks*16)*2);
            #pragma unroll
            for (int mi = 0; mi < 4; mi++)
                #pragma unroll
                for (int ni = 0; ni < 4; ni++)
                    mma_bf16_16x8x16(acc[mi][ni],
                        af[mi][0], af[mi][1], af[mi][2], af[mi][3],
                        bf[ni][0], bf[ni][1]);
        }
    }

    #pragma unroll
    for (int mi = 0; mi < 4; mi++) {
        #pragma unroll
        for (int ni = 0; ni < 4; ni++) {
            int grow = m0 + wm*64 + mi*16 + gr;
            int gcol = n0 + wn*32 + ni*8 + gc*2;
            const float* a = acc[mi][ni];
            float d0, d1, d2, d3;
            if (U) {
                __nv_bfloat162 u0 = *reinterpret_cast<const __nv_bfloat162*>(&U[(size_t)grow * ML + gcol]);
                __nv_bfloat162 u1 = *reinterpret_cast<const __nv_bfloat162*>(&U[(size_t)(grow+8) * ML + gcol]);
                d0 = c1*__bfloat162float(u0.x) + c2*a[0];
                d1 = c1*__bfloat162float(u0.y) + c2*a[1];
                d2 = c1*__bfloat162float(u1.x) + c2*a[2];
                d3 = c1*__bfloat162float(u1.y) + c2*a[3];
            } else {
                d0 = c2*a[0]; d1 = c2*a[1]; d2 = c2*a[2]; d3 = c2*a[3];
            }
            __nv_bfloat16 h0 = __float2bfloat16(d0), h1 = __float2bfloat16(d1);
            __nv_bfloat16 h2 = __float2bfloat16(d2), h3 = __float2bfloat16(d3);
            if (Cn) {
                __nv_bfloat162 p0; p0.x = h0; p0.y = h1;
                __nv_bfloat162 p1; p1.x = h2; p1.y = h3;
                *reinterpret_cast<__nv_bfloat162*>(&Cn[(size_t)grow * ML + gcol]) = p0;
                *reinterpret_cast<__nv_bfloat162*>(&Cn[(size_t)(grow+8) * ML + gcol]) = p1;
            }
            if (Ct) {
                Ct[(size_t)gcol * ML + grow]       = h0;
                Ct[(size_t)(gcol+1) * ML + grow]   = h1;
                Ct[(size_t)gcol * ML + grow+8]     = h2;
                Ct[(size_t)(gcol+1) * ML + grow+8] = h3;
            }
            if (Cf) {
                *reinterpret_cast<float2*>(&Cf[(size_t)grow * ML + gcol]) =
                    make_float2(cvt_tf32(d0), cvt_tf32(d1));
                *reinterpret_cast<float2*>(&Cf[(size_t)(grow+8) * ML + gcol]) =
                    make_float2(cvt_tf32(d2), cvt_tf32(d3));
            }
        }
    }
}

// ============ plain batched GEMM: C[z] = A[z] @ B[z]^T (B K-major; sims) ============
__global__ void __launch_bounds__(256, 2) gemm_tc_kernel(
    const float* __restrict__ A, const float* __restrict__ B, float* __restrict__ C,
    int lda, int ldb, int ldc, int kch,
    size_t sA, size_t sB, size_t sC)
{
    extern __shared__ float sm[];
    const int tid = threadIdx.x;
    const int z = blockIdx.z;
    const int m0 = blockIdx.y * 128, n0 = blockIdx.x * 128;
    A += (size_t)z * sA + (size_t)m0 * lda;
    B += (size_t)z * sB + (size_t)n0 * ldb;
    C += (size_t)z * sC;
    float acc[4][4][4];
    #pragma unroll
    for (int mi = 0; mi < 4; mi++)
        #pragma unroll
        for (int ni = 0; ni < 4; ni++)
            #pragma unroll
            for (int e = 0; e < 4; e++) acc[mi][ni][e] = 0.f;
    mainloop128x128(A, B, lda, ldb, kch, sm, tid, acc);
    const int wid = tid >> 5, lane = tid & 31;
    const int gr = lane >> 2, gc = lane & 3;
    const int wm = wid >> 2, wn = wid & 3;
    #pragma unroll
    for (int mi = 0; mi < 4; mi++) {
        #pragma unroll
        for (int ni = 0; ni < 4; ni++) {
            int lr = m0 + wm*64 + mi*16 + gr;
            int lc = n0 + wn*32 + ni*8 + gc*2;
            const float* a = acc[mi][ni];
            *reinterpret_cast<float2*>(&C[(size_t)lr * ldc + lc]) = make_float2(a[0], a[1]);
            *reinterpret_cast<float2*>(&C[(size_t)(lr+8) * ldc + lc]) = make_float2(a[2], a[3]);
        }
    }
}

// ============ QKV^T GEMM: qkvT[n][i] = wqkvT[n][c] @ x[b][c][i] ============
// A = wqkvT [1536][512] K-major; B = x[b] naturally row-major [c=512][i=1024].
// x enters mma via HW tf32 truncation. Scatter epilogue to q/k/v (tf32-rounded).
__global__ void __launch_bounds__(256, 2) qkvT_tc_kernel(const float* __restrict__ x) {
    extern __shared__ float sm[];
    const int tid = threadIdx.x;
    const int m0 = blockIdx.y * 128;        // over 1536 qkv dims
    const int n0 = blockIdx.x * 128;        // over 1024 tokens
    const int b  = blockIdx.z;
    const float* A = g_wqkvT + (size_t)m0 * CDIM;
    const float* B = x + (size_t)b * CDIM * NTOK + n0;
    float acc[4][4][4];
    #pragma unroll
    for (int mi = 0; mi < 4; mi++)
        #pragma unroll
        for (int ni = 0; ni < 4; ni++)
            #pragma unroll
            for (int e = 0; e < 4; e++) acc[mi][ni][e] = 0.f;
    mainloop128x128_rowB(A, B, CDIM, NTOK, CDIM/32, sm, tid, acc);
    const int wid = tid >> 5, lane = tid & 31;
    const int gr = lane >> 2, gc = lane & 3;
    const int wm = wid >> 2, wn = wid & 3;
    #pragma unroll
    for (int mi = 0; mi < 4; mi++) {
        int m = m0 + wm*64 + mi*16 + gr;      // qkv dim; m and m+8 share which/h
        int which = m >> 9;
        int h = (m >> 6) & 7;
        int d = m & 63;
        int bh = b*8 + h;
        float* dst = (which == 0) ? g_q : ((which == 1) ? g_k : g_v);
        float sc = (which == 0) ? 0.125f : 1.0f;
        #pragma unroll
        for (int ni = 0; ni < 4; ni++) {
            int i = n0 + wn*32 + ni*8 + gc*2; // token index
            const float* a = acc[mi][ni];
            dst[((size_t)(bh*NTOK + i))*DH + d]       = cvt_tf32(a[0]*sc);
            dst[((size_t)(bh*NTOK + i + 1))*DH + d]   = cvt_tf32(a[1]*sc);
            dst[((size_t)(bh*NTOK + i))*DH + d + 8]   = cvt_tf32(a[2]*sc);
            dst[((size_t)(bh*NTOK + i + 1))*DH + d + 8] = cvt_tf32(a[3]*sc);
        }
    }
}

// ============ final GEMM: out = outf @ woutT^T + bias, transposed store (fp32) ============
__global__ void __launch_bounds__(256, 2) final_tc_kernel(
    const float* __restrict__ bias, float* __restrict__ out)
{
    extern __shared__ float sm[];
    const int tid = threadIdx.x;
    const int m0 = blockIdx.y * 128;
    const int n0 = blockIdx.x * 128;
    const float* A = g_outf + (size_t)m0 * CDIM;
    const float* B = g_woutT + (size_t)n0 * CDIM;
    float acc[4][4][4];
    #pragma unroll
    for (int mi = 0; mi < 4; mi++)
        #pragma unroll
        for (int ni = 0; ni < 4; ni++)
            #pragma unroll
            for (int e = 0; e < 4; e++) acc[mi][ni][e] = 0.f;
    mainloop128x128(A, B, CDIM, CDIM, CDIM/32, sm, tid, acc);
    const int wid = tid >> 5, lane = tid & 31;
    const int gr = lane >> 2, gc = lane & 3;
    const int wm = wid >> 2, wn = wid & 3;
    #pragma unroll
    for (int mi = 0; mi < 4; mi++) {
        int m = m0 + wm*64 + mi*16 + gr;
        int b = m >> 10, i = m & 1023;
        #pragma unroll
        for (int ni = 0; ni < 4; ni++) {
            int n = n0 + wn*32 + ni*8 + gc*2;
            const float* a = acc[mi][ni];
            float b0 = bias[n], b1 = bias[n+1];
            out[((size_t)(b*CDIM + n))*NTOK + i]       = a[0] + b0;
            out[((size_t)(b*CDIM + n + 1))*NTOK + i]   = a[1] + b1;
            out[((size_t)(b*CDIM + n))*NTOK + i + 8]   = a[2] + b0;
            out[((size_t)(b*CDIM + n + 1))*NTOK + i + 8] = a[3] + b1;
        }
    }
}

// ============ 128x64 batched GEMM, B row-major [K,64]: C = A @ B ============
__global__ void __launch_bounds__(256, 2) gemm64_rowB_kernel(
    const float* __restrict__ A, const float* __restrict__ B, float* __restrict__ C,
    int lda, int kch, size_t sA, size_t sB, int flatC)
{
    extern __shared__ float sm[];
    const uint32_t sbase = (uint32_t)__cvta_generic_to_shared(sm);
    const uint32_t bbase = sbase + 3*PSTAGE*4;
    const int tid = threadIdx.x;
    const int wid = tid >> 5, lane = tid & 31;
    const int gr = lane >> 2, gc = lane & 3;
    const int wm = wid >> 1, wn = wid & 1;
    const int g = lane >> 3, r8 = lane & 7;
    const uint32_t a_lm = (uint32_t)((wm*32 + (g&1)*8 + r8)*PPITCH + (g>>1)*4)*4;
    const int z = blockIdx.z;
    const int m0 = blockIdx.x * 128;
    A += (size_t)z * sA + (size_t)m0 * lda;
    B += (size_t)z * sB;
    if (flatC) C += (size_t)(z >> 3) * (NTOK*CDIM) + (size_t)(z & 7) * DH;
    else       C += (size_t)z * (ML*DH);

    int arow[4], ac4[4], bk[2], bn4[2];
    #pragma unroll
    for (int e = 0; e < 4; e++) {
        int f4 = e * 256 + tid;
        arow[e] = f4 >> 3;  ac4[e] = (f4 & 7) << 2;
    }
    #pragma unroll
    for (int e = 0; e < 2; e++) {
        int f4 = e * 256 + tid;
        bk[e] = f4 >> 4;  bn4[e] = (f4 & 15) << 2;
    }

    float acc[2][4][4];
    #pragma unroll
    for (int mi = 0; mi < 2; mi++)
        #pragma unroll
        for (int ni = 0; ni < 4; ni++)
            #pragma unroll
            for (int e = 0; e < 4; e++) acc[mi][ni][e] = 0.f;

    #pragma unroll
    for (int p = 0; p < 2; p++) {
        if (p < kch) {
            const int k0 = p * 32;
            #pragma unroll
            for (int e = 0; e < 4; e++)
                cp16(sbase + (uint32_t)(p*PSTAGE + arow[e]*PPITCH + ac4[e])*4,
                     &A[(size_t)arow[e] * lda + k0 + ac4[e]]);
            #pragma unroll
            for (int e = 0; e < 2; e++)
                cp16(bbase + (uint32_t)(p*BRSTG64 + bk[e]*BNP64 + bn4[e])*4,
                     &B[(size_t)(k0 + bk[e]) * DH + bn4[e]]);
        }
        CP_COMMIT();
    }

    for (int c = 0; c < kch; c++) {
        const int st = c % 3;
        if (c + 1 < kch) { CP_WAIT1(); } else { CP_WAIT0(); }
        __syncthreads();
        if (c + 2 < kch) {
            const int nst = (c + 2) % 3;
            const int k0 = (c + 2) * 32;
            #pragma unroll
            for (int e = 0; e < 4; e++)
                cp16(sbase + (uint32_t)(nst*PSTAGE + arow[e]*PPITCH + ac4[e])*4,
                     &A[(size_t)arow[e] * lda + k0 + ac4[e]]);
            #pragma unroll
            for (int e = 0; e < 2; e++)
                cp16(bbase + (uint32_t)(nst*BRSTG64 + bk[e]*BNP64 + bn4[e])*4,
                     &B[(size_t)(k0 + bk[e]) * DH + bn4[e]]);
            CP_COMMIT();
        }
        const uint32_t a_st = sbase + (uint32_t)(st*PSTAGE)*4 + a_lm;
        const float* Bb = sm + 3*PSTAGE + st*BRSTG64;
        #pragma unroll
        for (int ks = 0; ks < 4; ks++) {
            uint32_t af[2][4];
            #pragma unroll
            for (int mi = 0; mi < 2; mi++)
                ldsm_x4(af[mi][0], af[mi][1], af[mi][2], af[mi][3],
                        a_st + (uint32_t)(mi*16*PPITCH + ks*8)*4);
            uint32_t bf[4][2];
            #pragma unroll
            for (int ni = 0; ni < 4; ni++) {
                int n = wn*32 + ni*8 + gr;
                bf[ni][0] = __float_as_uint(Bb[(ks*8 + gc)*BNP64 + n]);
                bf[ni][1] = __float_as_uint(Bb[(ks*8 + gc + 4)*BNP64 + n]);
            }
            #pragma unroll
            for (int mi = 0; mi < 2; mi++)
                #pragma unroll
                for (int ni = 0; ni < 4; ni++)
                    mma_tf32_16x8x8(acc[mi][ni],
                        af[mi][0], af[mi][1], af[mi][2], af[mi][3],
                        bf[ni][0], bf[ni][1]);
        }
    }

    #pragma unroll
    for (int mi = 0; mi < 2; mi++) {
        #pragma unroll
        for (int ni = 0; ni < 4; ni++) {
            int lr = m0 + wm*32 + mi*16 + gr;
            int lc = wn*32 + ni*8 + gc*2;
            const float* a = acc[mi][ni];
            float d0 = cvt_tf32(a[0]), d1 = cvt_tf32(a[1]);
            float d2 = cvt_tf32(a[2]), d3 = cvt_tf32(a[3]);
            int ldc = flatC ? CDIM : DH;
            *reinterpret_cast<float2*>(&C[(size_t)lr * ldc + lc]) = make_float2(d0, d1);
            *reinterpret_cast<float2*>(&C[(size_t)(lr+8) * ldc + lc]) = make_float2(d2, d3);
        }
    }
}

// ---------------- batched 2D transpose (tf32-rounded output) ----------------
__global__ void transpose_kernel(const float* __restrict__ in, float* __restrict__ out,
                                 int R, int C) {
    __shared__ float tile[32][33];
    const int z = blockIdx.z;
    in  += (size_t)z * R * C;
    out += (size_t)z * R * C;
    int c0 = blockIdx.x * 32, r0 = blockIdx.y * 32;
    int tx = threadIdx.x, ty = threadIdx.y;
    #pragma unroll
    for (int j = 0; j < 4; j++)
        tile[ty + j*8][tx] = in[(size_t)(r0 + ty + j*8) * C + c0 + tx];
    __syncthreads();
    #pragma unroll
    for (int j = 0; j < 4; j++)
        out[(size_t)(c0 + ty + j*8) * R + r0 + tx] = cvt_tf32(tile[tx][ty + j*8]);
}

// ---------------- landmark means (tf32-rounded) ----------------
__global__ void land_kernel() {
    int idx = blockIdx.x * blockDim.x + threadIdx.x;
    if (idx >= BHN*ML*DH) return;
    int d  = idx & 63;
    int j  = (idx >> 6) & 255;
    int bh = idx >> 14;
    size_t base = ((size_t)bh * NTOK + j*4) * DH + d;
    g_ql[idx] = cvt_tf32(0.25f * (g_q[base] + g_q[base+64] + g_q[base+128] + g_q[base+192]));
    g_kl[idx] = cvt_tf32(0.25f * (g_k[base] + g_k[base+64] + g_k[base+128] + g_k[base+192]));
}

// ---------------- warp-per-row softmax: fast exp, zero block barriers ----------------
template<int W>
__global__ void softmax_warp_kernel(float* __restrict__ data) {
    const int lane = threadIdx.x & 31;
    const int row = blockIdx.x * 8 + (threadIdx.x >> 5);
    float* r = data + (size_t)row * W;
    constexpr int PE = W / 32;
    float v[PE];
    float mx = -1e30f;
    #pragma unroll
    for (int e = 0; e < PE; e++) { v[e] = r[lane + e*32]; mx = fmaxf(mx, v[e]); }
    #pragma unroll
    for (int o = 16; o > 0; o >>= 1) mx = fmaxf(mx, __shfl_xor_sync(0xffffffffu, mx, o));
    float s = 0.f;
    #pragma unroll
    for (int e = 0; e < PE; e++) { v[e] = __expf(v[e] - mx); s += v[e]; }
    #pragma unroll
    for (int o = 16; o > 0; o >>= 1) s += __shfl_xor_sync(0xffffffffu, s, o);
    float inv = 1.0f / s;
    #pragma unroll
    for (int e = 0; e < PE; e++) r[lane + e*32] = cvt_tf32(v[e] * inv);
}

// ---------------- pinv scale reductions ----------------
__global__ void reset_max_kernel() { if (threadIdx.x == 0) { g_colmax = 0u; g_rowmax = 0u; } }

__global__ void colmax_kernel() {
    int gw = (blockIdx.x * blockDim.x + threadIdx.x) >> 5;
    int lane = threadIdx.x & 31;
    if (gw >= BHN * ML) return;
    const float* row = g_attn2 + (size_t)gw * ML;
    float s = 0.f;
    #pragma unroll
    for (int j = lane; j < ML; j += 32) s += fabsf(row[j]);
    #pragma unroll
    for (int o = 16; o > 0; o >>= 1) s += __shfl_down_sync(0xffffffffu, s, o);
    if (lane == 0) atomicMax(&g_colmax, __float_as_uint(s));
}

__global__ void rowmax_kernel() {
    int idx = blockIdx.x * blockDim.x + threadIdx.x;
    if (idx >= BHN * ML) return;
    int bh = idx >> 8, j = idx & 255;
    const float* base = g_attn2 + (size_t)bh * ML * ML + j;
    float s = 0.f;
    for (int i = 0; i < ML; i++) s += fabsf(base[(size_t)i * ML]);
    atomicMax(&g_rowmax, __float_as_uint(s));
}

// zinit: z0 (bf16, row + transposed) and a2h (bf16 of a2)
__global__ void zinit_kernel() {
    float inv = 1.0f / (__uint_as_float(g_colmax) * __uint_as_float(g_rowmax));
    size_t idx = (size_t)blockIdx.x * 256 + threadIdx.x;
    int j  = idx & 255;
    int i  = (idx >> 8) & 255;
    size_t bh = idx >> 16;
    float a2v  = g_attn2[idx];
    float a2tv = g_attn2[(bh << 16) + ((size_t)j << 8) + i];
    g_zhA[idx]  = __float2bfloat16(a2tv * inv);   // z0 row-major = scaled x^T
    g_zhTA[idx] = __float2bfloat16(a2v * inv);    // z0^T = scaled x
    g_a2h[idx]  = __float2bfloat16(a2v);
}

// ---------------- depthwise 33-tap conv residual (tf32-rounded add) ----------------
__global__ void res_add_kernel(const float* __restrict__ rk) {
    __shared__ float ker[KSZ];
    int blk = blockIdx.x;
    int bh = blk >> 8;
    int ichunk = blk & 255;
    int h = bh & 7, b = bh >> 3;
    if (threadIdx.x < KSZ) ker[threadIdx.x] = rk[h*KSZ + threadIdx.x];
    __syncthreads();
    int d = threadIdx.x & 63;
    int i = ichunk * 4 + (threadIdx.x >> 6);
    const float* vb = g_v + (size_t)bh * NTOK * DH;
    float s = 0.f;
    #pragma unroll
    for (int t = 0; t < KSZ; t++) {
        int ii = i + t - (KSZ/2);
        if (ii >= 0 && ii < NTOK) s += ker[t] * vb[(size_t)ii * DH + d];
    }
    size_t o = ((size_t)(b*NTOK + i)) * CDIM + h*64 + d;
    g_outf[o] = cvt_tf32(g_outf[o] + s);
}

// ---------------- host ----------------
extern "C" void kernel_launch(void* const* d_in, const int* in_sizes, int n_in,
                              void* d_out, int out_size) {
    const float* x     = (const float*)d_in[0];
    const float* w_qkv = (const float*)d_in[1];
    const float* w_out = (const float*)d_in[2];
    const float* b_out = (const float*)d_in[3];
    const float* rk    = (const float*)d_in[4];
    float* out = (float*)d_out;

    float *wqkvT, *woutT, *q, *k, *v, *ql, *kl, *a1, *a3, *a2;
    float *zA, *av, *bv, *outf;
    __nv_bfloat16 *a2h, *zhA, *zhB, *zhTA, *zhTB, *xzh, *xzhT, *t1hT, *t2hT;
    cudaGetSymbolAddress((void**)&wqkvT, g_wqkvT);
    cudaGetSymbolAddress((void**)&woutT, g_woutT);
    cudaGetSymbolAddress((void**)&q,  g_q);
    cudaGetSymbolAddress((void**)&k,  g_k);
    cudaGetSymbolAddress((void**)&v,  g_v);
    cudaGetSymbolAddress((void**)&ql, g_ql);
    cudaGetSymbolAddress((void**)&kl, g_kl);
    cudaGetSymbolAddress((void**)&a1, g_attn1);
    cudaGetSymbolAddress((void**)&a3, g_attn3);
    cudaGetSymbolAddress((void**)&a2, g_attn2);
    cudaGetSymbolAddress((void**)&zA, g_zA);
    cudaGetSymbolAddress((void**)&av, g_av);
    cudaGetSymbolAddress((void**)&bv, g_bv);
    cudaGetSymbolAddress((void**)&outf, g_outf);
    cudaGetSymbolAddress((void**)&a2h,  g_a2h);
    cudaGetSymbolAddress((void**)&zhA,  g_zhA);
    cudaGetSymbolAddress((void**)&zhB,  g_zhB);
    cudaGetSymbolAddress((void**)&zhTA, g_zhTA);
    cudaGetSymbolAddress((void**)&zhTB, g_zhTB);
    cudaGetSymbolAddress((void**)&xzh,  g_xzh);
    cudaGetSymbolAddress((void**)&xzhT, g_xzhT);
    cudaGetSymbolAddress((void**)&t1hT, g_t1hT);
    cudaGetSymbolAddress((void**)&t2hT, g_t2hT);

    cudaFuncSetAttribute(pinv_bf16_kernel,   cudaFuncAttributeMaxDynamicSharedMemorySize, BH_SMEM3);
    cudaFuncSetAttribute(gemm_tc_kernel,     cudaFuncAttributeMaxDynamicSharedMemorySize, G128_SMEM3);
    cudaFuncSetAttribute(qkvT_tc_kernel,     cudaFuncAttributeMaxDynamicSharedMemorySize, PB_SMEM3);
    cudaFuncSetAttribute(final_tc_kernel,    cudaFuncAttributeMaxDynamicSharedMemorySize, G128_SMEM3);
    cudaFuncSetAttribute(gemm64_rowB_kernel, cudaFuncAttributeMaxDynamicSharedMemorySize, G64R_SMEM3);

    // 0) layout prep (weights only — x is consumed in natural layout)
    transpose_kernel<<<dim3(48, 16, 1), dim3(32,8)>>>(w_qkv, wqkvT, CDIM, 3*CDIM);
    transpose_kernel<<<dim3(16, 16, 1), dim3(32,8)>>>(w_out, woutT, CDIM, CDIM);
    // 1) QKV projection, transposed form (x read directly; no x-transpose pass)
    qkvT_tc_kernel<<<dim3(8, 12, BATCH), 256, PB_SMEM3>>>(x);
    // 2) landmarks
    land_kernel<<<(BHN*ML*DH + 255)/256, 256>>>();
    // 3) similarity GEMMs
    gemm_tc_kernel<<<dim3(2, 8, BHN), 256, G128_SMEM3>>>(q,  kl, a1, DH, DH, ML,   2,
        (size_t)NTOK*DH, (size_t)ML*DH, (size_t)NTOK*ML);
    gemm_tc_kernel<<<dim3(2, 2, BHN), 256, G128_SMEM3>>>(ql, kl, a2, DH, DH, ML,   2,
        (size_t)ML*DH,   (size_t)ML*DH, (size_t)ML*ML);
    gemm_tc_kernel<<<dim3(8, 2, BHN), 256, G128_SMEM3>>>(ql, k,  a3, DH, DH, NTOK, 2,
        (size_t)ML*DH,   (size_t)NTOK*DH, (size_t)ML*NTOK);
    // 4) softmaxes — warp-per-row, fast exp
    softmax_warp_kernel<256> <<<BHN*NTOK/8, 256>>>(a1);
    softmax_warp_kernel<256> <<<BHN*ML/8,   256>>>(a2);
    softmax_warp_kernel<1024><<<BHN*ML/8,   256>>>(a3);
    // 5) pinv init (bf16 z0 / z0^T / a2h)
    reset_max_kernel<<<1, 32>>>();
    colmax_kernel<<<(BHN*ML*32)/256, 256>>>();
    rowmax_kernel<<<(BHN*ML)/256, 256>>>();
    zinit_kernel<<<(BHN*ML*ML)/256, 256>>>();
    // 6) Newton–Schulz: all 6 iterations in bf16 (noise contracted each iteration;
    //    empirically each precision downgrade added <2e-6 to rel_err). Final
    //    update of iteration 6 emits z as fp32 (tf32-rounded) via the Cf path.
    __nv_bfloat16 *zh_in = zhA, *zh_out = zhB, *zhT_in = zhTA, *zhT_out = zhTB;
    for (int it = 0; it < 6; it++) {
        pinv_bf16_kernel<<<1024, 256, BH_SMEM3>>>(a2h, zhT_in, nullptr, xzh, xzhT, nullptr, 0.0f, 1.0f);
        pinv_bf16_kernel<<<1024, 256, BH_SMEM3>>>(xzh, xzhT, xzh, nullptr, t1hT, nullptr, 7.0f, -1.0f);
        pinv_bf16_kernel<<<1024, 256, BH_SMEM3>>>(xzh, t1hT, xzh, nullptr, t2hT, nullptr, 15.0f, -1.0f);
        if (it < 5) {
            pinv_bf16_kernel<<<1024, 256, BH_SMEM3>>>(zh_in, t2hT, zh_in, zh_out, zhT_out, nullptr, 3.25f, -0.25f);
            __nv_bfloat16* tmp;
            tmp = zh_in;  zh_in  = zh_out;  zh_out  = tmp;
            tmp = zhT_in; zhT_in = zhT_out; zhT_out = tmp;
        } else {
            pinv_bf16_kernel<<<1024, 256, BH_SMEM3>>>(zh_in, t2hT, zh_in, nullptr, nullptr, zA, 3.25f, -0.25f);
        }
    }
    float* zfin = zA;
    // 7) output chain: av = attn3@v ; bv = z@av ; outf = attn1@bv
    gemm64_rowB_kernel<<<dim3(2, 1, BHN), 256, G64R_SMEM3>>>(a3, v, av,
        NTOK, 32, (size_t)ML*NTOK, (size_t)NTOK*DH, 0);
    gemm64_rowB_kernel<<<dim3(2, 1, BHN), 256, G64R_SMEM3>>>(zfin, av, bv,
        ML, 8, (size_t)ML*ML, (size_t)ML*DH, 0);
    gemm64_rowB_kernel<<<dim3(8, 1, BHN), 256, G64R_SMEM3>>>(a1, bv, outf,
        ML, 8, (size_t)NTOK*ML, (size_t)ML*DH, 1);
    // 8) depthwise conv residual (standalone — epilogue fusion regressed in R13)
    res_add_kernel<<<BHN*256, 256>>>(rk);
    // 9) output projection + bias + transposed store
    final_tc_kernel<<<dim3(4, 256), 256, G128_SMEM3>>>(b_out, out);
}

// round 16
// speedup vs baseline: 1.0634x; 1.0029x over previous
#include <cuda_runtime.h>
#include <cuda_bf16.h>
#include <cstdint>
#include <cstddef>

#define BATCH 32
#define HEADS 8
#define NTOK 1024
#define DH 64
#define ML 256          // landmarks
#define CDIM 512
#define BHN (BATCH*HEADS)   // 256
#define KSZ 33

// ---------------- device scratch ----------------
__device__ float g_wqkvT[3*CDIM*CDIM];              // (1536, 512), tf32-rounded
__device__ float g_woutT[CDIM*CDIM];                // (512, 512), tf32-rounded
__device__ float g_q [BHN*NTOK*DH];
__device__ float g_k [BHN*NTOK*DH];
__device__ float g_v [BHN*NTOK*DH];
__device__ float g_ql[BHN*ML*DH];
__device__ float g_kl[BHN*ML*DH];
__device__ float g_attn1[(size_t)BHN*NTOK*ML];      // (bh,1024,256)
__device__ float g_attn3[(size_t)BHN*ML*NTOK];      // (bh,256,1024)
__device__ float g_attn2[BHN*ML*ML];
__device__ float g_zA[BHN*ML*ML];                   // final z (fp32)
__device__ float g_av[BHN*ML*DH];
__device__ float g_bv[BHN*ML*DH];
__device__ float g_outf[(size_t)BATCH*NTOK*CDIM];   // (b, n, 512)
__device__ unsigned g_colmax;
__device__ unsigned g_rowmax;
// bf16 pinv buffers
__device__ __nv_bfloat16 g_a2h [BHN*ML*ML];   // bf16(a2), row-major [M][K]
__device__ __nv_bfloat16 g_zhA [BHN*ML*ML];   // z row-major
__device__ __nv_bfloat16 g_zhB [BHN*ML*ML];
__device__ __nv_bfloat16 g_zhTA[BHN*ML*ML];   // z^T (K-major for B operand)
__device__ __nv_bfloat16 g_zhTB[BHN*ML*ML];
__device__ __nv_bfloat16 g_xzh [BHN*ML*ML];
__device__ __nv_bfloat16 g_xzhT[BHN*ML*ML];
__device__ __nv_bfloat16 g_t1hT[BHN*ML*ML];
__device__ __nv_bfloat16 g_t2hT[BHN*ML*ML];

// ================= helpers =================
__device__ __forceinline__ float cvt_tf32(float x) {
    uint32_t u;
    asm("cvt.rna.tf32.f32 %0, %1;" : "=r"(u) : "f"(x));
    return __uint_as_float(u);
}
__device__ __forceinline__ void mma_tf32_16x8x8(float c[4],
    uint32_t a0, uint32_t a1, uint32_t a2, uint32_t a3, uint32_t b0, uint32_t b1) {
    asm volatile(
        "mma.sync.aligned.m16n8k8.row.col.f32.tf32.tf32.f32 "
        "{%0,%1,%2,%3},{%4,%5,%6,%7},{%8,%9},{%0,%1,%2,%3};"
        : "+f"(c[0]), "+f"(c[1]), "+f"(c[2]), "+f"(c[3])
        : "r"(a0), "r"(a1), "r"(a2), "r"(a3), "r"(b0), "r"(b1));
}
__device__ __forceinline__ void mma_bf16_16x8x16(float c[4],
    uint32_t a0, uint32_t a1, uint32_t a2, uint32_t a3, uint32_t b0, uint32_t b1) {
    asm volatile(
        "mma.sync.aligned.m16n8k16.row.col.f32.bf16.bf16.f32 "
        "{%0,%1,%2,%3},{%4,%5,%6,%7},{%8,%9},{%0,%1,%2,%3};"
        : "+f"(c[0]), "+f"(c[1]), "+f"(c[2]), "+f"(c[3])
        : "r"(a0), "r"(a1), "r"(a2), "r"(a3), "r"(b0), "r"(b1));
}
__device__ __forceinline__ void ldsm_x4(uint32_t& r0, uint32_t& r1,
                                        uint32_t& r2, uint32_t& r3, uint32_t saddr) {
    asm volatile("ldmatrix.sync.aligned.m8n8.x4.shared.b16 {%0,%1,%2,%3}, [%4];"
                 : "=r"(r0), "=r"(r1), "=r"(r2), "=r"(r3) : "r"(saddr));
}
__device__ __forceinline__ void cp16(uint32_t dst, const void* src) {
    asm volatile("cp.async.cg.shared.global [%0], [%1], 16;" :: "r"(dst), "l"(src));
}
#define CP_COMMIT() asm volatile("cp.async.commit_group;")
#define CP_WAIT1()  asm volatile("cp.async.wait_group 1;" ::: "memory")
#define CP_WAIT0()  asm volatile("cp.async.wait_group 0;" ::: "memory")

#define PPITCH 36
#define PSTAGE (128*PPITCH)
#define G128_SMEM3 (6*PSTAGE*4)                     // 110592 (A,B both K-major fp32)

#define BNP128 136
#define BRSTG128 (32*BNP128)
#define PB_SMEM3 ((3*PSTAGE + 3*BRSTG128)*4)        // 107520

#define BNP64 72
#define BRSTG64 (32*BNP64)
#define G64R_SMEM3 ((3*PSTAGE + 3*BRSTG64)*4)       // 82944

// bf16 tiles: [128 rows][KPH halves] per chunk (32 halves data, pitch 40)
#define KPH 40
#define HSTG (128*KPH)                               // halves per stage
#define BH_SMEM3 (6*HSTG*2)                          // 61440 bytes

// ============ mainloop A: B stored K-major ([N rows][K]) — sims/final ============
__device__ __forceinline__ void mainloop128x128(
    const float* __restrict__ A, const float* __restrict__ B,
    int lda, int ldb, int kch, float* sm, int tid, float acc[4][4][4])
{
    const uint32_t sbase = (uint32_t)__cvta_generic_to_shared(sm);
    const uint32_t bbase = sbase + 3*PSTAGE*4;
    const int wid = tid >> 5, lane = tid & 31;
    const int wm = wid >> 2, wn = wid & 3;
    const int g = lane >> 3, r8 = lane & 7;
    const uint32_t a_lm = (uint32_t)((wm*64 + (g&1)*8 + r8)*PPITCH + (g>>1)*4)*4;
    const uint32_t b_lm = (uint32_t)((wn*32 + (g>>1)*8 + r8)*PPITCH + (g&1)*4)*4;
    int rrow[4], rc4[4];
    #pragma unroll
    for (int e = 0; e < 4; e++) {
        int f4 = e * 256 + tid;
        rrow[e] = f4 >> 3;
        rc4[e] = (f4 & 7) << 2;
    }
    #pragma unroll
    for (int p = 0; p < 2; p++) {
        if (p < kch) {
            const int k0 = p * 32;
            #pragma unroll
            for (int e = 0; e < 4; e++) {
                cp16(sbase + (uint32_t)(p*PSTAGE + rrow[e]*PPITCH + rc4[e])*4,
                     &A[(size_t)rrow[e] * lda + k0 + rc4[e]]);
                cp16(bbase + (uint32_t)(p*PSTAGE + rrow[e]*PPITCH + rc4[e])*4,
                     &B[(size_t)rrow[e] * ldb + k0 + rc4[e]]);
            }
        }
        CP_COMMIT();
    }
    for (int c = 0; c < kch; c++) {
        const int st = c % 3;
        if (c + 1 < kch) { CP_WAIT1(); } else { CP_WAIT0(); }
        __syncthreads();
        if (c + 2 < kch) {
            const int nst = (c + 2) % 3;
            const int k0 = (c + 2) * 32;
            #pragma unroll
            for (int e = 0; e < 4; e++) {
                cp16(sbase + (uint32_t)(nst*PSTAGE + rrow[e]*PPITCH + rc4[e])*4,
                     &A[(size_t)rrow[e] * lda + k0 + rc4[e]]);
                cp16(bbase + (uint32_t)(nst*PSTAGE + rrow[e]*PPITCH + rc4[e])*4,
                     &B[(size_t)rrow[e] * ldb + k0 + rc4[e]]);
            }
            CP_COMMIT();
        }
        const uint32_t a_st = sbase + (uint32_t)(st*PSTAGE)*4 + a_lm;
        const uint32_t b_st = bbase + (uint32_t)(st*PSTAGE)*4 + b_lm;
        #pragma unroll
        for (int ks = 0; ks < 4; ks++) {
            uint32_t af[4][4];
            #pragma unroll
            for (int mi = 0; mi < 4; mi++)
                ldsm_x4(af[mi][0], af[mi][1], af[mi][2], af[mi][3],
                        a_st + (uint32_t)(mi*16*PPITCH + ks*8)*4);
            uint32_t bf[4][2];
            #pragma unroll
            for (int p = 0; p < 2; p++)
                ldsm_x4(bf[2*p][0], bf[2*p][1], bf[2*p+1][0], bf[2*p+1][1],
                        b_st + (uint32_t)(p*16*PPITCH + ks*8)*4);
            #pragma unroll
            for (int mi = 0; mi < 4; mi++)
                #pragma unroll
                for (int ni = 0; ni < 4; ni++)
                    mma_tf32_16x8x8(acc[mi][ni],
                        af[mi][0], af[mi][1], af[mi][2], af[mi][3],
                        bf[ni][0], bf[ni][1]);
        }
    }
}

// ============ mainloop B: B stored row-major [K][N] — qkvT ============
__device__ __forceinline__ void mainloop128x128_rowB(
    const float* __restrict__ A, const float* __restrict__ B,
    int lda, int ldb, int kch, float* sm, int tid, float acc[4][4][4])
{
    const uint32_t sbase = (uint32_t)__cvta_generic_to_shared(sm);
    const uint32_t bbase = sbase + 3*PSTAGE*4;
    const int wid = tid >> 5, lane = tid & 31;
    const int gr = lane >> 2, gc = lane & 3;
    const int wm = wid >> 2, wn = wid & 3;
    const int g = lane >> 3, r8 = lane & 7;
    const uint32_t a_lm = (uint32_t)((wm*64 + (g&1)*8 + r8)*PPITCH + (g>>1)*4)*4;
    int arow[4], ac4[4], bk[4], bn4[4];
    #pragma unroll
    for (int e = 0; e < 4; e++) {
        int f4 = e * 256 + tid;
        arow[e] = f4 >> 3;  ac4[e] = (f4 & 7) << 2;
        bk[e]   = f4 >> 5;  bn4[e] = (f4 & 31) << 2;
    }
    #pragma unroll
    for (int p = 0; p < 2; p++) {
        if (p < kch) {
            const int k0 = p * 32;
            #pragma unroll
            for (int e = 0; e < 4; e++) {
                cp16(sbase + (uint32_t)(p*PSTAGE + arow[e]*PPITCH + ac4[e])*4,
                     &A[(size_t)arow[e] * lda + k0 + ac4[e]]);
                cp16(bbase + (uint32_t)(p*BRSTG128 + bk[e]*BNP128 + bn4[e])*4,
                     &B[(size_t)(k0 + bk[e]) * ldb + bn4[e]]);
            }
        }
        CP_COMMIT();
    }
    for (int c = 0; c < kch; c++) {
        const int st = c % 3;
        if (c + 1 < kch) { CP_WAIT1(); } else { CP_WAIT0(); }
        __syncthreads();
        if (c + 2 < kch) {
            const int nst = (c + 2) % 3;
            const int k0 = (c + 2) * 32;
            #pragma unroll
            for (int e = 0; e < 4; e++) {
                cp16(sbase + (uint32_t)(nst*PSTAGE + arow[e]*PPITCH + ac4[e])*4,
                     &A[(size_t)arow[e] * lda + k0 + ac4[e]]);
                cp16(bbase + (uint32_t)(nst*BRSTG128 + bk[e]*BNP128 + bn4[e])*4,
                     &B[(size_t)(k0 + bk[e]) * ldb + bn4[e]]);
            }
            CP_COMMIT();
        }
        const uint32_t a_st = sbase + (uint32_t)(st*PSTAGE)*4 + a_lm;
        const float* Bb = sm + 3*PSTAGE + st*BRSTG128;
        #pragma unroll
        for (int ks = 0; ks < 4; ks++) {
            uint32_t af[4][4];
            #pragma unroll
            for (int mi = 0; mi < 4; mi++)
                ldsm_x4(af[mi][0], af[mi][1], af[mi][2], af[mi][3],
                        a_st + (uint32_t)(mi*16*PPITCH + ks*8)*4);
            uint32_t bf[4][2];
            #pragma unroll
            for (int ni = 0; ni < 4; ni++) {
                int n = wn*32 + ni*8 + gr;
                bf[ni][0] = __float_as_uint(Bb[(ks*8 + gc)*BNP128 + n]);
                bf[ni][1] = __float_as_uint(Bb[(ks*8 + gc + 4)*BNP128 + n]);
            }
            #pragma unroll
            for (int mi = 0; mi < 4; mi++)
                #pragma unroll
                for (int ni = 0; ni < 4; ni++)
                    mma_tf32_16x8x8(acc[mi][ni],
                        af[mi][0], af[mi][1], af[mi][2], af[mi][3],
                        bf[ni][0], bf[ni][1]);
        }
    }
}

// ============ bf16 pinv batched GEMM: D = c1*U + c2*(A @ B^T), both K-major ============
// Outputs (each optional): Cn bf16 [M][N], Ct bf16 [N][M], Cf fp32 tf32-rounded [M][N].
__global__ void __launch_bounds__(256, 2) pinv_bf16_kernel(
    const __nv_bfloat16* __restrict__ A, const __nv_bfloat16* __restrict__ B,
    const __nv_bfloat16* __restrict__ U,
    __nv_bfloat16* __restrict__ Cn, __nv_bfloat16* __restrict__ Ct,
    float* __restrict__ Cf, float c1, float c2)
{
    extern __shared__ __nv_bfloat16 smh[];
    const uint32_t sbase = (uint32_t)__cvta_generic_to_shared(smh);
    const uint32_t bbase = sbase + 3*HSTG*2;
    const int tid = threadIdx.x;
    const int wid = tid >> 5, lane = tid & 31;
    const int wm = wid >> 2, wn = wid & 3;
    const int gr = lane >> 2, gc = lane & 3;
    const int mtx = lane >> 3, mrow = lane & 7;
    const uint32_t a_lm = ((uint32_t)(((mtx&1)*8 + mrow)) * KPH + (uint32_t)((mtx>>1)*8)) * 2;
    const uint32_t b_lm = ((uint32_t)(((mtx>>1)*8 + mrow)) * KPH + (uint32_t)((mtx&1)*8)) * 2;

    const int tile = blockIdx.x;
    const int batch = tile >> 2;
    const int m0 = ((tile >> 1) & 1) << 7;
    const int n0 = (tile & 1) << 7;
    const size_t boff = (size_t)batch << 16;
    A += boff + (size_t)m0 * ML;
    B += boff + (size_t)n0 * ML;
    if (U)  U  += boff;
    if (Cn) Cn += boff;
    if (Ct) Ct += boff;
    if (Cf) Cf += boff;

    int crow[2], cseg[2];
    #pragma unroll
    for (int e = 0; e < 2; e++) {
        int f = e * 256 + tid;
        crow[e] = f >> 2;
        cseg[e] = (f & 3) * 8;
    }

    float acc[4][4][4];
    #pragma unroll
    for (int mi = 0; mi < 4; mi++)
        #pragma unroll
        for (int ni = 0; ni < 4; ni++)
            #pragma unroll
            for (int e = 0; e < 4; e++) acc[mi][ni][e] = 0.f;

    #pragma unroll
    for (int p = 0; p < 2; p++) {
        const int k0 = p * 32;
        #pragma unroll
        for (int e = 0; e < 2; e++) {
            cp16(sbase + (uint32_t)(p*HSTG + crow[e]*KPH + cseg[e])*2,
                 &A[(size_t)crow[e] * ML + k0 + cseg[e]]);
            cp16(bbase + (uint32_t)(p*HSTG + crow[e]*KPH + cseg[e])*2,
                 &B[(size_t)crow[e] * ML + k0 + cseg[e]]);
        }
        CP_COMMIT();
    }
    for (int c = 0; c < 8; c++) {
        const int st = c % 3;
        if (c + 1 < 8) { CP_WAIT1(); } else { CP_WAIT0(); }
        __syncthreads();
        if (c + 2 < 8) {
            const int nst = (c + 2) % 3;
            const int k0 = (c + 2) * 32;
            #pragma unroll
            for (int e = 0; e < 2; e++) {
                cp16(sbase + (uint32_t)(nst*HSTG + crow[e]*KPH + cseg[e])*2,
                     &A[(size_t)crow[e] * ML + k0 + cseg[e]]);
                cp16(bbase + (uint32_t)(nst*HSTG + crow[e]*KPH + cseg[e])*2,
                     &B[(size_t)crow[e] * ML + k0 + cseg[e]]);
            }
            CP_COMMIT();
        }
        const uint32_t a_st = sbase + (uint32_t)(st*HSTG)*2 + a_lm;
        const uint32_t b_st = bbase + (uint32_t)(st*HSTG)*2 + b_lm;
        #pragma unroll
        for (int ks = 0; ks < 2; ks++) {
            uint32_t af[4][4];
            #pragma unroll
            for (int mi = 0; mi < 4; mi++)
                ldsm_x4(af[mi][0], af[mi][1], af[mi][2], af[mi][3],
                        a_st + (uint32_t)((wm*64 + mi*16)*KPH + ks*16)*2);
            uint32_t bf[4][2];
            #pragma unroll
            for (int p = 0; p < 2; p++)
                ldsm_x4(bf[2*p][0], bf[2*p][1], bf[2*p+1][0], bf[2*p+1][1],
                        b_st + (uint32_t)((wn*32 + p*16)*KPH + ks*16)*2);
            #pragma unroll
            for (int mi = 0; mi < 4; mi++)
                #pragma unroll
                for (int ni = 0; ni < 4; ni++)
                    mma_bf16_16x8x16(acc[mi][ni],
                        af[mi][0], af[mi][1], af[mi][2], af[mi][3],
                        bf[ni][0], bf[ni][1]);
        }
    }

    #pragma unroll
    for (int mi = 0; mi < 4; mi++) {
        #pragma unroll
        for (int ni = 0; ni < 4; ni++) {
            int grow = m0 + wm*64 + mi*16 + gr;
            int gcol = n0 + wn*32 + ni*8 + gc*2;
            const float* a = acc[mi][ni];
            float d0, d1, d2, d3;
            if (U) {
                __nv_bfloat162 u0 = *reinterpret_cast<const __nv_bfloat162*>(&U[(size_t)grow * ML + gcol]);
                __nv_bfloat162 u1 = *reinterpret_cast<const __nv_bfloat162*>(&U[(size_t)(grow+8) * ML + gcol]);
                d0 = c1*__bfloat162float(u0.x) + c2*a[0];
                d1 = c1*__bfloat162float(u0.y) + c2*a[1];
                d2 = c1*__bfloat162float(u1.x) + c2*a[2];
                d3 = c1*__bfloat162float(u1.y) + c2*a[3];
            } else {
                d0 = c2*a[0]; d1 = c2*a[1]; d2 = c2*a[2]; d3 = c2*a[3];
            }
            __nv_bfloat16 h0 = __float2bfloat16(d0), h1 = __float2bfloat16(d1);
            __nv_bfloat16 h2 = __float2bfloat16(d2), h3 = __float2bfloat16(d3);
            if (Cn) {
                __nv_bfloat162 p0; p0.x = h0; p0.y = h1;
                __nv_bfloat162 p1; p1.x = h2; p1.y = h3;
                *reinterpret_cast<__nv_bfloat162*>(&Cn[(size_t)grow * ML + gcol]) = p0;
                *reinterpret_cast<__nv_bfloat162*>(&Cn[(size_t)(grow+8) * ML + gcol]) = p1;
            }
            if (Ct) {
                Ct[(size_t)gcol * ML + grow]       = h0;
                Ct[(size_t)(gcol+1) * ML + grow]   = h1;
                Ct[(size_t)gcol * ML + grow+8]     = h2;
                Ct[(size_t)(gcol+1) * ML + grow+8] = h3;
            }
            if (Cf) {
                *reinterpret_cast<float2*>(&Cf[(size_t)grow * ML + gcol]) =
                    make_float2(cvt_tf32(d0), cvt_tf32(d1));
                *reinterpret_cast<float2*>(&Cf[(size_t)(grow+8) * ML + gcol]) =
                    make_float2(cvt_tf32(d2), cvt_tf32(d3));
            }
        }
    }
}

// ============ plain batched GEMM: C[z] = A[z] @ B[z]^T (B K-major; sims) ============
__global__ void __launch_bounds__(256, 2) gemm_tc_kernel(
    const float* __restrict__ A, const float* __restrict__ B, float* __restrict__ C,
    int lda, int ldb, int ldc, int kch,
    size_t sA, size_t sB, size_t sC)
{
    extern __shared__ float sm[];
    const int tid = threadIdx.x;
    const int z = blockIdx.z;
    const int m0 = blockIdx.y * 128, n0 = blockIdx.x * 128;
    A += (size_t)z * sA + (size_t)m0 * lda;
    B += (size_t)z * sB + (size_t)n0 * ldb;
    C += (size_t)z * sC;
    float acc[4][4][4];
    #pragma unroll
    for (int mi = 0; mi < 4; mi++)
        #pragma unroll
        for (int ni = 0; ni < 4; ni++)
            #pragma unroll
            for (int e = 0; e < 4; e++) acc[mi][ni][e] = 0.f;
    mainloop128x128(A, B, lda, ldb, kch, sm, tid, acc);
    const int wid = tid >> 5, lane = tid & 31;
    const int gr = lane >> 2, gc = lane & 3;
    const int wm = wid >> 2, wn = wid & 3;
    #pragma unroll
    for (int mi = 0; mi < 4; mi++) {
        #pragma unroll
        for (int ni = 0; ni < 4; ni++) {
            int lr = m0 + wm*64 + mi*16 + gr;
            int lc = n0 + wn*32 + ni*8 + gc*2;
            const float* a = acc[mi][ni];
            *reinterpret_cast<float2*>(&C[(size_t)lr * ldc + lc]) = make_float2(a[0], a[1]);
            *reinterpret_cast<float2*>(&C[(size_t)(lr+8) * ldc + lc]) = make_float2(a[2], a[3]);
        }
    }
}

// ============ QKV^T GEMM: qkvT[n][i] = wqkvT[n][c] @ x[b][c][i] ============
__global__ void __launch_bounds__(256, 2) qkvT_tc_kernel(const float* __restrict__ x) {
    extern __shared__ float sm[];
    const int tid = threadIdx.x;
    const int m0 = blockIdx.y * 128;        // over 1536 qkv dims
    const int n0 = blockIdx.x * 128;        // over 1024 tokens
    const int b  = blockIdx.z;
    const float* A = g_wqkvT + (size_t)m0 * CDIM;
    const float* B = x + (size_t)b * CDIM * NTOK + n0;
    float acc[4][4][4];
    #pragma unroll
    for (int mi = 0; mi < 4; mi++)
        #pragma unroll
        for (int ni = 0; ni < 4; ni++)
            #pragma unroll
            for (int e = 0; e < 4; e++) acc[mi][ni][e] = 0.f;
    mainloop128x128_rowB(A, B, CDIM, NTOK, CDIM/32, sm, tid, acc);
    const int wid = tid >> 5, lane = tid & 31;
    const int gr = lane >> 2, gc = lane & 3;
    const int wm = wid >> 2, wn = wid & 3;
    #pragma unroll
    for (int mi = 0; mi < 4; mi++) {
        int m = m0 + wm*64 + mi*16 + gr;
        int which = m >> 9;
        int h = (m >> 6) & 7;
        int d = m & 63;
        int bh = b*8 + h;
        float* dst = (which == 0) ? g_q : ((which == 1) ? g_k : g_v);
        float sc = (which == 0) ? 0.125f : 1.0f;
        #pragma unroll
        for (int ni = 0; ni < 4; ni++) {
            int i = n0 + wn*32 + ni*8 + gc*2;
            const float* a = acc[mi][ni];
            dst[((size_t)(bh*NTOK + i))*DH + d]       = cvt_tf32(a[0]*sc);
            dst[((size_t)(bh*NTOK + i + 1))*DH + d]   = cvt_tf32(a[1]*sc);
            dst[((size_t)(bh*NTOK + i))*DH + d + 8]   = cvt_tf32(a[2]*sc);
            dst[((size_t)(bh*NTOK + i + 1))*DH + d + 8] = cvt_tf32(a[3]*sc);
        }
    }
}

// ============ final GEMM: out = outf @ woutT^T + bias, transposed store (fp32) ============
__global__ void __launch_bounds__(256, 2) final_tc_kernel(
    const float* __restrict__ bias, float* __restrict__ out)
{
    extern __shared__ float sm[];
    const int tid = threadIdx.x;
    const int m0 = blockIdx.y * 128;
    const int n0 = blockIdx.x * 128;
    const float* A = g_outf + (size_t)m0 * CDIM;
    const float* B = g_woutT + (size_t)n0 * CDIM;
    float acc[4][4][4];
    #pragma unroll
    for (int mi = 0; mi < 4; mi++)
        #pragma unroll
        for (int ni = 0; ni < 4; ni++)
            #pragma unroll
            for (int e = 0; e < 4; e++) acc[mi][ni][e] = 0.f;
    mainloop128x128(A, B, CDIM, CDIM, CDIM/32, sm, tid, acc);
    const int wid = tid >> 5, lane = tid & 31;
    const int gr = lane >> 2, gc = lane & 3;
    const int wm = wid >> 2, wn = wid & 3;
    #pragma unroll
    for (int mi = 0; mi < 4; mi++) {
        int m = m0 + wm*64 + mi*16 + gr;
        int b = m >> 10, i = m & 1023;
        #pragma unroll
        for (int ni = 0; ni < 4; ni++) {
            int n = n0 + wn*32 + ni*8 + gc*2;
            const float* a = acc[mi][ni];
            float b0 = bias[n], b1 = bias[n+1];
            out[((size_t)(b*CDIM + n))*NTOK + i]       = a[0] + b0;
            out[((size_t)(b*CDIM + n + 1))*NTOK + i]   = a[1] + b1;
            out[((size_t)(b*CDIM + n))*NTOK + i + 8]   = a[2] + b0;
            out[((size_t)(b*CDIM + n + 1))*NTOK + i + 8] = a[3] + b1;
        }
    }
}

// ============ 128x64 batched GEMM, B row-major [K,64]: C = A @ B ============
__global__ void __launch_bounds__(256, 2) gemm64_rowB_kernel(
    const float* __restrict__ A, const float* __restrict__ B, float* __restrict__ C,
    int lda, int kch, size_t sA, size_t sB, int flatC)
{
    extern __shared__ float sm[];
    const uint32_t sbase = (uint32_t)__cvta_generic_to_shared(sm);
    const uint32_t bbase = sbase + 3*PSTAGE*4;
    const int tid = threadIdx.x;
    const int wid = tid >> 5, lane = tid & 31;
    const int gr = lane >> 2, gc = lane & 3;
    const int wm = wid >> 1, wn = wid & 1;
    const int g = lane >> 3, r8 = lane & 7;
    const uint32_t a_lm = (uint32_t)((wm*32 + (g&1)*8 + r8)*PPITCH + (g>>1)*4)*4;
    const int z = blockIdx.z;
    const int m0 = blockIdx.x * 128;
    A += (size_t)z * sA + (size_t)m0 * lda;
    B += (size_t)z * sB;
    if (flatC) C += (size_t)(z >> 3) * (NTOK*CDIM) + (size_t)(z & 7) * DH;
    else       C += (size_t)z * (ML*DH);

    int arow[4], ac4[4], bk[2], bn4[2];
    #pragma unroll
    for (int e = 0; e < 4; e++) {
        int f4 = e * 256 + tid;
        arow[e] = f4 >> 3;  ac4[e] = (f4 & 7) << 2;
    }
    #pragma unroll
    for (int e = 0; e < 2; e++) {
        int f4 = e * 256 + tid;
        bk[e] = f4 >> 4;  bn4[e] = (f4 & 15) << 2;
    }

    float acc[2][4][4];
    #pragma unroll
    for (int mi = 0; mi < 2; mi++)
        #pragma unroll
        for (int ni = 0; ni < 4; ni++)
            #pragma unroll
            for (int e = 0; e < 4; e++) acc[mi][ni][e] = 0.f;

    #pragma unroll
    for (int p = 0; p < 2; p++) {
        if (p < kch) {
            const int k0 = p * 32;
            #pragma unroll
            for (int e = 0; e < 4; e++)
                cp16(sbase + (uint32_t)(p*PSTAGE + arow[e]*PPITCH + ac4[e])*4,
                     &A[(size_t)arow[e] * lda + k0 + ac4[e]]);
            #pragma unroll
            for (int e = 0; e < 2; e++)
                cp16(bbase + (uint32_t)(p*BRSTG64 + bk[e]*BNP64 + bn4[e])*4,
                     &B[(size_t)(k0 + bk[e]) * DH + bn4[e]]);
        }
        CP_COMMIT();
    }

    for (int c = 0; c < kch; c++) {
        const int st = c % 3;
        if (c + 1 < kch) { CP_WAIT1(); } else { CP_WAIT0(); }
        __syncthreads();
        if (c + 2 < kch) {
            const int nst = (c + 2) % 3;
            const int k0 = (c + 2) * 32;
            #pragma unroll
            for (int e = 0; e < 4; e++)
                cp16(sbase + (uint32_t)(nst*PSTAGE + arow[e]*PPITCH + ac4[e])*4,
                     &A[(size_t)arow[e] * lda + k0 + ac4[e]]);
            #pragma unroll
            for (int e = 0; e < 2; e++)
                cp16(bbase + (uint32_t)(nst*BRSTG64 + bk[e]*BNP64 + bn4[e])*4,
                     &B[(size_t)(k0 + bk[e]) * DH + bn4[e]]);
            CP_COMMIT();
        }
        const uint32_t a_st = sbase + (uint32_t)(st*PSTAGE)*4 + a_lm;
        const float* Bb = sm + 3*PSTAGE + st*BRSTG64;
        #pragma unroll
        for (int ks = 0; ks < 4; ks++) {
            uint32_t af[2][4];
            #pragma unroll
            for (int mi = 0; mi < 2; mi++)
                ldsm_x4(af[mi][0], af[mi][1], af[mi][2], af[mi][3],
                        a_st + (uint32_t)(mi*16*PPITCH + ks*8)*4);
            uint32_t bf[4][2];
            #pragma unroll
            for (int ni = 0; ni < 4; ni++) {
                int n = wn*32 + ni*8 + gr;
                bf[ni][0] = __float_as_uint(Bb[(ks*8 + gc)*BNP64 + n]);
                bf[ni][1] = __float_as_uint(Bb[(ks*8 + gc + 4)*BNP64 + n]);
            }
            #pragma unroll
            for (int mi = 0; mi < 2; mi++)
                #pragma unroll
                for (int ni = 0; ni < 4; ni++)
                    mma_tf32_16x8x8(acc[mi][ni],
                        af[mi][0], af[mi][1], af[mi][2], af[mi][3],
                        bf[ni][0], bf[ni][1]);
        }
    }

    #pragma unroll
    for (int mi = 0; mi < 2; mi++) {
        #pragma unroll
        for (int ni = 0; ni < 4; ni++) {
            int lr = m0 + wm*32 + mi*16 + gr;
            int lc = wn*32 + ni*8 + gc*2;
            const float* a = acc[mi][ni];
            float d0 = cvt_tf32(a[0]), d1 = cvt_tf32(a[1]);
            float d2 = cvt_tf32(a[2]), d3 = cvt_tf32(a[3]);
            int ldc = flatC ? CDIM : DH;
            *reinterpret_cast<float2*>(&C[(size_t)lr * ldc + lc]) = make_float2(d0, d1);
            *reinterpret_cast<float2*>(&C[(size_t)(lr+8) * ldc + lc]) = make_float2(d2, d3);
        }
    }
}

// ---------------- batched 2D transpose (tf32-rounded output) ----------------
__global__ void transpose_kernel(const float* __restrict__ in, float* __restrict__ out,
                                 int R, int C) {
    __shared__ float tile[32][33];
    const int z = blockIdx.z;
    in  += (size_t)z * R * C;
    out += (size_t)z * R * C;
    int c0 = blockIdx.x * 32, r0 = blockIdx.y * 32;
    int tx = threadIdx.x, ty = threadIdx.y;
    #pragma unroll
    for (int j = 0; j < 4; j++)
        tile[ty + j*8][tx] = in[(size_t)(r0 + ty + j*8) * C + c0 + tx];
    __syncthreads();
    #pragma unroll
    for (int j = 0; j < 4; j++)
        out[(size_t)(c0 + ty + j*8) * R + r0 + tx] = cvt_tf32(tile[tx][ty + j*8]);
}

// ---------------- landmark means (tf32-rounded) ----------------
__global__ void land_kernel() {
    int idx = blockIdx.x * blockDim.x + threadIdx.x;
    if (idx >= BHN*ML*DH) return;
    int d  = idx & 63;
    int j  = (idx >> 6) & 255;
    int bh = idx >> 14;
    size_t base = ((size_t)bh * NTOK + j*4) * DH + d;
    g_ql[idx] = cvt_tf32(0.25f * (g_q[base] + g_q[base+64] + g_q[base+128] + g_q[base+192]));
    g_kl[idx] = cvt_tf32(0.25f * (g_k[base] + g_k[base+64] + g_k[base+128] + g_k[base+192]));
}

// ---------------- warp-per-row softmax: fast exp, zero block barriers ----------------
template<int W>
__global__ void softmax_warp_kernel(float* __restrict__ data) {
    const int lane = threadIdx.x & 31;
    const int row = blockIdx.x * 8 + (threadIdx.x >> 5);
    float* r = data + (size_t)row * W;
    constexpr int PE = W / 32;
    float v[PE];
    float mx = -1e30f;
    #pragma unroll
    for (int e = 0; e < PE; e++) { v[e] = r[lane + e*32]; mx = fmaxf(mx, v[e]); }
    #pragma unroll
    for (int o = 16; o > 0; o >>= 1) mx = fmaxf(mx, __shfl_xor_sync(0xffffffffu, mx, o));
    float s = 0.f;
    #pragma unroll
    for (int e = 0; e < PE; e++) { v[e] = __expf(v[e] - mx); s += v[e]; }
    #pragma unroll
    for (int o = 16; o > 0; o >>= 1) s += __shfl_xor_sync(0xffffffffu, s, o);
    float inv = 1.0f / s;
    #pragma unroll
    for (int e = 0; e < PE; e++) r[lane + e*32] = cvt_tf32(v[e] * inv);
}

// ---------------- pinv scale reductions ----------------
__global__ void reset_max_kernel() { if (threadIdx.x == 0) { g_colmax = 0u; g_rowmax = 0u; } }

__global__ void colmax_kernel() {
    int gw = (blockIdx.x * blockDim.x + threadIdx.x) >> 5;
    int lane = threadIdx.x & 31;
    if (gw >= BHN * ML) return;
    const float* row = g_attn2 + (size_t)gw * ML;
    float s = 0.f;
    #pragma unroll
    for (int j = lane; j < ML; j += 32) s += fabsf(row[j]);
    #pragma unroll
    for (int o = 16; o > 0; o >>= 1) s += __shfl_down_sync(0xffffffffu, s, o);
    if (lane == 0) atomicMax(&g_colmax, __float_as_uint(s));
}

__global__ void rowmax_kernel() {
    int idx = blockIdx.x * blockDim.x + threadIdx.x;
    if (idx >= BHN * ML) return;
    int bh = idx >> 8, j = idx & 255;
    const float* base = g_attn2 + (size_t)bh * ML * ML + j;
    float s = 0.f;
    for (int i = 0; i < ML; i++) s += fabsf(base[(size_t)i * ML]);
    atomicMax(&g_rowmax, __float_as_uint(s));
}

// zinit: z0 (bf16, row + transposed) and a2h (bf16 of a2)
__global__ void zinit_kernel() {
    float inv = 1.0f / (__uint_as_float(g_colmax) * __uint_as_float(g_rowmax));
    size_t idx = (size_t)blockIdx.x * 256 + threadIdx.x;
    int j  = idx & 255;
    int i  = (idx >> 8) & 255;
    size_t bh = idx >> 16;
    float a2v  = g_attn2[idx];
    float a2tv = g_attn2[(bh << 16) + ((size_t)j << 8) + i];
    g_zhA[idx]  = __float2bfloat16(a2tv * inv);   // z0 row-major = scaled x^T
    g_zhTA[idx] = __float2bfloat16(a2v * inv);    // z0^T = scaled x
    g_a2h[idx]  = __float2bfloat16(a2v);
}

// ---------------- depthwise 33-tap conv residual (tf32-rounded add) ----------------
__global__ void res_add_kernel(const float* __restrict__ rk) {
    __shared__ float ker[KSZ];
    int blk = blockIdx.x;
    int bh = blk >> 8;
    int ichunk = blk & 255;
    int h = bh & 7, b = bh >> 3;
    if (threadIdx.x < KSZ) ker[threadIdx.x] = rk[h*KSZ + threadIdx.x];
    __syncthreads();
    int d = threadIdx.x & 63;
    int i = ichunk * 4 + (threadIdx.x >> 6);
    const float* vb = g_v + (size_t)bh * NTOK * DH;
    float s = 0.f;
    #pragma unroll
    for (int t = 0; t < KSZ; t++) {
        int ii = i + t - (KSZ/2);
        if (ii >= 0 && ii < NTOK) s += ker[t] * vb[(size_t)ii * DH + d];
    }
    size_t o = ((size_t)(b*NTOK + i)) * CDIM + h*64 + d;
    g_outf[o] = cvt_tf32(g_outf[o] + s);
}

// ---------------- host ----------------
extern "C" void kernel_launch(void* const* d_in, const int* in_sizes, int n_in,
                              void* d_out, int out_size) {
    const float* x     = (const float*)d_in[0];
    const float* w_qkv = (const float*)d_in[1];
    const float* w_out = (const float*)d_in[2];
    const float* b_out = (const float*)d_in[3];
    const float* rk    = (const float*)d_in[4];
    float* out = (float*)d_out;

    float *wqkvT, *woutT, *q, *k, *v, *ql, *kl, *a1, *a3, *a2;
    float *zA, *av, *bv, *outf;
    __nv_bfloat16 *a2h, *zhA, *zhB, *zhTA, *zhTB, *xzh, *xzhT, *t1hT, *t2hT;
    cudaGetSymbolAddress((void**)&wqkvT, g_wqkvT);
    cudaGetSymbolAddress((void**)&woutT, g_woutT);
    cudaGetSymbolAddress((void**)&q,  g_q);
    cudaGetSymbolAddress((void**)&k,  g_k);
    cudaGetSymbolAddress((void**)&v,  g_v);
    cudaGetSymbolAddress((void**)&ql, g_ql);
    cudaGetSymbolAddress((void**)&kl, g_kl);
    cudaGetSymbolAddress((void**)&a1, g_attn1);
    cudaGetSymbolAddress((void**)&a3, g_attn3);
    cudaGetSymbolAddress((void**)&a2, g_attn2);
    cudaGetSymbolAddress((void**)&zA, g_zA);
    cudaGetSymbolAddress((void**)&av, g_av);
    cudaGetSymbolAddress((void**)&bv, g_bv);
    cudaGetSymbolAddress((void**)&outf, g_outf);
    cudaGetSymbolAddress((void**)&a2h,  g_a2h);
    cudaGetSymbolAddress((void**)&zhA,  g_zhA);
    cudaGetSymbolAddress((void**)&zhB,  g_zhB);
    cudaGetSymbolAddress((void**)&zhTA, g_zhTA);
    cudaGetSymbolAddress((void**)&zhTB, g_zhTB);
    cudaGetSymbolAddress((void**)&xzh,  g_xzh);
    cudaGetSymbolAddress((void**)&xzhT, g_xzhT);
    cudaGetSymbolAddress((void**)&t1hT, g_t1hT);
    cudaGetSymbolAddress((void**)&t2hT, g_t2hT);

    cudaFuncSetAttribute(pinv_bf16_kernel,   cudaFuncAttributeMaxDynamicSharedMemorySize, BH_SMEM3);
    cudaFuncSetAttribute(gemm_tc_kernel,     cudaFuncAttributeMaxDynamicSharedMemorySize, G128_SMEM3);
    cudaFuncSetAttribute(qkvT_tc_kernel,     cudaFuncAttributeMaxDynamicSharedMemorySize, PB_SMEM3);
    cudaFuncSetAttribute(final_tc_kernel,    cudaFuncAttributeMaxDynamicSharedMemorySize, G128_SMEM3);
    cudaFuncSetAttribute(gemm64_rowB_kernel, cudaFuncAttributeMaxDynamicSharedMemorySize, G64R_SMEM3);

    // stream forks for concurrent pipelines (created/destroyed per call: no statics,
    // no retained device resources at the harness mem checkpoints)
    cudaStream_t s1, s2;
    cudaStreamCreateWithFlags(&s1, cudaStreamNonBlocking);
    cudaStreamCreateWithFlags(&s2, cudaStreamNonBlocking);
    cudaEvent_t evL, ev1, ev2;
    cudaEventCreateWithFlags(&evL, cudaEventDisableTiming);
    cudaEventCreateWithFlags(&ev1, cudaEventDisableTiming);
    cudaEventCreateWithFlags(&ev2, cudaEventDisableTiming);

    // 0) layout prep (weights only)
    transpose_kernel<<<dim3(48, 16, 1), dim3(32,8)>>>(w_qkv, wqkvT, CDIM, 3*CDIM);
    transpose_kernel<<<dim3(16, 16, 1), dim3(32,8)>>>(w_out, woutT, CDIM, CDIM);
    // 1) QKV projection (transposed form, x in natural layout)
    qkvT_tc_kernel<<<dim3(8, 12, BATCH), 256, PB_SMEM3>>>(x);
    // 2) landmarks
    land_kernel<<<(BHN*ML*DH + 255)/256, 256>>>();
    cudaEventRecord(evL, 0);

    // ---- branch s1: sim1 + softmax a1 (consumed by outf GEMM much later) ----
    cudaStreamWaitEvent(s1, evL, 0);
    gemm_tc_kernel<<<dim3(2, 8, BHN), 256, G128_SMEM3, s1>>>(q,  kl, a1, DH, DH, ML, 2,
        (size_t)NTOK*DH, (size_t)ML*DH, (size_t)NTOK*ML);
    softmax_warp_kernel<256> <<<BHN*NTOK/8, 256, 0, s1>>>(a1);
    cudaEventRecord(ev1, s1);

    // ---- branch s2: sim3 + softmax a3 + av = attn3@v ----
    cudaStreamWaitEvent(s2, evL, 0);
    gemm_tc_kernel<<<dim3(8, 2, BHN), 256, G128_SMEM3, s2>>>(ql, k, a3, DH, DH, NTOK, 2,
        (size_t)ML*DH, (size_t)NTOK*DH, (size_t)ML*NTOK);
    softmax_warp_kernel<1024><<<BHN*ML/8, 256, 0, s2>>>(a3);
    gemm64_rowB_kernel<<<dim3(2, 1, BHN), 256, G64R_SMEM3, s2>>>(a3, v, av,
        NTOK, 32, (size_t)ML*NTOK, (size_t)NTOK*DH, 0);
    cudaEventRecord(ev2, s2);

    // ---- main stream: a2 path + pinv chain (runs concurrent with s1/s2) ----
    gemm_tc_kernel<<<dim3(2, 2, BHN), 256, G128_SMEM3>>>(ql, kl, a2, DH, DH, ML, 2,
        (size_t)ML*DH, (size_t)ML*DH, (size_t)ML*ML);
    softmax_warp_kernel<256> <<<BHN*ML/8, 256>>>(a2);
    reset_max_kernel<<<1, 32>>>();
    colmax_kernel<<<(BHN*ML*32)/256, 256>>>();
    rowmax_kernel<<<(BHN*ML)/256, 256>>>();
    zinit_kernel<<<(BHN*ML*ML)/256, 256>>>();
    // Newton–Schulz: all 6 iterations in bf16; final update emits fp32 z (Cf path)
    __nv_bfloat16 *zh_in = zhA, *zh_out = zhB, *zhT_in = zhTA, *zhT_out = zhTB;
    for (int it = 0; it < 6; it++) {
        pinv_bf16_kernel<<<1024, 256, BH_SMEM3>>>(a2h, zhT_in, nullptr, xzh, xzhT, nullptr, 0.0f, 1.0f);
        pinv_bf16_kernel<<<1024, 256, BH_SMEM3>>>(xzh, xzhT, xzh, nullptr, t1hT, nullptr, 7.0f, -1.0f);
        pinv_bf16_kernel<<<1024, 256, BH_SMEM3>>>(xzh, t1hT, xzh, nullptr, t2hT, nullptr, 15.0f, -1.0f);
        if (it < 5) {
            pinv_bf16_kernel<<<1024, 256, BH_SMEM3>>>(zh_in, t2hT, zh_in, zh_out, zhT_out, nullptr, 3.25f, -0.25f);
            __nv_bfloat16* tmp;
            tmp = zh_in;  zh_in  = zh_out;  zh_out  = tmp;
            tmp = zhT_in; zhT_in = zhT_out; zhT_out = tmp;
        } else {
            pinv_bf16_kernel<<<1024, 256, BH_SMEM3>>>(zh_in, t2hT, zh_in, nullptr, nullptr, zA, 3.25f, -0.25f);
        }
    }
    float* zfin = zA;

    // joins: bv needs av (s2); outf needs a1 (s1)
    cudaStreamWaitEvent(0, ev2, 0);
    gemm64_rowB_kernel<<<dim3(2, 1, BHN), 256, G64R_SMEM3>>>(zfin, av, bv,
        ML, 8, (size_t)ML*ML, (size_t)ML*DH, 0);
    cudaStreamWaitEvent(0, ev1, 0);
    gemm64_rowB_kernel<<<dim3(8, 1, BHN), 256, G64R_SMEM3>>>(a1, bv, outf,
        ML, 8, (size_t)NTOK*ML, (size_t)ML*DH, 1);
    // depthwise conv residual + output projection
    res_add_kernel<<<BHN*256, 256>>>(rk);
    final_tc_kernel<<<dim3(4, 256), 256, G128_SMEM3>>>(b_out, out);

    cudaEventDestroy(evL);
    cudaEventDestroy(ev1);
    cudaEventDestroy(ev2);
    cudaStreamDestroy(s1);
    cudaStreamDestroy(s2);
}

// round 17
// speedup vs baseline: 1.1357x; 1.0680x over previous
#include <cuda_runtime.h>
#include <cuda_bf16.h>
#include <cstdint>
#include <cstddef>

#define BATCH 32
#define HEADS 8
#define NTOK 1024
#define DH 64
#define ML 256          // landmarks
#define CDIM 512
#define BHN (BATCH*HEADS)   // 256
#define KSZ 33

// ---------------- device scratch ----------------
__device__ float g_wqkvT[3*CDIM*CDIM];              // (1536, 512), tf32-rounded
__device__ float g_woutT[CDIM*CDIM];                // (512, 512), tf32-rounded
__device__ float g_q [BHN*NTOK*DH];
__device__ float g_k [BHN*NTOK*DH];
__device__ float g_v [BHN*NTOK*DH];
__device__ float g_ql[BHN*ML*DH];
__device__ float g_kl[BHN*ML*DH];
__device__ float g_attn1[(size_t)BHN*NTOK*ML];      // (bh,1024,256)
__device__ float g_attn3[(size_t)BHN*ML*NTOK];      // (bh,256,1024)
__device__ float g_attn2[BHN*ML*ML];
__device__ float g_zA[BHN*ML*ML];                   // final z (fp32)
__device__ float g_av[BHN*ML*DH];
__device__ float g_bv[BHN*ML*DH];
__device__ float g_outf[(size_t)BATCH*NTOK*CDIM];   // (b, n, 512)
__device__ unsigned g_colmax;
__device__ unsigned g_rowmax;
// bf16 pinv buffers
__device__ __nv_bfloat16 g_a2h [BHN*ML*ML];   // bf16(a2), row-major [M][K]
__device__ __nv_bfloat16 g_zhA [BHN*ML*ML];   // z row-major
__device__ __nv_bfloat16 g_zhB [BHN*ML*ML];
__device__ __nv_bfloat16 g_zhTA[BHN*ML*ML];   // z^T (K-major for B operand)
__device__ __nv_bfloat16 g_zhTB[BHN*ML*ML];
__device__ __nv_bfloat16 g_xzh [BHN*ML*ML];
__device__ __nv_bfloat16 g_xzhT[BHN*ML*ML];
__device__ __nv_bfloat16 g_t1hT[BHN*ML*ML];
__device__ __nv_bfloat16 g_t2hT[BHN*ML*ML];

// ================= helpers =================
__device__ __forceinline__ float cvt_tf32(float x) {
    uint32_t u;
    asm("cvt.rna.tf32.f32 %0, %1;" : "=r"(u) : "f"(x));
    return __uint_as_float(u);
}
__device__ __forceinline__ void mma_tf32_16x8x8(float c[4],
    uint32_t a0, uint32_t a1, uint32_t a2, uint32_t a3, uint32_t b0, uint32_t b1) {
    asm volatile(
        "mma.sync.aligned.m16n8k8.row.col.f32.tf32.tf32.f32 "
        "{%0,%1,%2,%3},{%4,%5,%6,%7},{%8,%9},{%0,%1,%2,%3};"
        : "+f"(c[0]), "+f"(c[1]), "+f"(c[2]), "+f"(c[3])
        : "r"(a0), "r"(a1), "r"(a2), "r"(a3), "r"(b0), "r"(b1));
}
__device__ __forceinline__ void mma_bf16_16x8x16(float c[4],
    uint32_t a0, uint32_t a1, uint32_t a2, uint32_t a3, uint32_t b0, uint32_t b1) {
    asm volatile(
        "mma.sync.aligned.m16n8k16.row.col.f32.bf16.bf16.f32 "
        "{%0,%1,%2,%3},{%4,%5,%6,%7},{%8,%9},{%0,%1,%2,%3};"
        : "+f"(c[0]), "+f"(c[1]), "+f"(c[2]), "+f"(c[3])
        : "r"(a0), "r"(a1), "r"(a2), "r"(a3), "r"(b0), "r"(b1));
}
__device__ __forceinline__ void ldsm_x4(uint32_t& r0, uint32_t& r1,
                                        uint32_t& r2, uint32_t& r3, uint32_t saddr) {
    asm volatile("ldmatrix.sync.aligned.m8n8.x4.shared.b16 {%0,%1,%2,%3}, [%4];"
                 : "=r"(r0), "=r"(r1), "=r"(r2), "=r"(r3) : "r"(saddr));
}
__device__ __forceinline__ void cp16(uint32_t dst, const void* src) {
    asm volatile("cp.async.cg.shared.global [%0], [%1], 16;" :: "r"(dst), "l"(src));
}
#define CP_COMMIT() asm volatile("cp.async.commit_group;")
#define CP_WAIT1()  asm volatile("cp.async.wait_group 1;" ::: "memory")
#define CP_WAIT0()  asm volatile("cp.async.wait_group 0;" ::: "memory")

#define PPITCH 36
#define PSTAGE (128*PPITCH)
#define G128_SMEM3 (6*PSTAGE*4)                     // 110592 (A,B both K-major fp32)

#define BNP128 136
#define BRSTG128 (32*BNP128)
#define PB_SMEM3 ((3*PSTAGE + 3*BRSTG128)*4)        // 107520

#define BNP64 72
#define BRSTG64 (32*BNP64)
#define G64R_SMEM3 ((3*PSTAGE + 3*BRSTG64)*4)       // 82944

// bf16 tiles: [128 rows][KPH halves] per chunk (32 halves data, pitch 40)
#define KPH 40
#define HSTG (128*KPH)                               // halves per stage
#define BH_SMEM3 (6*HSTG*2)                          // 61440 bytes

// ============ mainloop A: B stored K-major ([N rows][K]) — sims/final ============
__device__ __forceinline__ void mainloop128x128(
    const float* __restrict__ A, const float* __restrict__ B,
    int lda, int ldb, int kch, float* sm, int tid, float acc[4][4][4])
{
    const uint32_t sbase = (uint32_t)__cvta_generic_to_shared(sm);
    const uint32_t bbase = sbase + 3*PSTAGE*4;
    const int wid = tid >> 5, lane = tid & 31;
    const int wm = wid >> 2, wn = wid & 3;
    const int g = lane >> 3, r8 = lane & 7;
    const uint32_t a_lm = (uint32_t)((wm*64 + (g&1)*8 + r8)*PPITCH + (g>>1)*4)*4;
    const uint32_t b_lm = (uint32_t)((wn*32 + (g>>1)*8 + r8)*PPITCH + (g&1)*4)*4;
    int rrow[4], rc4[4];
    #pragma unroll
    for (int e = 0; e < 4; e++) {
        int f4 = e * 256 + tid;
        rrow[e] = f4 >> 3;
        rc4[e] = (f4 & 7) << 2;
    }
    #pragma unroll
    for (int p = 0; p < 2; p++) {
        if (p < kch) {
            const int k0 = p * 32;
            #pragma unroll
            for (int e = 0; e < 4; e++) {
                cp16(sbase + (uint32_t)(p*PSTAGE + rrow[e]*PPITCH + rc4[e])*4,
                     &A[(size_t)rrow[e] * lda + k0 + rc4[e]]);
                cp16(bbase + (uint32_t)(p*PSTAGE + rrow[e]*PPITCH + rc4[e])*4,
                     &B[(size_t)rrow[e] * ldb + k0 + rc4[e]]);
            }
        }
        CP_COMMIT();
    }
    for (int c = 0; c < kch; c++) {
        const int st = c % 3;
        if (c + 1 < kch) { CP_WAIT1(); } else { CP_WAIT0(); }
        __syncthreads();
        if (c + 2 < kch) {
            const int nst = (c + 2) % 3;
            const int k0 = (c + 2) * 32;
            #pragma unroll
            for (int e = 0; e < 4; e++) {
                cp16(sbase + (uint32_t)(nst*PSTAGE + rrow[e]*PPITCH + rc4[e])*4,
                     &A[(size_t)rrow[e] * lda + k0 + rc4[e]]);
                cp16(bbase + (uint32_t)(nst*PSTAGE + rrow[e]*PPITCH + rc4[e])*4,
                     &B[(size_t)rrow[e] * ldb + k0 + rc4[e]]);
            }
            CP_COMMIT();
        }
        const uint32_t a_st = sbase + (uint32_t)(st*PSTAGE)*4 + a_lm;
        const uint32_t b_st = bbase + (uint32_t)(st*PSTAGE)*4 + b_lm;
        #pragma unroll
        for (int ks = 0; ks < 4; ks++) {
            uint32_t af[4][4];
            #pragma unroll
            for (int mi = 0; mi < 4; mi++)
                ldsm_x4(af[mi][0], af[mi][1], af[mi][2], af[mi][3],
                        a_st + (uint32_t)(mi*16*PPITCH + ks*8)*4);
            uint32_t bf[4][2];
            #pragma unroll
            for (int p = 0; p < 2; p++)
                ldsm_x4(bf[2*p][0], bf[2*p][1], bf[2*p+1][0], bf[2*p+1][1],
                        b_st + (uint32_t)(p*16*PPITCH + ks*8)*4);
            #pragma unroll
            for (int mi = 0; mi < 4; mi++)
                #pragma unroll
                for (int ni = 0; ni < 4; ni++)
                    mma_tf32_16x8x8(acc[mi][ni],
                        af[mi][0], af[mi][1], af[mi][2], af[mi][3],
                        bf[ni][0], bf[ni][1]);
        }
    }
}

// ============ mainloop B: B stored row-major [K][N] — qkvT ============
__device__ __forceinline__ void mainloop128x128_rowB(
    const float* __restrict__ A, const float* __restrict__ B,
    int lda, int ldb, int kch, float* sm, int tid, float acc[4][4][4])
{
    const uint32_t sbase = (uint32_t)__cvta_generic_to_shared(sm);
    const uint32_t bbase = sbase + 3*PSTAGE*4;
    const int wid = tid >> 5, lane = tid & 31;
    const int gr = lane >> 2, gc = lane & 3;
    const int wm = wid >> 2, wn = wid & 3;
    const int g = lane >> 3, r8 = lane & 7;
    const uint32_t a_lm = (uint32_t)((wm*64 + (g&1)*8 + r8)*PPITCH + (g>>1)*4)*4;
    int arow[4], ac4[4], bk[4], bn4[4];
    #pragma unroll
    for (int e = 0; e < 4; e++) {
        int f4 = e * 256 + tid;
        arow[e] = f4 >> 3;  ac4[e] = (f4 & 7) << 2;
        bk[e]   = f4 >> 5;  bn4[e] = (f4 & 31) << 2;
    }
    #pragma unroll
    for (int p = 0; p < 2; p++) {
        if (p < kch) {
            const int k0 = p * 32;
            #pragma unroll
            for (int e = 0; e < 4; e++) {
                cp16(sbase + (uint32_t)(p*PSTAGE + arow[e]*PPITCH + ac4[e])*4,
                     &A[(size_t)arow[e] * lda + k0 + ac4[e]]);
                cp16(bbase + (uint32_t)(p*BRSTG128 + bk[e]*BNP128 + bn4[e])*4,
                     &B[(size_t)(k0 + bk[e]) * ldb + bn4[e]]);
            }
        }
        CP_COMMIT();
    }
    for (int c = 0; c < kch; c++) {
        const int st = c % 3;
        if (c + 1 < kch) { CP_WAIT1(); } else { CP_WAIT0(); }
        __syncthreads();
        if (c + 2 < kch) {
            const int nst = (c + 2) % 3;
            const int k0 = (c + 2) * 32;
            #pragma unroll
            for (int e = 0; e < 4; e++) {
                cp16(sbase + (uint32_t)(nst*PSTAGE + arow[e]*PPITCH + ac4[e])*4,
                     &A[(size_t)arow[e] * lda + k0 + ac4[e]]);
                cp16(bbase + (uint32_t)(nst*BRSTG128 + bk[e]*BNP128 + bn4[e])*4,
                     &B[(size_t)(k0 + bk[e]) * ldb + bn4[e]]);
            }
            CP_COMMIT();
        }
        const uint32_t a_st = sbase + (uint32_t)(st*PSTAGE)*4 + a_lm;
        const float* Bb = sm + 3*PSTAGE + st*BRSTG128;
        #pragma unroll
        for (int ks = 0; ks < 4; ks++) {
            uint32_t af[4][4];
            #pragma unroll
            for (int mi = 0; mi < 4; mi++)
                ldsm_x4(af[mi][0], af[mi][1], af[mi][2], af[mi][3],
                        a_st + (uint32_t)(mi*16*PPITCH + ks*8)*4);
            uint32_t bf[4][2];
            #pragma unroll
            for (int ni = 0; ni < 4; ni++) {
                int n = wn*32 + ni*8 + gr;
                bf[ni][0] = __float_as_uint(Bb[(ks*8 + gc)*BNP128 + n]);
                bf[ni][1] = __float_as_uint(Bb[(ks*8 + gc + 4)*BNP128 + n]);
            }
            #pragma unroll
            for (int mi = 0; mi < 4; mi++)
                #pragma unroll
                for (int ni = 0; ni < 4; ni++)
                    mma_tf32_16x8x8(acc[mi][ni],
                        af[mi][0], af[mi][1], af[mi][2], af[mi][3],
                        bf[ni][0], bf[ni][1]);
        }
    }
}

// ============ bf16 pinv batched GEMM: D = c1*U + c2*(A @ B^T), both K-major ============
// Outputs (each optional): Cn bf16 [M][N], Ct bf16 [N][M], Cf fp32 tf32-rounded [M][N].
__global__ void __launch_bounds__(256, 2) pinv_bf16_kernel(
    const __nv_bfloat16* __restrict__ A, const __nv_bfloat16* __restrict__ B,
    const __nv_bfloat16* __restrict__ U,
    __nv_bfloat16* __restrict__ Cn, __nv_bfloat16* __restrict__ Ct,
    float* __restrict__ Cf, float c1, float c2)
{
    extern __shared__ __nv_bfloat16 smh[];
    const uint32_t sbase = (uint32_t)__cvta_generic_to_shared(smh);
    const uint32_t bbase = sbase + 3*HSTG*2;
    const int tid = threadIdx.x;
    const int wid = tid >> 5, lane = tid & 31;
    const int wm = wid >> 2, wn = wid & 3;
    const int gr = lane >> 2, gc = lane & 3;
    const int mtx = lane >> 3, mrow = lane & 7;
    const uint32_t a_lm = ((uint32_t)(((mtx&1)*8 + mrow)) * KPH + (uint32_t)((mtx>>1)*8)) * 2;
    const uint32_t b_lm = ((uint32_t)(((mtx>>1)*8 + mrow)) * KPH + (uint32_t)((mtx&1)*8)) * 2;

    const int tile = blockIdx.x;
    const int batch = tile >> 2;
    const int m0 = ((tile >> 1) & 1) << 7;
    const int n0 = (tile & 1) << 7;
    const size_t boff = (size_t)batch << 16;
    A += boff + (size_t)m0 * ML;
    B += boff + (size_t)n0 * ML;
    if (U)  U  += boff;
    if (Cn) Cn += boff;
    if (Ct) Ct += boff;
    if (Cf) Cf += boff;

    int crow[2], cseg[2];
    #pragma unroll
    for (int e = 0; e < 2; e++) {
        int f = e * 256 + tid;
        crow[e] = f >> 2;
        cseg[e] = (f & 3) * 8;
    }

    float acc[4][4][4];
    #pragma unroll
    for (int mi = 0; mi < 4; mi++)
        #pragma unroll
        for (int ni = 0; ni < 4; ni++)
            #pragma unroll
            for (int e = 0; e < 4; e++) acc[mi][ni][e] = 0.f;

    #pragma unroll
    for (int p = 0; p < 2; p++) {
        const int k0 = p * 32;
        #pragma unroll
        for (int e = 0; e < 2; e++) {
            cp16(sbase + (uint32_t)(p*HSTG + crow[e]*KPH + cseg[e])*2,
                 &A[(size_t)crow[e] * ML + k0 + cseg[e]]);
            cp16(bbase + (uint32_t)(p*HSTG + crow[e]*KPH + cseg[e])*2,
                 &B[(size_t)crow[e] * ML + k0 + cseg[e]]);
        }
        CP_COMMIT();
    }
    for (int c = 0; c < 8; c++) {
        const int st = c % 3;
        if (c + 1 < 8) { CP_WAIT1(); } else { CP_WAIT0(); }
        __syncthreads();
        if (c + 2 < 8) {
            const int nst = (c + 2) % 3;
            const int k0 = (c + 2) * 32;
            #pragma unroll
            for (int e = 0; e < 2; e++) {
                cp16(sbase + (uint32_t)(nst*HSTG + crow[e]*KPH + cseg[e])*2,
                     &A[(size_t)crow[e] * ML + k0 + cseg[e]]);
                cp16(bbase + (uint32_t)(nst*HSTG + crow[e]*KPH + cseg[e])*2,
                     &B[(size_t)crow[e] * ML + k0 + cseg[e]]);
            }
            CP_COMMIT();
        }
        const uint32_t a_st = sbase + (uint32_t)(st*HSTG)*2 + a_lm;
        const uint32_t b_st = bbase + (uint32_t)(st*HSTG)*2 + b_lm;
        #pragma unroll
        for (int ks = 0; ks < 2; ks++) {
            uint32_t af[4][4];
            #pragma unroll
            for (int mi = 0; mi < 4; mi++)
                ldsm_x4(af[mi][0], af[mi][1], af[mi][2], af[mi][3],
                        a_st + (uint32_t)((wm*64 + mi*16)*KPH + ks*16)*2);
            uint32_t bf[4][2];
            #pragma unroll
            for (int p = 0; p < 2; p++)
                ldsm_x4(bf[2*p][0], bf[2*p][1], bf[2*p+1][0], bf[2*p+1][1],
                        b_st + (uint32_t)((wn*32 + p*16)*KPH + ks*16)*2);
            #pragma unroll
            for (int mi = 0; mi < 4; mi++)
                #pragma unroll
                for (int ni = 0; ni < 4; ni++)
                    mma_bf16_16x8x16(acc[mi][ni],
                        af[mi][0], af[mi][1], af[mi][2], af[mi][3],
                        bf[ni][0], bf[ni][1]);
        }
    }

    #pragma unroll
    for (int mi = 0; mi < 4; mi++) {
        #pragma unroll
        for (int ni = 0; ni < 4; ni++) {
            int grow = m0 + wm*64 + mi*16 + gr;
            int gcol = n0 + wn*32 + ni*8 + gc*2;
            const float* a = acc[mi][ni];
            float d0, d1, d2, d3;
            if (U) {
                __nv_bfloat162 u0 = *reinterpret_cast<const __nv_bfloat162*>(&U[(size_t)grow * ML + gcol]);
                __nv_bfloat162 u1 = *reinterpret_cast<const __nv_bfloat162*>(&U[(size_t)(grow+8) * ML + gcol]);
                d0 = c1*__bfloat162float(u0.x) + c2*a[0];
                d1 = c1*__bfloat162float(u0.y) + c2*a[1];
                d2 = c1*__bfloat162float(u1.x) + c2*a[2];
                d3 = c1*__bfloat162float(u1.y) + c2*a[3];
            } else {
                d0 = c2*a[0]; d1 = c2*a[1]; d2 = c2*a[2]; d3 = c2*a[3];
            }
            __nv_bfloat16 h0 = __float2bfloat16(d0), h1 = __float2bfloat16(d1);
            __nv_bfloat16 h2 = __float2bfloat16(d2), h3 = __float2bfloat16(d3);
            if (Cn) {
                __nv_bfloat162 p0; p0.x = h0; p0.y = h1;
                __nv_bfloat162 p1; p1.x = h2; p1.y = h3;
                *reinterpret_cast<__nv_bfloat162*>(&Cn[(size_t)grow * ML + gcol]) = p0;
                *reinterpret_cast<__nv_bfloat162*>(&Cn[(size_t)(grow+8) * ML + gcol]) = p1;
            }
            if (Ct) {
                Ct[(size_t)gcol * ML + grow]       = h0;
                Ct[(size_t)(gcol+1) * ML + grow]   = h1;
                Ct[(size_t)gcol * ML + grow+8]     = h2;
                Ct[(size_t)(gcol+1) * ML + grow+8] = h3;
            }
            if (Cf) {
                *reinterpret_cast<float2*>(&Cf[(size_t)grow * ML + gcol]) =
                    make_float2(cvt_tf32(d0), cvt_tf32(d1));
                *reinterpret_cast<float2*>(&Cf[(size_t)(grow+8) * ML + gcol]) =
                    make_float2(cvt_tf32(d2), cvt_tf32(d3));
            }
        }
    }
}

// ============ plain batched GEMM: C[z] = A[z] @ B[z]^T (B K-major; sims) ============
__global__ void __launch_bounds__(256, 2) gemm_tc_kernel(
    const float* __restrict__ A, const float* __restrict__ B, float* __restrict__ C,
    int lda, int ldb, int ldc, int kch,
    size_t sA, size_t sB, size_t sC)
{
    extern __shared__ float sm[];
    const int tid = threadIdx.x;
    const int z = blockIdx.z;
    const int m0 = blockIdx.y * 128, n0 = blockIdx.x * 128;
    A += (size_t)z * sA + (size_t)m0 * lda;
    B += (size_t)z * sB + (size_t)n0 * ldb;
    C += (size_t)z * sC;
    float acc[4][4][4];
    #pragma unroll
    for (int mi = 0; mi < 4; mi++)
        #pragma unroll
        for (int ni = 0; ni < 4; ni++)
            #pragma unroll
            for (int e = 0; e < 4; e++) acc[mi][ni][e] = 0.f;
    mainloop128x128(A, B, lda, ldb, kch, sm, tid, acc);
    const int wid = tid >> 5, lane = tid & 31;
    const int gr = lane >> 2, gc = lane & 3;
    const int wm = wid >> 2, wn = wid & 3;
    #pragma unroll
    for (int mi = 0; mi < 4; mi++) {
        #pragma unroll
        for (int ni = 0; ni < 4; ni++) {
            int lr = m0 + wm*64 + mi*16 + gr;
            int lc = n0 + wn*32 + ni*8 + gc*2;
            const float* a = acc[mi][ni];
            *reinterpret_cast<float2*>(&C[(size_t)lr * ldc + lc]) = make_float2(a[0], a[1]);
            *reinterpret_cast<float2*>(&C[(size_t)(lr+8) * ldc + lc]) = make_float2(a[2], a[3]);
        }
    }
}

// ============ QKV^T GEMM: qkvT[n][i] = wqkvT[n][c] @ x[b][c][i] ============
__global__ void __launch_bounds__(256, 2) qkvT_tc_kernel(const float* __restrict__ x) {
    extern __shared__ float sm[];
    const int tid = threadIdx.x;
    const int m0 = blockIdx.y * 128;        // over 1536 qkv dims
    const int n0 = blockIdx.x * 128;        // over 1024 tokens
    const int b  = blockIdx.z;
    const float* A = g_wqkvT + (size_t)m0 * CDIM;
    const float* B = x + (size_t)b * CDIM * NTOK + n0;
    float acc[4][4][4];
    #pragma unroll
    for (int mi = 0; mi < 4; mi++)
        #pragma unroll
        for (int ni = 0; ni < 4; ni++)
            #pragma unroll
            for (int e = 0; e < 4; e++) acc[mi][ni][e] = 0.f;
    mainloop128x128_rowB(A, B, CDIM, NTOK, CDIM/32, sm, tid, acc);
    const int wid = tid >> 5, lane = tid & 31;
    const int gr = lane >> 2, gc = lane & 3;
    const int wm = wid >> 2, wn = wid & 3;
    #pragma unroll
    for (int mi = 0; mi < 4; mi++) {
        int m = m0 + wm*64 + mi*16 + gr;
        int which = m >> 9;
        int h = (m >> 6) & 7;
        int d = m & 63;
        int bh = b*8 + h;
        float* dst = (which == 0) ? g_q : ((which == 1) ? g_k : g_v);
        float sc = (which == 0) ? 0.125f : 1.0f;
        #pragma unroll
        for (int ni = 0; ni < 4; ni++) {
            int i = n0 + wn*32 + ni*8 + gc*2;
            const float* a = acc[mi][ni];
            dst[((size_t)(bh*NTOK + i))*DH + d]       = cvt_tf32(a[0]*sc);
            dst[((size_t)(bh*NTOK + i + 1))*DH + d]   = cvt_tf32(a[1]*sc);
            dst[((size_t)(bh*NTOK + i))*DH + d + 8]   = cvt_tf32(a[2]*sc);
            dst[((size_t)(bh*NTOK + i + 1))*DH + d + 8] = cvt_tf32(a[3]*sc);
        }
    }
}

// ============ final GEMM: out = outf @ woutT^T + bias, transposed store (fp32) ============
__global__ void __launch_bounds__(256, 2) final_tc_kernel(
    const float* __restrict__ bias, float* __restrict__ out)
{
    extern __shared__ float sm[];
    const int tid = threadIdx.x;
    const int m0 = blockIdx.y * 128;
    const int n0 = blockIdx.x * 128;
    const float* A = g_outf + (size_t)m0 * CDIM;
    const float* B = g_woutT + (size_t)n0 * CDIM;
    float acc[4][4][4];
    #pragma unroll
    for (int mi = 0; mi < 4; mi++)
        #pragma unroll
        for (int ni = 0; ni < 4; ni++)
            #pragma unroll
            for (int e = 0; e < 4; e++) acc[mi][ni][e] = 0.f;
    mainloop128x128(A, B, CDIM, CDIM, CDIM/32, sm, tid, acc);
    const int wid = tid >> 5, lane = tid & 31;
    const int gr = lane >> 2, gc = lane & 3;
    const int wm = wid >> 2, wn = wid & 3;
    #pragma unroll
    for (int mi = 0; mi < 4; mi++) {
        int m = m0 + wm*64 + mi*16 + gr;
        int b = m >> 10, i = m & 1023;
        #pragma unroll
        for (int ni = 0; ni < 4; ni++) {
            int n = n0 + wn*32 + ni*8 + gc*2;
            const float* a = acc[mi][ni];
            float b0 = bias[n], b1 = bias[n+1];
            out[((size_t)(b*CDIM + n))*NTOK + i]       = a[0] + b0;
            out[((size_t)(b*CDIM + n + 1))*NTOK + i]   = a[1] + b1;
            out[((size_t)(b*CDIM + n))*NTOK + i + 8]   = a[2] + b0;
            out[((size_t)(b*CDIM + n + 1))*NTOK + i + 8] = a[3] + b1;
        }
    }
}

// ============ 128x64 batched GEMM, B row-major [K,64]: C = A @ B ============
__global__ void __launch_bounds__(256, 2) gemm64_rowB_kernel(
    const float* __restrict__ A, const float* __restrict__ B, float* __restrict__ C,
    int lda, int kch, size_t sA, size_t sB, int flatC)
{
    extern __shared__ float sm[];
    const uint32_t sbase = (uint32_t)__cvta_generic_to_shared(sm);
    const uint32_t bbase = sbase + 3*PSTAGE*4;
    const int tid = threadIdx.x;
    const int wid = tid >> 5, lane = tid & 31;
    const int gr = lane >> 2, gc = lane & 3;
    const int wm = wid >> 1, wn = wid & 1;
    const int g = lane >> 3, r8 = lane & 7;
    const uint32_t a_lm = (uint32_t)((wm*32 + (g&1)*8 + r8)*PPITCH + (g>>1)*4)*4;
    const int z = blockIdx.z;
    const int m0 = blockIdx.x * 128;
    A += (size_t)z * sA + (size_t)m0 * lda;
    B += (size_t)z * sB;
    if (flatC) C += (size_t)(z >> 3) * (NTOK*CDIM) + (size_t)(z & 7) * DH;
    else       C += (size_t)z * (ML*DH);

    int arow[4], ac4[4], bk[2], bn4[2];
    #pragma unroll
    for (int e = 0; e < 4; e++) {
        int f4 = e * 256 + tid;
        arow[e] = f4 >> 3;  ac4[e] = (f4 & 7) << 2;
    }
    #pragma unroll
    for (int e = 0; e < 2; e++) {
        int f4 = e * 256 + tid;
        bk[e] = f4 >> 4;  bn4[e] = (f4 & 15) << 2;
    }

    float acc[2][4][4];
    #pragma unroll
    for (int mi = 0; mi < 2; mi++)
        #pragma unroll
        for (int ni = 0; ni < 4; ni++)
            #pragma unroll
            for (int e = 0; e < 4; e++) acc[mi][ni][e] = 0.f;

    #pragma unroll
    for (int p = 0; p < 2; p++) {
        if (p < kch) {
            const int k0 = p * 32;
            #pragma unroll
            for (int e = 0; e < 4; e++)
                cp16(sbase + (uint32_t)(p*PSTAGE + arow[e]*PPITCH + ac4[e])*4,
                     &A[(size_t)arow[e] * lda + k0 + ac4[e]]);
            #pragma unroll
            for (int e = 0; e < 2; e++)
                cp16(bbase + (uint32_t)(p*BRSTG64 + bk[e]*BNP64 + bn4[e])*4,
                     &B[(size_t)(k0 + bk[e]) * DH + bn4[e]]);
        }
        CP_COMMIT();
    }

    for (int c = 0; c < kch; c++) {
        const int st = c % 3;
        if (c + 1 < kch) { CP_WAIT1(); } else { CP_WAIT0(); }
        __syncthreads();
        if (c + 2 < kch) {
            const int nst = (c + 2) % 3;
            const int k0 = (c + 2) * 32;
            #pragma unroll
            for (int e = 0; e < 4; e++)
                cp16(sbase + (uint32_t)(nst*PSTAGE + arow[e]*PPITCH + ac4[e])*4,
                     &A[(size_t)arow[e] * lda + k0 + ac4[e]]);
            #pragma unroll
            for (int e = 0; e < 2; e++)
                cp16(bbase + (uint32_t)(nst*BRSTG64 + bk[e]*BNP64 + bn4[e])*4,
                     &B[(size_t)(k0 + bk[e]) * DH + bn4[e]]);
            CP_COMMIT();
        }
        const uint32_t a_st = sbase + (uint32_t)(st*PSTAGE)*4 + a_lm;
        const float* Bb = sm + 3*PSTAGE + st*BRSTG64;
        #pragma unroll
        for (int ks = 0; ks < 4; ks++) {
            uint32_t af[2][4];
            #pragma unroll
            for (int mi = 0; mi < 2; mi++)
                ldsm_x4(af[mi][0], af[mi][1], af[mi][2], af[mi][3],
                        a_st + (uint32_t)(mi*16*PPITCH + ks*8)*4);
            uint32_t bf[4][2];
            #pragma unroll
            for (int ni = 0; ni < 4; ni++) {
                int n = wn*32 + ni*8 + gr;
                bf[ni][0] = __float_as_uint(Bb[(ks*8 + gc)*BNP64 + n]);
                bf[ni][1] = __float_as_uint(Bb[(ks*8 + gc + 4)*BNP64 + n]);
            }
            #pragma unroll
            for (int mi = 0; mi < 2; mi++)
                #pragma unroll
                for (int ni = 0; ni < 4; ni++)
                    mma_tf32_16x8x8(acc[mi][ni],
                        af[mi][0], af[mi][1], af[mi][2], af[mi][3],
                        bf[ni][0], bf[ni][1]);
        }
    }

    #pragma unroll
    for (int mi = 0; mi < 2; mi++) {
        #pragma unroll
        for (int ni = 0; ni < 4; ni++) {
            int lr = m0 + wm*32 + mi*16 + gr;
            int lc = wn*32 + ni*8 + gc*2;
            const float* a = acc[mi][ni];
            float d0 = cvt_tf32(a[0]), d1 = cvt_tf32(a[1]);
            float d2 = cvt_tf32(a[2]), d3 = cvt_tf32(a[3]);
            int ldc = flatC ? CDIM : DH;
            *reinterpret_cast<float2*>(&C[(size_t)lr * ldc + lc]) = make_float2(d0, d1);
            *reinterpret_cast<float2*>(&C[(size_t)(lr+8) * ldc + lc]) = make_float2(d2, d3);
        }
    }
}

// ---------------- batched 2D transpose (tf32-rounded output) ----------------
__global__ void transpose_kernel(const float* __restrict__ in, float* __restrict__ out,
                                 int R, int C) {
    __shared__ float tile[32][33];
    const int z = blockIdx.z;
    in  += (size_t)z * R * C;
    out += (size_t)z * R * C;
    int c0 = blockIdx.x * 32, r0 = blockIdx.y * 32;
    int tx = threadIdx.x, ty = threadIdx.y;
    #pragma unroll
    for (int j = 0; j < 4; j++)
        tile[ty + j*8][tx] = in[(size_t)(r0 + ty + j*8) * C + c0 + tx];
    __syncthreads();
    #pragma unroll
    for (int j = 0; j < 4; j++)
        out[(size_t)(c0 + ty + j*8) * R + r0 + tx] = cvt_tf32(tile[tx][ty + j*8]);
}

// ---------------- landmark means (tf32-rounded) ----------------
__global__ void land_kernel() {
    int idx = blockIdx.x * blockDim.x + threadIdx.x;
    if (idx >= BHN*ML*DH) return;
    int d  = idx & 63;
    int j  = (idx >> 6) & 255;
    int bh = idx >> 14;
    size_t base = ((size_t)bh * NTOK + j*4) * DH + d;
    g_ql[idx] = cvt_tf32(0.25f * (g_q[base] + g_q[base+64] + g_q[base+128] + g_q[base+192]));
    g_kl[idx] = cvt_tf32(0.25f * (g_k[base] + g_k[base+64] + g_k[base+128] + g_k[base+192]));
}

// ---------------- warp-per-row softmax: fast exp, zero block barriers ----------------
template<int W>
__global__ void softmax_warp_kernel(float* __restrict__ data) {
    const int lane = threadIdx.x & 31;
    const int row = blockIdx.x * 8 + (threadIdx.x >> 5);
    float* r = data + (size_t)row * W;
    constexpr int PE = W / 32;
    float v[PE];
    float mx = -1e30f;
    #pragma unroll
    for (int e = 0; e < PE; e++) { v[e] = r[lane + e*32]; mx = fmaxf(mx, v[e]); }
    #pragma unroll
    for (int o = 16; o > 0; o >>= 1) mx = fmaxf(mx, __shfl_xor_sync(0xffffffffu, mx, o));
    float s = 0.f;
    #pragma unroll
    for (int e = 0; e < PE; e++) { v[e] = __expf(v[e] - mx); s += v[e]; }
    #pragma unroll
    for (int o = 16; o > 0; o >>= 1) s += __shfl_xor_sync(0xffffffffu, s, o);
    float inv = 1.0f / s;
    #pragma unroll
    for (int e = 0; e < PE; e++) r[lane + e*32] = cvt_tf32(v[e] * inv);
}

// ---------------- pinv scale reductions ----------------
__global__ void reset_max_kernel() { if (threadIdx.x == 0) { g_colmax = 0u; g_rowmax = 0u; } }

__global__ void colmax_kernel() {
    int gw = (blockIdx.x * blockDim.x + threadIdx.x) >> 5;
    int lane = threadIdx.x & 31;
    if (gw >= BHN * ML) return;
    const float* row = g_attn2 + (size_t)gw * ML;
    float s = 0.f;
    #pragma unroll
    for (int j = lane; j < ML; j += 32) s += fabsf(row[j]);
    #pragma unroll
    for (int o = 16; o > 0; o >>= 1) s += __shfl_down_sync(0xffffffffu, s, o);
    if (lane == 0) atomicMax(&g_colmax, __float_as_uint(s));
}

__global__ void rowmax_kernel() {
    int idx = blockIdx.x * blockDim.x + threadIdx.x;
    if (idx >= BHN * ML) return;
    int bh = idx >> 8, j = idx & 255;
    const float* base = g_attn2 + (size_t)bh * ML * ML + j;
    float s = 0.f;
    for (int i = 0; i < ML; i++) s += fabsf(base[(size_t)i * ML]);
    atomicMax(&g_rowmax, __float_as_uint(s));
}

// zinit: z0 (bf16, row + transposed) and a2h (bf16 of a2)
__global__ void zinit_kernel() {
    float inv = 1.0f / (__uint_as_float(g_colmax) * __uint_as_float(g_rowmax));
    size_t idx = (size_t)blockIdx.x * 256 + threadIdx.x;
    int j  = idx & 255;
    int i  = (idx >> 8) & 255;
    size_t bh = idx >> 16;
    float a2v  = g_attn2[idx];
    float a2tv = g_attn2[(bh << 16) + ((size_t)j << 8) + i];
    g_zhA[idx]  = __float2bfloat16(a2tv * inv);   // z0 row-major = scaled x^T
    g_zhTA[idx] = __float2bfloat16(a2v * inv);    // z0^T = scaled x
    g_a2h[idx]  = __float2bfloat16(a2v);
}

// ---------------- depthwise 33-tap conv residual (tf32-rounded add) ----------------
__global__ void res_add_kernel(const float* __restrict__ rk) {
    __shared__ float ker[KSZ];
    int blk = blockIdx.x;
    int bh = blk >> 8;
    int ichunk = blk & 255;
    int h = bh & 7, b = bh >> 3;
    if (threadIdx.x < KSZ) ker[threadIdx.x] = rk[h*KSZ + threadIdx.x];
    __syncthreads();
    int d = threadIdx.x & 63;
    int i = ichunk * 4 + (threadIdx.x >> 6);
    const float* vb = g_v + (size_t)bh * NTOK * DH;
    float s = 0.f;
    #pragma unroll
    for (int t = 0; t < KSZ; t++) {
        int ii = i + t - (KSZ/2);
        if (ii >= 0 && ii < NTOK) s += ker[t] * vb[(size_t)ii * DH + d];
    }
    size_t o = ((size_t)(b*NTOK + i)) * CDIM + h*64 + d;
    g_outf[o] = cvt_tf32(g_outf[o] + s);
}

// ---------------- host ----------------
extern "C" void kernel_launch(void* const* d_in, const int* in_sizes, int n_in,
                              void* d_out, int out_size) {
    const float* x     = (const float*)d_in[0];
    const float* w_qkv = (const float*)d_in[1];
    const float* w_out = (const float*)d_in[2];
    const float* b_out = (const float*)d_in[3];
    const float* rk    = (const float*)d_in[4];
    float* out = (float*)d_out;

    float *wqkvT, *woutT, *q, *k, *v, *ql, *kl, *a1, *a3, *a2;
    float *zA, *av, *bv, *outf;
    __nv_bfloat16 *a2h, *zhA, *zhB, *zhTA, *zhTB, *xzh, *xzhT, *t1hT, *t2hT;
    cudaGetSymbolAddress((void**)&wqkvT, g_wqkvT);
    cudaGetSymbolAddress((void**)&woutT, g_woutT);
    cudaGetSymbolAddress((void**)&q,  g_q);
    cudaGetSymbolAddress((void**)&k,  g_k);
    cudaGetSymbolAddress((void**)&v,  g_v);
    cudaGetSymbolAddress((void**)&ql, g_ql);
    cudaGetSymbolAddress((void**)&kl, g_kl);
    cudaGetSymbolAddress((void**)&a1, g_attn1);
    cudaGetSymbolAddress((void**)&a3, g_attn3);
    cudaGetSymbolAddress((void**)&a2, g_attn2);
    cudaGetSymbolAddress((void**)&zA, g_zA);
    cudaGetSymbolAddress((void**)&av, g_av);
    cudaGetSymbolAddress((void**)&bv, g_bv);
    cudaGetSymbolAddress((void**)&outf, g_outf);
    cudaGetSymbolAddress((void**)&a2h,  g_a2h);
    cudaGetSymbolAddress((void**)&zhA,  g_zhA);
    cudaGetSymbolAddress((void**)&zhB,  g_zhB);
    cudaGetSymbolAddress((void**)&zhTA, g_zhTA);
    cudaGetSymbolAddress((void**)&zhTB, g_zhTB);
    cudaGetSymbolAddress((void**)&xzh,  g_xzh);
    cudaGetSymbolAddress((void**)&xzhT, g_xzhT);
    cudaGetSymbolAddress((void**)&t1hT, g_t1hT);
    cudaGetSymbolAddress((void**)&t2hT, g_t2hT);

    cudaFuncSetAttribute(pinv_bf16_kernel,   cudaFuncAttributeMaxDynamicSharedMemorySize, BH_SMEM3);
    cudaFuncSetAttribute(gemm_tc_kernel,     cudaFuncAttributeMaxDynamicSharedMemorySize, G128_SMEM3);
    cudaFuncSetAttribute(qkvT_tc_kernel,     cudaFuncAttributeMaxDynamicSharedMemorySize, PB_SMEM3);
    cudaFuncSetAttribute(final_tc_kernel,    cudaFuncAttributeMaxDynamicSharedMemorySize, G128_SMEM3);
    cudaFuncSetAttribute(gemm64_rowB_kernel, cudaFuncAttributeMaxDynamicSharedMemorySize, G64R_SMEM3);

    cudaStream_t s1, s2;
    cudaStreamCreateWithFlags(&s1, cudaStreamNonBlocking);
    cudaStreamCreateWithFlags(&s2, cudaStreamNonBlocking);
    cudaEvent_t evL, ev1, ev2, evZ, evP;
    cudaEventCreateWithFlags(&evL, cudaEventDisableTiming);
    cudaEventCreateWithFlags(&ev1, cudaEventDisableTiming);
    cudaEventCreateWithFlags(&ev2, cudaEventDisableTiming);
    cudaEventCreateWithFlags(&evZ, cudaEventDisableTiming);
    cudaEventCreateWithFlags(&evP, cudaEventDisableTiming);

    // 0) layout prep (weights only)
    transpose_kernel<<<dim3(48, 16, 1), dim3(32,8)>>>(w_qkv, wqkvT, CDIM, 3*CDIM);
    transpose_kernel<<<dim3(16, 16, 1), dim3(32,8)>>>(w_out, woutT, CDIM, CDIM);
    // 1) QKV projection (transposed form, x in natural layout)
    qkvT_tc_kernel<<<dim3(8, 12, BATCH), 256, PB_SMEM3>>>(x);
    // 2) landmarks
    land_kernel<<<(BHN*ML*DH + 255)/256, 256>>>();
    cudaEventRecord(evL, 0);

    // ---- branch s1: sim1 + softmax a1 (consumed by outf GEMM much later) ----
    cudaStreamWaitEvent(s1, evL, 0);
    gemm_tc_kernel<<<dim3(2, 8, BHN), 256, G128_SMEM3, s1>>>(q,  kl, a1, DH, DH, ML, 2,
        (size_t)NTOK*DH, (size_t)ML*DH, (size_t)NTOK*ML);
    softmax_warp_kernel<256> <<<BHN*NTOK/8, 256, 0, s1>>>(a1);
    cudaEventRecord(ev1, s1);

    // ---- branch s2: sim3 + softmax a3 + av = attn3@v ----
    cudaStreamWaitEvent(s2, evL, 0);
    gemm_tc_kernel<<<dim3(8, 2, BHN), 256, G128_SMEM3, s2>>>(ql, k, a3, DH, DH, NTOK, 2,
        (size_t)ML*DH, (size_t)NTOK*DH, (size_t)ML*NTOK);
    softmax_warp_kernel<1024><<<BHN*ML/8, 256, 0, s2>>>(a3);
    gemm64_rowB_kernel<<<dim3(2, 1, BHN), 256, G64R_SMEM3, s2>>>(a3, v, av,
        NTOK, 32, (size_t)ML*NTOK, (size_t)NTOK*DH, 0);
    cudaEventRecord(ev2, s2);

    // ---- main stream: a2 path, then pinv split over two half-batch chains ----
    gemm_tc_kernel<<<dim3(2, 2, BHN), 256, G128_SMEM3>>>(ql, kl, a2, DH, DH, ML, 2,
        (size_t)ML*DH, (size_t)ML*DH, (size_t)ML*ML);
    softmax_warp_kernel<256> <<<BHN*ML/8, 256>>>(a2);
    reset_max_kernel<<<1, 32>>>();
    colmax_kernel<<<(BHN*ML*32)/256, 256>>>();
    rowmax_kernel<<<(BHN*ML)/256, 256>>>();
    zinit_kernel<<<(BHN*ML*ML)/256, 256>>>();
    cudaEventRecord(evZ, 0);

    // Newton–Schulz (all bf16; final update emits fp32 z via Cf) — batches split
    // into two independent half-chains (grid 512 each) so one chain's wave tails
    // and launch gaps backfill with the other's CTAs.
    const size_t HOFF = (size_t)(BHN/2) << 16;   // elements per half (all ML*ML bufs)
    auto run_chain = [&](cudaStream_t st, size_t off) {
        __nv_bfloat16 *zi = zhA + off, *zo = zhB + off;
        __nv_bfloat16 *zTi = zhTA + off, *zTo = zhTB + off;
        for (int it = 0; it < 6; it++) {
            pinv_bf16_kernel<<<512, 256, BH_SMEM3, st>>>(a2h + off, zTi, nullptr,
                xzh + off, xzhT + off, nullptr, 0.0f, 1.0f);
            pinv_bf16_kernel<<<512, 256, BH_SMEM3, st>>>(xzh + off, xzhT + off, xzh + off,
                nullptr, t1hT + off, nullptr, 7.0f, -1.0f);
            pinv_bf16_kernel<<<512, 256, BH_SMEM3, st>>>(xzh + off, t1hT + off, xzh + off,
                nullptr, t2hT + off, nullptr, 15.0f, -1.0f);
            if (it < 5) {
                pinv_bf16_kernel<<<512, 256, BH_SMEM3, st>>>(zi, t2hT + off, zi,
                    zo, zTo, nullptr, 3.25f, -0.25f);
                __nv_bfloat16* tmp;
                tmp = zi;  zi  = zo;  zo  = tmp;
                tmp = zTi; zTi = zTo; zTo = tmp;
            } else {
                pinv_bf16_kernel<<<512, 256, BH_SMEM3, st>>>(zi, t2hT + off, zi,
                    nullptr, nullptr, zA + off, 3.25f, -0.25f);
            }
        }
    };
    run_chain(0, 0);                  // batches [0, 128) on main stream
    cudaStreamWaitEvent(s1, evZ, 0);  // s1 finished a1 work; reuse for second half
    run_chain(s1, HOFF);              // batches [128, 256)
    cudaEventRecord(evP, s1);
    float* zfin = zA;

    // joins: bv needs z (both halves) + av (s2); outf needs a1 (s1, ordered before evP)
    cudaStreamWaitEvent(0, evP, 0);
    cudaStreamWaitEvent(0, ev2, 0);
    gemm64_rowB_kernel<<<dim3(2, 1, BHN), 256, G64R_SMEM3>>>(zfin, av, bv,
        ML, 8, (size_t)ML*ML, (size_t)ML*DH, 0);
    cudaStreamWaitEvent(0, ev1, 0);
    gemm64_rowB_kernel<<<dim3(8, 1, BHN), 256, G64R_SMEM3>>>(a1, bv, outf,
        ML, 8, (size_t)NTOK*ML, (size_t)ML*DH, 1);
    // depthwise conv residual + output projection
    res_add_kernel<<<BHN*256, 256>>>(rk);
    final_tc_kernel<<<dim3(4, 256), 256, G128_SMEM3>>>(b_out, out);

    cudaEventDestroy(evL);
    cudaEventDestroy(ev1);
    cudaEventDestroy(ev2);
    cudaEventDestroy(evZ);
    cudaEventDestroy(evP);
    cudaStreamDestroy(s1);
    cudaStreamDestroy(s2);
}